// round 7
// baseline (speedup 1.0000x reference)
#include <cuda_runtime.h>
#include <cuda_bf16.h>
#include <cstdint>
#include <math.h>

// Problem constants (fixed shapes)
#define BS   2
#define SEQ  2048
#define EMB  1024
#define NH   16
#define HD   64
#define F3   3072   // 3*EMB
#define ROWS (BS * SEQ)   // 4096

// ---------------------------------------------------------------------------
// Scratch (device globals: allocation-free rule)
// ---------------------------------------------------------------------------
__device__ __nv_bfloat16 g_x_hi[ROWS * EMB];
__device__ __nv_bfloat16 g_x_lo[ROWS * EMB];
__device__ __nv_bfloat16 g_wqkv_hi[F3 * EMB];
__device__ __nv_bfloat16 g_wqkv_lo[F3 * EMB];
__device__ __nv_bfloat16 g_wout_hi[EMB * EMB];
__device__ __nv_bfloat16 g_wout_lo[EMB * EMB];
__device__ __nv_bfloat16 g_qkv_hi[ROWS * F3];
__device__ __nv_bfloat16 g_qkv_lo[ROWS * F3];
__device__ __nv_bfloat16 g_att_hi[ROWS * EMB];
__device__ __nv_bfloat16 g_att_lo[ROWS * EMB];

// ---------------------------------------------------------------------------
// helpers
// ---------------------------------------------------------------------------
__device__ __forceinline__ uint32_t smem_u32(const void* p) {
    uint32_t a;
    asm("{ .reg .u64 t; cvta.to.shared.u64 t, %1; cvt.u32.u64 %0, t; }" : "=r"(a) : "l"(p));
    return a;
}
__device__ __forceinline__ void ldsm_x4(uint32_t addr, uint32_t r[4]) {
    asm volatile("ldmatrix.sync.aligned.m8n8.x4.shared.b16 {%0,%1,%2,%3}, [%4];"
                 : "=r"(r[0]), "=r"(r[1]), "=r"(r[2]), "=r"(r[3]) : "r"(addr));
}
__device__ __forceinline__ void ldsm_x4_t(uint32_t addr, uint32_t r[4]) {
    asm volatile("ldmatrix.sync.aligned.m8n8.x4.trans.shared.b16 {%0,%1,%2,%3}, [%4];"
                 : "=r"(r[0]), "=r"(r[1]), "=r"(r[2]), "=r"(r[3]) : "r"(addr));
}
__device__ __forceinline__ void mma16816(float c[4], const uint32_t a[4],
                                         const uint32_t b0, const uint32_t b1) {
    asm volatile(
        "mma.sync.aligned.m16n8k16.row.col.f32.bf16.bf16.f32 "
        "{%0,%1,%2,%3}, {%4,%5,%6,%7}, {%8,%9}, {%0,%1,%2,%3};"
        : "+f"(c[0]), "+f"(c[1]), "+f"(c[2]), "+f"(c[3])
        : "r"(a[0]), "r"(a[1]), "r"(a[2]), "r"(a[3]), "r"(b0), "r"(b1));
}
__device__ __forceinline__ uint32_t pack_bf16(float lo, float hi) {
    uint32_t r;
    asm("cvt.rn.bf16x2.f32 %0, %1, %2;" : "=r"(r) : "f"(hi), "f"(lo));
    return r;
}
__device__ __forceinline__ float ex2(float x) {
    float r;
    asm("ex2.approx.ftz.f32 %0, %1;" : "=f"(r) : "f"(x));
    return r;
}
__device__ __forceinline__ void cp_async16(uint32_t dst, const void* src) {
    asm volatile("cp.async.cg.shared.global [%0], [%1], 16;" :: "r"(dst), "l"(src));
}
#define CP_COMMIT() asm volatile("cp.async.commit_group;" ::: "memory")
#define CP_WAIT1()  asm volatile("cp.async.wait_group 1;" ::: "memory")
#define CP_WAIT0()  asm volatile("cp.async.wait_group 0;" ::: "memory")

// ---------------------------------------------------------------------------
// bf16 hi/lo split (float4 vectorized)
// ---------------------------------------------------------------------------
__global__ void split_bf16(const float4* __restrict__ in,
                           __nv_bfloat162* __restrict__ hi,
                           __nv_bfloat162* __restrict__ lo, int n4) {
    int i = blockIdx.x * blockDim.x + threadIdx.x;
    if (i >= n4) return;
    float4 v = in[i];
    __nv_bfloat16 h0 = __float2bfloat16_rn(v.x);
    __nv_bfloat16 h1 = __float2bfloat16_rn(v.y);
    __nv_bfloat16 h2 = __float2bfloat16_rn(v.z);
    __nv_bfloat16 h3 = __float2bfloat16_rn(v.w);
    __nv_bfloat16 l0 = __float2bfloat16_rn(v.x - __bfloat162float(h0));
    __nv_bfloat16 l1 = __float2bfloat16_rn(v.y - __bfloat162float(h1));
    __nv_bfloat16 l2 = __float2bfloat16_rn(v.z - __bfloat162float(h2));
    __nv_bfloat16 l3 = __float2bfloat16_rn(v.w - __bfloat162float(h3));
    hi[2 * i]     = __nv_bfloat162(h0, h1);
    hi[2 * i + 1] = __nv_bfloat162(h2, h3);
    lo[2 * i]     = __nv_bfloat162(l0, l1);
    lo[2 * i + 1] = __nv_bfloat162(l2, l3);
}

// ---------------------------------------------------------------------------
// mma.sync bf16x3 GEMM, cp.async double-buffered, PER-WARP PASS ROTATION.
// CTA tile 256x128, 8 warps, warp tile 64x64, BK=32.
// ---------------------------------------------------------------------------
#define SA_STRIDE 40
#define ATILE_B (256 * SA_STRIDE * 2)           // 20480
#define BTILE_B (128 * SA_STRIDE * 2)           // 10240
#define STAGE_B (2 * ATILE_B + 2 * BTILE_B)     // 61440
#define GEMM_SMEM (2 * STAGE_B)                 // 122880

template <bool HAS_BIAS, bool SPLIT_OUT>
__global__ __launch_bounds__(256, 1)
void gemm_mma(const __nv_bfloat16* __restrict__ Ahi, const __nv_bfloat16* __restrict__ Alo,
              const __nv_bfloat16* __restrict__ Bhi, const __nv_bfloat16* __restrict__ Blo,
              const float* __restrict__ bias, float* __restrict__ C,
              __nv_bfloat16* __restrict__ Chi, __nv_bfloat16* __restrict__ Clo,
              int N, int K) {
    extern __shared__ char smem[];
    const uint32_t sb = smem_u32(smem);

    const int tid  = threadIdx.x;
    const int wid  = tid >> 5;
    const int lane = tid & 31;
    const int rot  = wid % 3;        // per-warp pass rotation (anti-lockstep)
    const int n0 = blockIdx.x * 128;
    const int m0 = blockIdx.y * 256;
    const int wm = (wid & 3) * 64;
    const int wn = (wid >> 2) * 64;

    const int trow  = lane & 7;
    const int tquad = lane >> 3;
    const int a_row_off = (tquad & 1) * 8 + trow;
    const int a_col_off = (tquad >> 1) * 8;
    const int b_row_off = (tquad >> 1) * 8 + trow;
    const int b_col_off = (tquad & 1) * 8;

    float acc[4][8][4];
#pragma unroll
    for (int mt = 0; mt < 4; mt++)
#pragma unroll
        for (int nt = 0; nt < 8; nt++)
#pragma unroll
            for (int j = 0; j < 4; j++) acc[mt][nt][j] = 0.0f;

    auto load_stage = [&](int stage, int k0) {
        uint32_t s0 = sb + stage * STAGE_B;
#pragma unroll
        for (int i = 0; i < 4; i++) {
            int idx = tid + 256 * i;
            int row = idx >> 2, q = idx & 3;
            uint32_t soff = (uint32_t)(row * SA_STRIDE + q * 8) * 2;
            size_t ga = (size_t)(m0 + row) * K + k0 + q * 8;
            cp_async16(s0 + soff,            Ahi + ga);
            cp_async16(s0 + ATILE_B + soff,  Alo + ga);
        }
#pragma unroll
        for (int i = 0; i < 2; i++) {
            int idx = tid + 256 * i;
            int row = idx >> 2, q = idx & 3;
            uint32_t soff = (uint32_t)(row * SA_STRIDE + q * 8) * 2;
            size_t gb = (size_t)(n0 + row) * K + k0 + q * 8;
            cp_async16(s0 + 2 * ATILE_B + soff,           Bhi + gb);
            cp_async16(s0 + 2 * ATILE_B + BTILE_B + soff, Blo + gb);
        }
        CP_COMMIT();
    };

    const int NC = K >> 5;
    load_stage(0, 0);

    for (int c = 0; c < NC; c++) {
        const bool pref = (c + 1 < NC);
        if (pref) load_stage((c + 1) & 1, (c + 1) * 32);
        if (pref) CP_WAIT1(); else CP_WAIT0();
        __syncthreads();

        const uint32_t AH = sb + (c & 1) * STAGE_B;
        const uint32_t AL = AH + ATILE_B;
        const uint32_t BH = AH + 2 * ATILE_B;
        const uint32_t BL = BH + BTILE_B;

#pragma unroll
        for (int ks = 0; ks < 2; ks++) {
            const int kk = ks * 16;
            uint32_t ah[4][4], al[4][4], bh[4][4], bl[4][4];

            auto loadA = [&](uint32_t base, uint32_t (*f)[4]) {
#pragma unroll
                for (int mt = 0; mt < 4; mt++)
                    ldsm_x4(base + (uint32_t)((wm + mt * 16 + a_row_off) * SA_STRIDE +
                                              kk + a_col_off) * 2, f[mt]);
            };
            auto loadB = [&](uint32_t base, uint32_t (*f)[4]) {
#pragma unroll
                for (int np = 0; np < 4; np++)
                    ldsm_x4(base + (uint32_t)((wn + np * 16 + b_row_off) * SA_STRIDE +
                                              kk + b_col_off) * 2, f[np]);
            };
            auto mmaH = [&](uint32_t (*A)[4], uint32_t (*B)[4], int half) {
#pragma unroll
                for (int mt = 2 * half; mt < 2 * half + 2; mt++)
#pragma unroll
                    for (int np = 0; np < 4; np++) {
                        mma16816(acc[mt][2 * np],     A[mt], B[np][0], B[np][1]);
                        mma16816(acc[mt][2 * np + 1], A[mt], B[np][2], B[np][3]);
                    }
            };

            if (rot == 0) {          // hh, hl, lh
                loadA(AH, ah); loadB(BH, bh);
                mmaH(ah, bh, 0); loadB(BL, bl); mmaH(ah, bh, 1);
                mmaH(ah, bl, 0); loadA(AL, al); mmaH(ah, bl, 1);
                mmaH(al, bh, 0); mmaH(al, bh, 1);
            } else if (rot == 1) {   // hl, lh, hh
                loadA(AH, ah); loadB(BL, bl);
                mmaH(ah, bl, 0); loadA(AL, al); mmaH(ah, bl, 1);
                loadB(BH, bh);
                mmaH(al, bh, 0); mmaH(al, bh, 1);
                mmaH(ah, bh, 0); mmaH(ah, bh, 1);
            } else {                 // lh, hh, hl
                loadA(AL, al); loadB(BH, bh);
                mmaH(al, bh, 0); loadA(AH, ah); mmaH(al, bh, 1);
                mmaH(ah, bh, 0); loadB(BL, bl); mmaH(ah, bh, 1);
                mmaH(ah, bl, 0); mmaH(ah, bl, 1);
            }
        }
        __syncthreads();
    }

    const int g  = lane >> 2;
    const int t2 = (lane & 3) * 2;
#pragma unroll
    for (int mt = 0; mt < 4; mt++) {
        int mrow0 = m0 + wm + mt * 16 + g;
#pragma unroll
        for (int nt = 0; nt < 8; nt++) {
            int n = n0 + wn + nt * 8 + t2;
            float b0 = 0.f, b1 = 0.f;
            if (HAS_BIAS) { b0 = bias[n]; b1 = bias[n + 1]; }
            float v00 = acc[mt][nt][0] + b0, v01 = acc[mt][nt][1] + b1;
            float v10 = acc[mt][nt][2] + b0, v11 = acc[mt][nt][3] + b1;
            if (SPLIT_OUT) {
                size_t i0 = (size_t)mrow0 * N + n;
                size_t i1 = (size_t)(mrow0 + 8) * N + n;
                float h00 = __bfloat162float(__float2bfloat16_rn(v00));
                float h01 = __bfloat162float(__float2bfloat16_rn(v01));
                float h10 = __bfloat162float(__float2bfloat16_rn(v10));
                float h11 = __bfloat162float(__float2bfloat16_rn(v11));
                *(uint32_t*)(Chi + i0) = pack_bf16(h00, h01);
                *(uint32_t*)(Clo + i0) = pack_bf16(v00 - h00, v01 - h01);
                *(uint32_t*)(Chi + i1) = pack_bf16(h10, h11);
                *(uint32_t*)(Clo + i1) = pack_bf16(v10 - h10, v11 - h11);
            } else {
                *(float2*)(C + (size_t)mrow0 * N + n)       = make_float2(v00, v01);
                *(float2*)(C + (size_t)(mrow0 + 8) * N + n) = make_float2(v10, v11);
            }
        }
    }
}

// ---------------------------------------------------------------------------
// Tensor-core causal flash attention (bf16x3), cp.async double-buffered,
// per-warp pass rotation in S and PV loops. BM=128, BN=64, HD=64, 8 warps.
// ---------------------------------------------------------------------------
#define AT_STRIDE 72
#define AT_TILE (64 * AT_STRIDE * 2)       // 9216 bytes
#define AT_STAGE (4 * AT_TILE)             // 36864: KH, KL, VH, VL
#define ATTN_SMEM (2 * AT_STAGE)           // 73728

#define SCALE2 0.1803368801111244f         // 0.125 * log2(e)

__global__ __launch_bounds__(256)
void attn_mma(const __nv_bfloat16* __restrict__ qkv_hi,
              const __nv_bfloat16* __restrict__ qkv_lo,
              __nv_bfloat16* __restrict__ att_hi,
              __nv_bfloat16* __restrict__ att_lo) {
    extern __shared__ char smem[];
    const uint32_t sb = smem_u32(smem);

    const int tid  = threadIdx.x;
    const int wid  = tid >> 5;
    const int lane = tid & 31;
    const int rot  = wid % 3;
    const int it = gridDim.x - 1 - blockIdx.x;   // big tiles first
    const int h  = blockIdx.y;
    const int b  = blockIdx.z;
    const size_t hbase = (size_t)b * SEQ * F3 + (size_t)h * 192;

    // ---- Stage Q (128x64 hi & lo) through stage-0 buffers ----
#pragma unroll
    for (int i = 0; i < 2; i++) {
        int idx = tid * 2 + i;        // 0..511
        int row = idx >> 3, q = idx & 7;
        uint32_t soff = (uint32_t)(row * AT_STRIDE + q * 8) * 2;
        size_t glo = hbase + (size_t)(it * 128 + row) * F3 + q * 8;
        size_t ghi = hbase + (size_t)(it * 128 + 64 + row) * F3 + q * 8;
        *(uint4*)(smem + soff)               = *(const uint4*)(qkv_hi + glo);
        *(uint4*)(smem + AT_TILE + soff)     = *(const uint4*)(qkv_lo + glo);
        *(uint4*)(smem + 2 * AT_TILE + soff) = *(const uint4*)(qkv_hi + ghi);
        *(uint4*)(smem + 3 * AT_TILE + soff) = *(const uint4*)(qkv_lo + ghi);
    }
    __syncthreads();

    // Q fragments (register resident): warp w owns rows 16*(w&3) + 64*(w>>2)
    uint32_t qh[4][4], ql[4][4];
    {
        uint32_t hb = (wid < 4) ? sb : sb + 2 * AT_TILE;
        uint32_t lb = (wid < 4) ? sb + AT_TILE : sb + 3 * AT_TILE;
        uint32_t qoff = (uint32_t)((16 * (wid & 3) + (lane & 15)) * AT_STRIDE +
                                   (lane >> 4) * 8) * 2;
#pragma unroll
        for (int ks = 0; ks < 4; ks++) {
            ldsm_x4(hb + qoff + ks * 32, qh[ks]);
            ldsm_x4(lb + qoff + ks * 32, ql[ks]);
        }
    }
    __syncthreads();   // everyone done reading Q before stage-0 overwrite

    auto load_kv = [&](int stage, int jt) {
        uint32_t sbase = sb + stage * AT_STAGE;
#pragma unroll
        for (int i = 0; i < 2; i++) {
            int idx = tid * 2 + i;
            int row = idx >> 3, q = idx & 7;
            uint32_t soff = (uint32_t)(row * AT_STRIDE + q * 8) * 2;
            size_t gr = hbase + (size_t)(jt * 64 + row) * F3 + q * 8;
            cp_async16(sbase + soff,               qkv_hi + gr + 64);    // K hi
            cp_async16(sbase + AT_TILE + soff,     qkv_lo + gr + 64);    // K lo
            cp_async16(sbase + 2 * AT_TILE + soff, qkv_hi + gr + 128);   // V hi
            cp_async16(sbase + 3 * AT_TILE + soff, qkv_lo + gr + 128);   // V lo
        }
        CP_COMMIT();
    };

    float m2[2] = {-1e30f, -1e30f}, l[2] = {0.f, 0.f};
    float o[8][4];
#pragma unroll
    for (int dt = 0; dt < 8; dt++)
#pragma unroll
        for (int j = 0; j < 4; j++) o[dt][j] = 0.0f;

    const int rbase = 128 * it + 16 * (wid & 3) + 64 * (wid >> 2);
    const int g  = lane >> 2;
    const int t2 = (lane & 3) * 2;
    const uint32_t koff = (uint32_t)(((lane >> 4) * 8 + (lane & 7)) * AT_STRIDE +
                                     ((lane >> 3) & 1) * 8) * 2;
    const uint32_t voff = (uint32_t)((lane & 15) * AT_STRIDE + (lane >> 4) * 8) * 2;

    const int jt_max = 2 * it + 2;
    load_kv(0, 0);

    for (int jt = 0; jt < jt_max; jt++) {
        const bool pref = (jt + 1 < jt_max);
        if (pref) load_kv((jt + 1) & 1, jt + 1);
        if (pref) CP_WAIT1(); else CP_WAIT0();
        __syncthreads();

        const uint32_t KH = sb + (jt & 1) * AT_STAGE;
        const uint32_t KL = KH + AT_TILE;
        const uint32_t VH = KH + 2 * AT_TILE;
        const uint32_t VL = KH + 3 * AT_TILE;

        // ---- S = Q K^T (pass-rotated per warp) ----
        float s[8][4];
#pragma unroll
        for (int nt = 0; nt < 8; nt++)
#pragma unroll
            for (int j = 0; j < 4; j++) s[nt][j] = 0.0f;

#pragma unroll
        for (int ks = 0; ks < 4; ks++) {
            uint32_t kh[4][4], kl[4][4];
            auto loadK = [&](uint32_t base, uint32_t (*f)[4]) {
#pragma unroll
                for (int np = 0; np < 4; np++)
                    ldsm_x4(base + koff + (uint32_t)(np * 16 * AT_STRIDE + ks * 16) * 2, f[np]);
            };
            auto smmaH = [&](const uint32_t A[4], uint32_t (*B)[4], int half) {
#pragma unroll
                for (int np = 2 * half; np < 2 * half + 2; np++) {
                    mma16816(s[2 * np],     A, B[np][0], B[np][1]);
                    mma16816(s[2 * np + 1], A, B[np][2], B[np][3]);
                }
            };
            if (rot == 0) {          // qh*kh, qh*kl, ql*kh
                loadK(KH, kh);
                smmaH(qh[ks], kh, 0); loadK(KL, kl); smmaH(qh[ks], kh, 1);
                smmaH(qh[ks], kl, 0); smmaH(qh[ks], kl, 1);
                smmaH(ql[ks], kh, 0); smmaH(ql[ks], kh, 1);
            } else if (rot == 1) {   // qh*kl, ql*kh, qh*kh
                loadK(KL, kl);
                smmaH(qh[ks], kl, 0); loadK(KH, kh); smmaH(qh[ks], kl, 1);
                smmaH(ql[ks], kh, 0); smmaH(ql[ks], kh, 1);
                smmaH(qh[ks], kh, 0); smmaH(qh[ks], kh, 1);
            } else {                 // ql*kh, qh*kh, qh*kl
                loadK(KH, kh);
                smmaH(ql[ks], kh, 0); smmaH(ql[ks], kh, 1);
                smmaH(qh[ks], kh, 0); loadK(KL, kl); smmaH(qh[ks], kh, 1);
                smmaH(qh[ks], kl, 0); smmaH(qh[ks], kl, 1);
            }
        }

        // ---- scale (+ causal mask on diagonal tiles) ----
        const bool diag = (jt >= 2 * it);
#pragma unroll
        for (int nt = 0; nt < 8; nt++)
#pragma unroll
            for (int j = 0; j < 4; j++) {
                float t = s[nt][j] * SCALE2;
                if (diag) {
                    int col = jt * 64 + nt * 8 + t2 + (j & 1);
                    int row = rbase + g + 8 * (j >> 1);
                    if (col > row) t = -1e30f;
                }
                s[nt][j] = t;
            }

        // ---- online softmax ----
        float rmax[2] = {-1e30f, -1e30f};
#pragma unroll
        for (int nt = 0; nt < 8; nt++) {
            rmax[0] = fmaxf(rmax[0], fmaxf(s[nt][0], s[nt][1]));
            rmax[1] = fmaxf(rmax[1], fmaxf(s[nt][2], s[nt][3]));
        }
#pragma unroll
        for (int off = 1; off <= 2; off <<= 1) {
            rmax[0] = fmaxf(rmax[0], __shfl_xor_sync(0xffffffffu, rmax[0], off));
            rmax[1] = fmaxf(rmax[1], __shfl_xor_sync(0xffffffffu, rmax[1], off));
        }
        float alpha[2], rsum[2];
#pragma unroll
        for (int r = 0; r < 2; r++) {
            float mnew = fmaxf(m2[r], rmax[r]);
            alpha[r] = ex2(m2[r] - mnew);
            m2[r] = mnew;
            rsum[r] = 0.f;
        }
#pragma unroll
        for (int nt = 0; nt < 8; nt++) {
            s[nt][0] = ex2(s[nt][0] - m2[0]);
            s[nt][1] = ex2(s[nt][1] - m2[0]);
            s[nt][2] = ex2(s[nt][2] - m2[1]);
            s[nt][3] = ex2(s[nt][3] - m2[1]);
            rsum[0] += s[nt][0] + s[nt][1];
            rsum[1] += s[nt][2] + s[nt][3];
        }
#pragma unroll
        for (int off = 1; off <= 2; off <<= 1) {
            rsum[0] += __shfl_xor_sync(0xffffffffu, rsum[0], off);
            rsum[1] += __shfl_xor_sync(0xffffffffu, rsum[1], off);
        }
#pragma unroll
        for (int r = 0; r < 2; r++) l[r] = l[r] * alpha[r] + rsum[r];
#pragma unroll
        for (int dt = 0; dt < 8; dt++) {
            o[dt][0] *= alpha[0];
            o[dt][1] *= alpha[0];
            o[dt][2] *= alpha[1];
            o[dt][3] *= alpha[1];
        }

        // ---- pack P into A-fragments (hi + lo) ----
        uint32_t ph[4][4], pl[4][4];
#pragma unroll
        for (int ks = 0; ks < 4; ks++) {
#pragma unroll
            for (int half = 0; half < 2; half++) {
                int nt = 2 * ks + half;
                float p0 = s[nt][0], p1 = s[nt][1], p2 = s[nt][2], p3 = s[nt][3];
                float h0 = __bfloat162float(__float2bfloat16_rn(p0));
                float h1 = __bfloat162float(__float2bfloat16_rn(p1));
                float h2 = __bfloat162float(__float2bfloat16_rn(p2));
                float h3 = __bfloat162float(__float2bfloat16_rn(p3));
                ph[ks][2 * half]     = pack_bf16(h0, h1);
                ph[ks][2 * half + 1] = pack_bf16(h2, h3);
                pl[ks][2 * half]     = pack_bf16(p0 - h0, p1 - h1);
                pl[ks][2 * half + 1] = pack_bf16(p2 - h2, p3 - h3);
            }
        }

        // ---- O += P V (pass-rotated per warp; ldmatrix.trans V) ----
#pragma unroll
        for (int ks = 0; ks < 4; ks++) {
            uint32_t vh[4][4], vl[4][4];
            auto loadV = [&](uint32_t base, uint32_t (*f)[4]) {
#pragma unroll
                for (int np = 0; np < 4; np++)
                    ldsm_x4_t(base + voff + (uint32_t)(ks * 16 * AT_STRIDE + np * 16) * 2, f[np]);
            };
            auto ommaH = [&](const uint32_t A[4], uint32_t (*B)[4], int half) {
#pragma unroll
                for (int np = 2 * half; np < 2 * half + 2; np++) {
                    mma16816(o[2 * np],     A, B[np][0], B[np][1]);
                    mma16816(o[2 * np + 1], A, B[np][2], B[np][3]);
                }
            };
            if (rot == 0) {          // ph*vh, ph*vl, pl*vh
                loadV(VH, vh);
                ommaH(ph[ks], vh, 0); loadV(VL, vl); ommaH(ph[ks], vh, 1);
                ommaH(ph[ks], vl, 0); ommaH(ph[ks], vl, 1);
                ommaH(pl[ks], vh, 0); ommaH(pl[ks], vh, 1);
            } else if (rot == 1) {   // ph*vl, pl*vh, ph*vh
                loadV(VL, vl);
                ommaH(ph[ks], vl, 0); loadV(VH, vh); ommaH(ph[ks], vl, 1);
                ommaH(pl[ks], vh, 0); ommaH(pl[ks], vh, 1);
                ommaH(ph[ks], vh, 0); ommaH(ph[ks], vh, 1);
            } else {                 // pl*vh, ph*vh, ph*vl
                loadV(VH, vh);
                ommaH(pl[ks], vh, 0); ommaH(pl[ks], vh, 1);
                ommaH(ph[ks], vh, 0); loadV(VL, vl); ommaH(ph[ks], vh, 1);
                ommaH(ph[ks], vl, 0); ommaH(ph[ks], vl, 1);
            }
        }
        __syncthreads();
    }

    // ---- epilogue: O/l -> att hi/lo ----
    float inv0 = 1.0f / l[0], inv1 = 1.0f / l[1];
#pragma unroll
    for (int dt = 0; dt < 8; dt++) {
        int col = h * 64 + dt * 8 + t2;
        size_t i0 = ((size_t)b * SEQ + rbase + g) * EMB + col;
        size_t i1 = ((size_t)b * SEQ + rbase + g + 8) * EMB + col;
        float v00 = o[dt][0] * inv0, v01 = o[dt][1] * inv0;
        float v10 = o[dt][2] * inv1, v11 = o[dt][3] * inv1;
        float h00 = __bfloat162float(__float2bfloat16_rn(v00));
        float h01 = __bfloat162float(__float2bfloat16_rn(v01));
        float h10 = __bfloat162float(__float2bfloat16_rn(v10));
        float h11 = __bfloat162float(__float2bfloat16_rn(v11));
        *(uint32_t*)(att_hi + i0) = pack_bf16(h00, h01);
        *(uint32_t*)(att_lo + i0) = pack_bf16(v00 - h00, v01 - h01);
        *(uint32_t*)(att_hi + i1) = pack_bf16(h10, h11);
        *(uint32_t*)(att_lo + i1) = pack_bf16(v10 - h10, v11 - h11);
    }
}

// ---------------------------------------------------------------------------
// Launch
// ---------------------------------------------------------------------------
extern "C" void kernel_launch(void* const* d_in, const int* in_sizes, int n_in,
                              void* d_out, int out_size) {
    const float* x      = (const float*)d_in[0];
    const float* w_qkv  = (const float*)d_in[1];
    const float* w_out  = (const float*)d_in[2];
    const float* b_out  = (const float*)d_in[3];
    float* out = (float*)d_out;

    __nv_bfloat16 *x_hi, *x_lo, *wq_hi, *wq_lo, *wo_hi, *wo_lo;
    __nv_bfloat16 *qkv_hi, *qkv_lo, *a_hi, *a_lo;
    cudaGetSymbolAddress((void**)&x_hi,   g_x_hi);
    cudaGetSymbolAddress((void**)&x_lo,   g_x_lo);
    cudaGetSymbolAddress((void**)&wq_hi,  g_wqkv_hi);
    cudaGetSymbolAddress((void**)&wq_lo,  g_wqkv_lo);
    cudaGetSymbolAddress((void**)&wo_hi,  g_wout_hi);
    cudaGetSymbolAddress((void**)&wo_lo,  g_wout_lo);
    cudaGetSymbolAddress((void**)&qkv_hi, g_qkv_hi);
    cudaGetSymbolAddress((void**)&qkv_lo, g_qkv_lo);
    cudaGetSymbolAddress((void**)&a_hi,   g_att_hi);
    cudaGetSymbolAddress((void**)&a_lo,   g_att_lo);

    cudaFuncSetAttribute(attn_mma,
                         cudaFuncAttributeMaxDynamicSharedMemorySize, ATTN_SMEM);
    cudaFuncSetAttribute((const void*)gemm_mma<false, true>,
                         cudaFuncAttributeMaxDynamicSharedMemorySize, GEMM_SMEM);
    cudaFuncSetAttribute((const void*)gemm_mma<true, false>,
                         cudaFuncAttributeMaxDynamicSharedMemorySize, GEMM_SMEM);

    // 0) bf16 hi/lo splits of inputs
    {
        int n4 = ROWS * EMB / 4;
        split_bf16<<<(n4 + 255) / 256, 256>>>((const float4*)x,
            (__nv_bfloat162*)x_hi, (__nv_bfloat162*)x_lo, n4);
        n4 = F3 * EMB / 4;
        split_bf16<<<(n4 + 255) / 256, 256>>>((const float4*)w_qkv,
            (__nv_bfloat162*)wq_hi, (__nv_bfloat162*)wq_lo, n4);
        n4 = EMB * EMB / 4;
        split_bf16<<<(n4 + 255) / 256, 256>>>((const float4*)w_out,
            (__nv_bfloat162*)wo_hi, (__nv_bfloat162*)wo_lo, n4);
    }

    // 1) QKV projection -> bf16 hi/lo qkv directly
    gemm_mma<false, true><<<dim3(F3 / 128, ROWS / 256), 256, GEMM_SMEM>>>(
        x_hi, x_lo, wq_hi, wq_lo, nullptr, nullptr, qkv_hi, qkv_lo, F3, EMB);

    // 2) Tensor-core causal flash attention -> att hi/lo
    attn_mma<<<dim3(SEQ / 128, NH, BS), 256, ATTN_SMEM>>>(qkv_hi, qkv_lo, a_hi, a_lo);

    // 3) Output projection + bias -> fp32 out
    gemm_mma<true, false><<<dim3(EMB / 128, ROWS / 256), 256, GEMM_SMEM>>>(
        a_hi, a_lo, wo_hi, wo_lo, b_out, out, nullptr, nullptr, EMB, EMB);
}

// round 8
// speedup vs baseline: 1.4099x; 1.4099x over previous
#include <cuda_runtime.h>
#include <cuda_fp16.h>
#include <cstdint>
#include <math.h>

// Problem constants (fixed shapes)
#define BS   2
#define SEQ  2048
#define EMB  1024
#define NH   16
#define HD   64
#define F3   3072   // 3*EMB
#define ROWS (BS * SEQ)   // 4096

// ---------------------------------------------------------------------------
// Scratch (device globals: allocation-free rule)
// ---------------------------------------------------------------------------
__device__ __half g_x_hi[ROWS * EMB];
__device__ __half g_x_lo[ROWS * EMB];
__device__ __half g_wqkv_hi[F3 * EMB];      // single-rounded weights (B operand)
__device__ __half g_wout_hi[EMB * EMB];
__device__ __half g_qkv_hi[ROWS * F3];
__device__ __half g_qkv_lo[ROWS * F3];
__device__ __half g_att_hi[ROWS * EMB];
__device__ __half g_att_lo[ROWS * EMB];

// ---------------------------------------------------------------------------
// helpers
// ---------------------------------------------------------------------------
__device__ __forceinline__ uint32_t smem_u32(const void* p) {
    uint32_t a;
    asm("{ .reg .u64 t; cvta.to.shared.u64 t, %1; cvt.u32.u64 %0, t; }" : "=r"(a) : "l"(p));
    return a;
}
__device__ __forceinline__ void ldsm_x4(uint32_t addr, uint32_t r[4]) {
    asm volatile("ldmatrix.sync.aligned.m8n8.x4.shared.b16 {%0,%1,%2,%3}, [%4];"
                 : "=r"(r[0]), "=r"(r[1]), "=r"(r[2]), "=r"(r[3]) : "r"(addr));
}
__device__ __forceinline__ void ldsm_x4_t(uint32_t addr, uint32_t r[4]) {
    asm volatile("ldmatrix.sync.aligned.m8n8.x4.trans.shared.b16 {%0,%1,%2,%3}, [%4];"
                 : "=r"(r[0]), "=r"(r[1]), "=r"(r[2]), "=r"(r[3]) : "r"(addr));
}
__device__ __forceinline__ void mma16816(float c[4], const uint32_t a[4],
                                         const uint32_t b0, const uint32_t b1) {
    asm volatile(
        "mma.sync.aligned.m16n8k16.row.col.f32.f16.f16.f32 "
        "{%0,%1,%2,%3}, {%4,%5,%6,%7}, {%8,%9}, {%0,%1,%2,%3};"
        : "+f"(c[0]), "+f"(c[1]), "+f"(c[2]), "+f"(c[3])
        : "r"(a[0]), "r"(a[1]), "r"(a[2]), "r"(a[3]), "r"(b0), "r"(b1));
}
__device__ __forceinline__ uint32_t pack_f16(float lo, float hi) {
    __half2 h = __floats2half2_rn(lo, hi);
    return *(uint32_t*)&h;
}
__device__ __forceinline__ float ex2(float x) {
    float r;
    asm("ex2.approx.ftz.f32 %0, %1;" : "=f"(r) : "f"(x));
    return r;
}
__device__ __forceinline__ void cp_async16(uint32_t dst, const void* src) {
    asm volatile("cp.async.cg.shared.global [%0], [%1], 16;" :: "r"(dst), "l"(src));
}
#define CP_COMMIT() asm volatile("cp.async.commit_group;" ::: "memory")
#define CP_WAIT1()  asm volatile("cp.async.wait_group 1;" ::: "memory")
#define CP_WAIT0()  asm volatile("cp.async.wait_group 0;" ::: "memory")

// ---------------------------------------------------------------------------
// fp16 hi/lo split (float4 vectorized). hi alone = single-rounded value.
// ---------------------------------------------------------------------------
__global__ void split_f16(const float4* __restrict__ in,
                          __half2* __restrict__ hi,
                          __half2* __restrict__ lo, int n4) {
    int i = blockIdx.x * blockDim.x + threadIdx.x;
    if (i >= n4) return;
    float4 v = in[i];
    __half h0 = __float2half_rn(v.x);
    __half h1 = __float2half_rn(v.y);
    __half h2 = __float2half_rn(v.z);
    __half h3 = __float2half_rn(v.w);
    hi[2 * i]     = __half2(h0, h1);
    hi[2 * i + 1] = __half2(h2, h3);
    if (lo) {
        __half l0 = __float2half_rn(v.x - __half2float(h0));
        __half l1 = __float2half_rn(v.y - __half2float(h1));
        __half l2 = __float2half_rn(v.z - __half2float(h2));
        __half l3 = __float2half_rn(v.w - __half2float(h3));
        lo[2 * i]     = __half2(l0, l1);
        lo[2 * i + 1] = __half2(l2, l3);
    }
}

// ---------------------------------------------------------------------------
// mma.sync fp16x2 GEMM (A split hi/lo, B single), cp.async double-buffered.
// CTA tile 256x128, 8 warps, warp tile 64x64, BK=32. 2 passes: Ahi*B + Alo*B.
// ---------------------------------------------------------------------------
#define SA_STRIDE 40
#define ATILE_B (256 * SA_STRIDE * 2)           // 20480
#define BTILE_B (128 * SA_STRIDE * 2)           // 10240
#define STAGE_B (2 * ATILE_B + BTILE_B)         // 51200
#define GEMM_SMEM (2 * STAGE_B)                 // 102400

template <bool HAS_BIAS, bool SPLIT_OUT>
__global__ __launch_bounds__(256, 1)
void gemm_mma(const __half* __restrict__ Ahi, const __half* __restrict__ Alo,
              const __half* __restrict__ B,
              const float* __restrict__ bias, float* __restrict__ C,
              __half* __restrict__ Chi, __half* __restrict__ Clo,
              int N, int K) {
    extern __shared__ char smem[];
    const uint32_t sb = smem_u32(smem);

    const int tid  = threadIdx.x;
    const int wid  = tid >> 5;
    const int lane = tid & 31;
    const int n0 = blockIdx.x * 128;
    const int m0 = blockIdx.y * 256;
    const int wm = (wid & 3) * 64;
    const int wn = (wid >> 2) * 64;

    const int trow  = lane & 7;
    const int tquad = lane >> 3;
    const int a_row_off = (tquad & 1) * 8 + trow;
    const int a_col_off = (tquad >> 1) * 8;
    const int b_row_off = (tquad >> 1) * 8 + trow;
    const int b_col_off = (tquad & 1) * 8;

    float acc[4][8][4];
#pragma unroll
    for (int mt = 0; mt < 4; mt++)
#pragma unroll
        for (int nt = 0; nt < 8; nt++)
#pragma unroll
            for (int j = 0; j < 4; j++) acc[mt][nt][j] = 0.0f;

    auto load_stage = [&](int stage, int k0) {
        uint32_t s0 = sb + stage * STAGE_B;
#pragma unroll
        for (int i = 0; i < 4; i++) {
            int idx = tid + 256 * i;
            int row = idx >> 2, q = idx & 3;
            uint32_t soff = (uint32_t)(row * SA_STRIDE + q * 8) * 2;
            size_t ga = (size_t)(m0 + row) * K + k0 + q * 8;
            cp_async16(s0 + soff,            Ahi + ga);
            cp_async16(s0 + ATILE_B + soff,  Alo + ga);
        }
#pragma unroll
        for (int i = 0; i < 2; i++) {
            int idx = tid + 256 * i;
            int row = idx >> 2, q = idx & 3;
            uint32_t soff = (uint32_t)(row * SA_STRIDE + q * 8) * 2;
            size_t gb = (size_t)(n0 + row) * K + k0 + q * 8;
            cp_async16(s0 + 2 * ATILE_B + soff, B + gb);
        }
        CP_COMMIT();
    };

    const int NC = K >> 5;
    load_stage(0, 0);

    for (int c = 0; c < NC; c++) {
        const bool pref = (c + 1 < NC);
        if (pref) load_stage((c + 1) & 1, (c + 1) * 32);
        if (pref) CP_WAIT1(); else CP_WAIT0();
        __syncthreads();

        const uint32_t AH = sb + (c & 1) * STAGE_B;
        const uint32_t AL = AH + ATILE_B;
        const uint32_t BB = AH + 2 * ATILE_B;

#pragma unroll
        for (int ks = 0; ks < 2; ks++) {
            const int kk = ks * 16;
            uint32_t ah[4][4], al[4][4], bf[4][4];

#pragma unroll
            for (int mt = 0; mt < 4; mt++)
                ldsm_x4(AH + (uint32_t)((wm + mt * 16 + a_row_off) * SA_STRIDE +
                                        kk + a_col_off) * 2, ah[mt]);
#pragma unroll
            for (int np = 0; np < 4; np++)
                ldsm_x4(BB + (uint32_t)((wn + np * 16 + b_row_off) * SA_STRIDE +
                                        kk + b_col_off) * 2, bf[np]);
            // pass 1: Ahi * B (first half), prefetch Alo mid-burst
#pragma unroll
            for (int mt = 0; mt < 2; mt++)
#pragma unroll
                for (int np = 0; np < 4; np++) {
                    mma16816(acc[mt][2 * np],     ah[mt], bf[np][0], bf[np][1]);
                    mma16816(acc[mt][2 * np + 1], ah[mt], bf[np][2], bf[np][3]);
                }
#pragma unroll
            for (int mt = 0; mt < 4; mt++)
                ldsm_x4(AL + (uint32_t)((wm + mt * 16 + a_row_off) * SA_STRIDE +
                                        kk + a_col_off) * 2, al[mt]);
#pragma unroll
            for (int mt = 2; mt < 4; mt++)
#pragma unroll
                for (int np = 0; np < 4; np++) {
                    mma16816(acc[mt][2 * np],     ah[mt], bf[np][0], bf[np][1]);
                    mma16816(acc[mt][2 * np + 1], ah[mt], bf[np][2], bf[np][3]);
                }
            // pass 2: Alo * B
#pragma unroll
            for (int mt = 0; mt < 4; mt++)
#pragma unroll
                for (int np = 0; np < 4; np++) {
                    mma16816(acc[mt][2 * np],     al[mt], bf[np][0], bf[np][1]);
                    mma16816(acc[mt][2 * np + 1], al[mt], bf[np][2], bf[np][3]);
                }
        }
        __syncthreads();
    }

    const int g  = lane >> 2;
    const int t2 = (lane & 3) * 2;
#pragma unroll
    for (int mt = 0; mt < 4; mt++) {
        int mrow0 = m0 + wm + mt * 16 + g;
#pragma unroll
        for (int nt = 0; nt < 8; nt++) {
            int n = n0 + wn + nt * 8 + t2;
            float b0 = 0.f, b1 = 0.f;
            if (HAS_BIAS) { b0 = bias[n]; b1 = bias[n + 1]; }
            float v00 = acc[mt][nt][0] + b0, v01 = acc[mt][nt][1] + b1;
            float v10 = acc[mt][nt][2] + b0, v11 = acc[mt][nt][3] + b1;
            if (SPLIT_OUT) {
                size_t i0 = (size_t)mrow0 * N + n;
                size_t i1 = (size_t)(mrow0 + 8) * N + n;
                float h00 = __half2float(__float2half_rn(v00));
                float h01 = __half2float(__float2half_rn(v01));
                float h10 = __half2float(__float2half_rn(v10));
                float h11 = __half2float(__float2half_rn(v11));
                *(uint32_t*)(Chi + i0) = pack_f16(h00, h01);
                *(uint32_t*)(Clo + i0) = pack_f16(v00 - h00, v01 - h01);
                *(uint32_t*)(Chi + i1) = pack_f16(h10, h11);
                *(uint32_t*)(Clo + i1) = pack_f16(v10 - h10, v11 - h11);
            } else {
                *(float2*)(C + (size_t)mrow0 * N + n)       = make_float2(v00, v01);
                *(float2*)(C + (size_t)(mrow0 + 8) * N + n) = make_float2(v10, v11);
            }
        }
    }
}

// ---------------------------------------------------------------------------
// Tensor-core causal flash attention (fp16x2): Q split hi/lo (exact), K and V
// single fp16, P split hi/lo in registers. BM=128, BN=64, HD=64, 8 warps.
// cp.async double-buffered (K,V tiles only -> stage = 2 tiles).
// ---------------------------------------------------------------------------
#define AT_STRIDE 72
#define AT_TILE (64 * AT_STRIDE * 2)       // 9216 bytes
#define AT_STAGE (2 * AT_TILE)             // 18432: K, V
#define ATTN_SMEM (2 * AT_STAGE)           // 36864

#define SCALE2 0.1803368801111244f         // 0.125 * log2(e)

__global__ __launch_bounds__(256)
void attn_mma(const __half* __restrict__ qkv_hi,
              const __half* __restrict__ qkv_lo,
              __half* __restrict__ att_hi,
              __half* __restrict__ att_lo) {
    extern __shared__ char smem[];
    const uint32_t sb = smem_u32(smem);

    const int tid  = threadIdx.x;
    const int wid  = tid >> 5;
    const int lane = tid & 31;
    const int it = gridDim.x - 1 - blockIdx.x;   // big tiles first
    const int h  = blockIdx.y;
    const int b  = blockIdx.z;
    const size_t hbase = (size_t)b * SEQ * F3 + (size_t)h * 192;

    // ---- Stage Q: hi rows0-63 -> s0t0, hi rows64-127 -> s0t1,
    //               lo rows0-63 -> s1t0, lo rows64-127 -> s1t1 ----
#pragma unroll
    for (int i = 0; i < 4; i++) {
        int idx = tid + 256 * i;      // 0..1023
        int row = idx >> 3, q = idx & 7;
        int tsel = row >> 6, drow = row & 63;
        uint32_t soff = (uint32_t)(tsel * AT_TILE + (drow * AT_STRIDE + q * 8) * 2);
        size_t gq = hbase + (size_t)(it * 128 + row) * F3 + q * 8;
        *(uint4*)(smem + soff)            = *(const uint4*)(qkv_hi + gq);
        *(uint4*)(smem + AT_STAGE + soff) = *(const uint4*)(qkv_lo + gq);
    }
    __syncthreads();

    // Q fragments: warp w owns rows 16*(w&3) + 64*(w>>2)
    uint32_t qh[4][4], ql[4][4];
    {
        uint32_t hb = sb + (wid >> 2) * AT_TILE;
        uint32_t lb = hb + AT_STAGE;
        uint32_t qoff = (uint32_t)((16 * (wid & 3) + (lane & 15)) * AT_STRIDE +
                                   (lane >> 4) * 8) * 2;
#pragma unroll
        for (int ks = 0; ks < 4; ks++) {
            ldsm_x4(hb + qoff + ks * 32, qh[ks]);
            ldsm_x4(lb + qoff + ks * 32, ql[ks]);
        }
    }
    __syncthreads();   // everyone done reading Q before overwrite

    auto load_kv = [&](int stage, int jt) {
        uint32_t sbase = sb + stage * AT_STAGE;
#pragma unroll
        for (int i = 0; i < 2; i++) {
            int idx = tid * 2 + i;
            int row = idx >> 3, q = idx & 7;
            uint32_t soff = (uint32_t)(row * AT_STRIDE + q * 8) * 2;
            size_t gr = hbase + (size_t)(jt * 64 + row) * F3 + q * 8;
            cp_async16(sbase + soff,           qkv_hi + gr + 64);    // K
            cp_async16(sbase + AT_TILE + soff, qkv_hi + gr + 128);   // V
        }
        CP_COMMIT();
    };

    float m2[2] = {-1e30f, -1e30f}, l[2] = {0.f, 0.f};
    float o[8][4];
#pragma unroll
    for (int dt = 0; dt < 8; dt++)
#pragma unroll
        for (int j = 0; j < 4; j++) o[dt][j] = 0.0f;

    const int rbase = 128 * it + 16 * (wid & 3) + 64 * (wid >> 2);
    const int g  = lane >> 2;
    const int t2 = (lane & 3) * 2;
    const uint32_t koff = (uint32_t)(((lane >> 4) * 8 + (lane & 7)) * AT_STRIDE +
                                     ((lane >> 3) & 1) * 8) * 2;
    const uint32_t voff = (uint32_t)((lane & 15) * AT_STRIDE + (lane >> 4) * 8) * 2;

    const int jt_max = 2 * it + 2;
    load_kv(0, 0);

    for (int jt = 0; jt < jt_max; jt++) {
        const bool pref = (jt + 1 < jt_max);
        if (pref) load_kv((jt + 1) & 1, jt + 1);
        if (pref) CP_WAIT1(); else CP_WAIT0();
        __syncthreads();

        const uint32_t KB = sb + (jt & 1) * AT_STAGE;
        const uint32_t VB = KB + AT_TILE;

        // ---- S = (Qhi + Qlo) K^T : 2 passes ----
        float s[8][4];
#pragma unroll
        for (int nt = 0; nt < 8; nt++)
#pragma unroll
            for (int j = 0; j < 4; j++) s[nt][j] = 0.0f;

#pragma unroll
        for (int ks = 0; ks < 4; ks++) {
            uint32_t kf[4][4];
#pragma unroll
            for (int np = 0; np < 4; np++)
                ldsm_x4(KB + koff + (uint32_t)(np * 16 * AT_STRIDE + ks * 16) * 2, kf[np]);
#pragma unroll
            for (int np = 0; np < 4; np++) {
                mma16816(s[2 * np],     qh[ks], kf[np][0], kf[np][1]);
                mma16816(s[2 * np + 1], qh[ks], kf[np][2], kf[np][3]);
            }
#pragma unroll
            for (int np = 0; np < 4; np++) {
                mma16816(s[2 * np],     ql[ks], kf[np][0], kf[np][1]);
                mma16816(s[2 * np + 1], ql[ks], kf[np][2], kf[np][3]);
            }
        }

        // ---- scale (+ causal mask on diagonal tiles) ----
        const bool diag = (jt >= 2 * it);
#pragma unroll
        for (int nt = 0; nt < 8; nt++)
#pragma unroll
            for (int j = 0; j < 4; j++) {
                float t = s[nt][j] * SCALE2;
                if (diag) {
                    int col = jt * 64 + nt * 8 + t2 + (j & 1);
                    int row = rbase + g + 8 * (j >> 1);
                    if (col > row) t = -1e30f;
                }
                s[nt][j] = t;
            }

        // ---- online softmax ----
        float rmax[2] = {-1e30f, -1e30f};
#pragma unroll
        for (int nt = 0; nt < 8; nt++) {
            rmax[0] = fmaxf(rmax[0], fmaxf(s[nt][0], s[nt][1]));
            rmax[1] = fmaxf(rmax[1], fmaxf(s[nt][2], s[nt][3]));
        }
#pragma unroll
        for (int off = 1; off <= 2; off <<= 1) {
            rmax[0] = fmaxf(rmax[0], __shfl_xor_sync(0xffffffffu, rmax[0], off));
            rmax[1] = fmaxf(rmax[1], __shfl_xor_sync(0xffffffffu, rmax[1], off));
        }
        float alpha[2], rsum[2];
#pragma unroll
        for (int r = 0; r < 2; r++) {
            float mnew = fmaxf(m2[r], rmax[r]);
            alpha[r] = ex2(m2[r] - mnew);
            m2[r] = mnew;
            rsum[r] = 0.f;
        }
#pragma unroll
        for (int nt = 0; nt < 8; nt++) {
            s[nt][0] = ex2(s[nt][0] - m2[0]);
            s[nt][1] = ex2(s[nt][1] - m2[0]);
            s[nt][2] = ex2(s[nt][2] - m2[1]);
            s[nt][3] = ex2(s[nt][3] - m2[1]);
            rsum[0] += s[nt][0] + s[nt][1];
            rsum[1] += s[nt][2] + s[nt][3];
        }
#pragma unroll
        for (int off = 1; off <= 2; off <<= 1) {
            rsum[0] += __shfl_xor_sync(0xffffffffu, rsum[0], off);
            rsum[1] += __shfl_xor_sync(0xffffffffu, rsum[1], off);
        }
#pragma unroll
        for (int r = 0; r < 2; r++) l[r] = l[r] * alpha[r] + rsum[r];
#pragma unroll
        for (int dt = 0; dt < 8; dt++) {
            o[dt][0] *= alpha[0];
            o[dt][1] *= alpha[0];
            o[dt][2] *= alpha[1];
            o[dt][3] *= alpha[1];
        }

        // ---- pack P into hi/lo A-fragments ----
        uint32_t ph[4][4], pl[4][4];
#pragma unroll
        for (int ks = 0; ks < 4; ks++) {
#pragma unroll
            for (int half = 0; half < 2; half++) {
                int nt = 2 * ks + half;
                float p0 = s[nt][0], p1 = s[nt][1], p2 = s[nt][2], p3 = s[nt][3];
                float h0 = __half2float(__float2half_rn(p0));
                float h1 = __half2float(__float2half_rn(p1));
                float h2 = __half2float(__float2half_rn(p2));
                float h3 = __half2float(__float2half_rn(p3));
                ph[ks][2 * half]     = pack_f16(h0, h1);
                ph[ks][2 * half + 1] = pack_f16(h2, h3);
                pl[ks][2 * half]     = pack_f16(p0 - h0, p1 - h1);
                pl[ks][2 * half + 1] = pack_f16(p2 - h2, p3 - h3);
            }
        }

        // ---- O += (Phi + Plo) V : 2 passes ----
#pragma unroll
        for (int ks = 0; ks < 4; ks++) {
            uint32_t vf[4][4];
#pragma unroll
            for (int np = 0; np < 4; np++)
                ldsm_x4_t(VB + voff + (uint32_t)(ks * 16 * AT_STRIDE + np * 16) * 2, vf[np]);
#pragma unroll
            for (int np = 0; np < 4; np++) {
                mma16816(o[2 * np],     ph[ks], vf[np][0], vf[np][1]);
                mma16816(o[2 * np + 1], ph[ks], vf[np][2], vf[np][3]);
            }
#pragma unroll
            for (int np = 0; np < 4; np++) {
                mma16816(o[2 * np],     pl[ks], vf[np][0], vf[np][1]);
                mma16816(o[2 * np + 1], pl[ks], vf[np][2], vf[np][3]);
            }
        }
        __syncthreads();
    }

    // ---- epilogue: O/l -> att hi/lo ----
    float inv0 = 1.0f / l[0], inv1 = 1.0f / l[1];
#pragma unroll
    for (int dt = 0; dt < 8; dt++) {
        int col = h * 64 + dt * 8 + t2;
        size_t i0 = ((size_t)b * SEQ + rbase + g) * EMB + col;
        size_t i1 = ((size_t)b * SEQ + rbase + g + 8) * EMB + col;
        float v00 = o[dt][0] * inv0, v01 = o[dt][1] * inv0;
        float v10 = o[dt][2] * inv1, v11 = o[dt][3] * inv1;
        float h00 = __half2float(__float2half_rn(v00));
        float h01 = __half2float(__float2half_rn(v01));
        float h10 = __half2float(__float2half_rn(v10));
        float h11 = __half2float(__float2half_rn(v11));
        *(uint32_t*)(att_hi + i0) = pack_f16(h00, h01);
        *(uint32_t*)(att_lo + i0) = pack_f16(v00 - h00, v01 - h01);
        *(uint32_t*)(att_hi + i1) = pack_f16(h10, h11);
        *(uint32_t*)(att_lo + i1) = pack_f16(v10 - h10, v11 - h11);
    }
}

// ---------------------------------------------------------------------------
// Launch
// ---------------------------------------------------------------------------
extern "C" void kernel_launch(void* const* d_in, const int* in_sizes, int n_in,
                              void* d_out, int out_size) {
    const float* x      = (const float*)d_in[0];
    const float* w_qkv  = (const float*)d_in[1];
    const float* w_out  = (const float*)d_in[2];
    const float* b_out  = (const float*)d_in[3];
    float* out = (float*)d_out;

    __half *x_hi, *x_lo, *wq_hi, *wo_hi, *qkv_hi, *qkv_lo, *a_hi, *a_lo;
    cudaGetSymbolAddress((void**)&x_hi,   g_x_hi);
    cudaGetSymbolAddress((void**)&x_lo,   g_x_lo);
    cudaGetSymbolAddress((void**)&wq_hi,  g_wqkv_hi);
    cudaGetSymbolAddress((void**)&wo_hi,  g_wout_hi);
    cudaGetSymbolAddress((void**)&qkv_hi, g_qkv_hi);
    cudaGetSymbolAddress((void**)&qkv_lo, g_qkv_lo);
    cudaGetSymbolAddress((void**)&a_hi,   g_att_hi);
    cudaGetSymbolAddress((void**)&a_lo,   g_att_lo);

    cudaFuncSetAttribute(attn_mma,
                         cudaFuncAttributeMaxDynamicSharedMemorySize, ATTN_SMEM);
    cudaFuncSetAttribute((const void*)gemm_mma<false, true>,
                         cudaFuncAttributeMaxDynamicSharedMemorySize, GEMM_SMEM);
    cudaFuncSetAttribute((const void*)gemm_mma<true, false>,
                         cudaFuncAttributeMaxDynamicSharedMemorySize, GEMM_SMEM);

    // 0) fp16 splits: x -> hi/lo; weights -> single-rounded (hi only)
    {
        int n4 = ROWS * EMB / 4;
        split_f16<<<(n4 + 255) / 256, 256>>>((const float4*)x,
            (__half2*)x_hi, (__half2*)x_lo, n4);
        n4 = F3 * EMB / 4;
        split_f16<<<(n4 + 255) / 256, 256>>>((const float4*)w_qkv,
            (__half2*)wq_hi, nullptr, n4);
        n4 = EMB * EMB / 4;
        split_f16<<<(n4 + 255) / 256, 256>>>((const float4*)w_out,
            (__half2*)wo_hi, nullptr, n4);
    }

    // 1) QKV projection -> fp16 hi/lo qkv
    gemm_mma<false, true><<<dim3(F3 / 128, ROWS / 256), 256, GEMM_SMEM>>>(
        x_hi, x_lo, wq_hi, nullptr, nullptr, qkv_hi, qkv_lo, F3, EMB);

    // 2) Tensor-core causal flash attention -> att hi/lo
    attn_mma<<<dim3(SEQ / 128, NH, BS), 256, ATTN_SMEM>>>(qkv_hi, qkv_lo, a_hi, a_lo);

    // 3) Output projection + bias -> fp32 out
    gemm_mma<true, false><<<dim3(EMB / 128, ROWS / 256), 256, GEMM_SMEM>>>(
        a_hi, a_lo, wo_hi, b_out, out, nullptr, nullptr, EMB, EMB);
}

// round 9
// speedup vs baseline: 1.6175x; 1.1472x over previous
#include <cuda_runtime.h>
#include <cuda_fp16.h>
#include <cstdint>
#include <math.h>

// Problem constants (fixed shapes)
#define BS   2
#define SEQ  2048
#define EMB  1024
#define NH   16
#define HD   64
#define F3   3072   // 3*EMB
#define ROWS (BS * SEQ)   // 4096

// ---------------------------------------------------------------------------
// Scratch (device globals: allocation-free rule)
// ---------------------------------------------------------------------------
__device__ __half g_x_hi[ROWS * EMB];
__device__ __half g_x_lo[ROWS * EMB];
__device__ __half g_wqkv_hi[F3 * EMB];      // single-rounded weights (B operand)
__device__ __half g_wout_hi[EMB * EMB];
__device__ __half g_qkv_hi[ROWS * F3];
__device__ __half g_qkv_lo[ROWS * F3];      // lo meaningful for Q columns
__device__ __half g_att_hi[ROWS * EMB];

// ---------------------------------------------------------------------------
// helpers
// ---------------------------------------------------------------------------
__device__ __forceinline__ uint32_t smem_u32(const void* p) {
    uint32_t a;
    asm("{ .reg .u64 t; cvta.to.shared.u64 t, %1; cvt.u32.u64 %0, t; }" : "=r"(a) : "l"(p));
    return a;
}
__device__ __forceinline__ void ldsm_x4(uint32_t addr, uint32_t r[4]) {
    asm volatile("ldmatrix.sync.aligned.m8n8.x4.shared.b16 {%0,%1,%2,%3}, [%4];"
                 : "=r"(r[0]), "=r"(r[1]), "=r"(r[2]), "=r"(r[3]) : "r"(addr));
}
__device__ __forceinline__ void ldsm_x4_t(uint32_t addr, uint32_t r[4]) {
    asm volatile("ldmatrix.sync.aligned.m8n8.x4.trans.shared.b16 {%0,%1,%2,%3}, [%4];"
                 : "=r"(r[0]), "=r"(r[1]), "=r"(r[2]), "=r"(r[3]) : "r"(addr));
}
__device__ __forceinline__ void mma16816(float c[4], const uint32_t a[4],
                                         const uint32_t b0, const uint32_t b1) {
    asm volatile(
        "mma.sync.aligned.m16n8k16.row.col.f32.f16.f16.f32 "
        "{%0,%1,%2,%3}, {%4,%5,%6,%7}, {%8,%9}, {%0,%1,%2,%3};"
        : "+f"(c[0]), "+f"(c[1]), "+f"(c[2]), "+f"(c[3])
        : "r"(a[0]), "r"(a[1]), "r"(a[2]), "r"(a[3]), "r"(b0), "r"(b1));
}
__device__ __forceinline__ uint32_t pack_f16(float lo, float hi) {
    __half2 h = __floats2half2_rn(lo, hi);
    return *(uint32_t*)&h;
}
__device__ __forceinline__ float ex2(float x) {
    float r;
    asm("ex2.approx.ftz.f32 %0, %1;" : "=f"(r) : "f"(x));
    return r;
}
__device__ __forceinline__ void cp_async16(uint32_t dst, const void* src) {
    asm volatile("cp.async.cg.shared.global [%0], [%1], 16;" :: "r"(dst), "l"(src));
}
#define CP_COMMIT() asm volatile("cp.async.commit_group;" ::: "memory")
#define CP_WAIT1()  asm volatile("cp.async.wait_group 1;" ::: "memory")
#define CP_WAIT0()  asm volatile("cp.async.wait_group 0;" ::: "memory")

// ---------------------------------------------------------------------------
// fp16 hi/lo split (float4 vectorized). hi alone = single-rounded value.
// ---------------------------------------------------------------------------
__global__ void split_f16(const float4* __restrict__ in,
                          __half2* __restrict__ hi,
                          __half2* __restrict__ lo, int n4) {
    int i = blockIdx.x * blockDim.x + threadIdx.x;
    if (i >= n4) return;
    float4 v = in[i];
    __half h0 = __float2half_rn(v.x);
    __half h1 = __float2half_rn(v.y);
    __half h2 = __float2half_rn(v.z);
    __half h3 = __float2half_rn(v.w);
    hi[2 * i]     = __half2(h0, h1);
    hi[2 * i + 1] = __half2(h2, h3);
    if (lo) {
        __half l0 = __float2half_rn(v.x - __half2float(h0));
        __half l1 = __float2half_rn(v.y - __half2float(h1));
        __half l2 = __float2half_rn(v.z - __half2float(h2));
        __half l3 = __float2half_rn(v.w - __half2float(h3));
        lo[2 * i]     = __half2(l0, l1);
        lo[2 * i + 1] = __half2(l2, l3);
    }
}

// ---------------------------------------------------------------------------
// mma.sync fp16 GEMM, cp.async double-buffered.
// CTA tile 256x128, 8 warps, warp tile 64x64, BK=32.
// MODE 1: QKV — pass2 (Alo*B) only for Q column groups ((col/64)%3==0).
// MODE 2: single pass (Ahi*B only), Alo never loaded.
// ---------------------------------------------------------------------------
#define SA_STRIDE 40
#define ATILE_B (256 * SA_STRIDE * 2)           // 20480
#define BTILE_B (128 * SA_STRIDE * 2)           // 10240
#define STAGE_B (2 * ATILE_B + BTILE_B)         // 51200
#define GEMM_SMEM (2 * STAGE_B)                 // 102400

template <int MODE, bool HAS_BIAS, bool SPLIT_OUT>
__global__ __launch_bounds__(256, 1)
void gemm_mma(const __half* __restrict__ Ahi, const __half* __restrict__ Alo,
              const __half* __restrict__ B,
              const float* __restrict__ bias, float* __restrict__ C,
              __half* __restrict__ Chi, __half* __restrict__ Clo,
              int N, int K) {
    extern __shared__ char smem[];
    const uint32_t sb = smem_u32(smem);

    const int tid  = threadIdx.x;
    const int wid  = tid >> 5;
    const int lane = tid & 31;
    const int n0 = blockIdx.x * 128;
    const int m0 = blockIdx.y * 256;
    const int wm = (wid & 3) * 64;
    const int wn = (wid >> 2) * 64;

    // warp-uniform: does this warp run the Alo pass?
    const bool do2 = (MODE == 2) ? false
                   : (MODE == 1) ? ((((n0 + wn) >> 6) % 3) == 0)
                   : true;

    const int trow  = lane & 7;
    const int tquad = lane >> 3;
    const int a_row_off = (tquad & 1) * 8 + trow;
    const int a_col_off = (tquad >> 1) * 8;
    const int b_row_off = (tquad >> 1) * 8 + trow;
    const int b_col_off = (tquad & 1) * 8;

    float acc[4][8][4];
#pragma unroll
    for (int mt = 0; mt < 4; mt++)
#pragma unroll
        for (int nt = 0; nt < 8; nt++)
#pragma unroll
            for (int j = 0; j < 4; j++) acc[mt][nt][j] = 0.0f;

    auto load_stage = [&](int stage, int k0) {
        uint32_t s0 = sb + stage * STAGE_B;
#pragma unroll
        for (int i = 0; i < 4; i++) {
            int idx = tid + 256 * i;
            int row = idx >> 2, q = idx & 3;
            uint32_t soff = (uint32_t)(row * SA_STRIDE + q * 8) * 2;
            size_t ga = (size_t)(m0 + row) * K + k0 + q * 8;
            cp_async16(s0 + soff, Ahi + ga);
            if (MODE != 2) cp_async16(s0 + ATILE_B + soff, Alo + ga);
        }
#pragma unroll
        for (int i = 0; i < 2; i++) {
            int idx = tid + 256 * i;
            int row = idx >> 2, q = idx & 3;
            uint32_t soff = (uint32_t)(row * SA_STRIDE + q * 8) * 2;
            size_t gb = (size_t)(n0 + row) * K + k0 + q * 8;
            cp_async16(s0 + 2 * ATILE_B + soff, B + gb);
        }
        CP_COMMIT();
    };

    const int NC = K >> 5;
    load_stage(0, 0);

    for (int c = 0; c < NC; c++) {
        const bool pref = (c + 1 < NC);
        if (pref) load_stage((c + 1) & 1, (c + 1) * 32);
        if (pref) CP_WAIT1(); else CP_WAIT0();
        __syncthreads();

        const uint32_t AH = sb + (c & 1) * STAGE_B;
        const uint32_t AL = AH + ATILE_B;
        const uint32_t BB = AH + 2 * ATILE_B;

#pragma unroll
        for (int ks = 0; ks < 2; ks++) {
            const int kk = ks * 16;
            uint32_t ah[4][4], bf[4][4];

#pragma unroll
            for (int mt = 0; mt < 4; mt++)
                ldsm_x4(AH + (uint32_t)((wm + mt * 16 + a_row_off) * SA_STRIDE +
                                        kk + a_col_off) * 2, ah[mt]);
#pragma unroll
            for (int np = 0; np < 4; np++)
                ldsm_x4(BB + (uint32_t)((wn + np * 16 + b_row_off) * SA_STRIDE +
                                        kk + b_col_off) * 2, bf[np]);
            // pass 1: Ahi * B
#pragma unroll
            for (int mt = 0; mt < 4; mt++)
#pragma unroll
                for (int np = 0; np < 4; np++) {
                    mma16816(acc[mt][2 * np],     ah[mt], bf[np][0], bf[np][1]);
                    mma16816(acc[mt][2 * np + 1], ah[mt], bf[np][2], bf[np][3]);
                }
            // pass 2: Alo * B (warp-uniform predicate)
            if (do2) {
                uint32_t al[4][4];
#pragma unroll
                for (int mt = 0; mt < 4; mt++)
                    ldsm_x4(AL + (uint32_t)((wm + mt * 16 + a_row_off) * SA_STRIDE +
                                            kk + a_col_off) * 2, al[mt]);
#pragma unroll
                for (int mt = 0; mt < 4; mt++)
#pragma unroll
                    for (int np = 0; np < 4; np++) {
                        mma16816(acc[mt][2 * np],     al[mt], bf[np][0], bf[np][1]);
                        mma16816(acc[mt][2 * np + 1], al[mt], bf[np][2], bf[np][3]);
                    }
            }
        }
        __syncthreads();
    }

    const int g  = lane >> 2;
    const int t2 = (lane & 3) * 2;
#pragma unroll
    for (int mt = 0; mt < 4; mt++) {
        int mrow0 = m0 + wm + mt * 16 + g;
#pragma unroll
        for (int nt = 0; nt < 8; nt++) {
            int n = n0 + wn + nt * 8 + t2;
            float b0 = 0.f, b1 = 0.f;
            if (HAS_BIAS) { b0 = bias[n]; b1 = bias[n + 1]; }
            float v00 = acc[mt][nt][0] + b0, v01 = acc[mt][nt][1] + b1;
            float v10 = acc[mt][nt][2] + b0, v11 = acc[mt][nt][3] + b1;
            if (SPLIT_OUT) {
                size_t i0 = (size_t)mrow0 * N + n;
                size_t i1 = (size_t)(mrow0 + 8) * N + n;
                float h00 = __half2float(__float2half_rn(v00));
                float h01 = __half2float(__float2half_rn(v01));
                float h10 = __half2float(__float2half_rn(v10));
                float h11 = __half2float(__float2half_rn(v11));
                *(uint32_t*)(Chi + i0) = pack_f16(h00, h01);
                *(uint32_t*)(Clo + i0) = pack_f16(v00 - h00, v01 - h01);
                *(uint32_t*)(Chi + i1) = pack_f16(h10, h11);
                *(uint32_t*)(Clo + i1) = pack_f16(v10 - h10, v11 - h11);
            } else {
                *(float2*)(C + (size_t)mrow0 * N + n)       = make_float2(v00, v01);
                *(float2*)(C + (size_t)(mrow0 + 8) * N + n) = make_float2(v10, v11);
            }
        }
    }
}

// ---------------------------------------------------------------------------
// Tensor-core causal flash attention (fp16x2): Q split hi/lo (exact), K and V
// single fp16, P split hi/lo in registers. BM=128, BN=64, HD=64, 8 warps.
// Output: att_hi only (single fp16; consumer GEMM2 is single-pass).
// ---------------------------------------------------------------------------
#define AT_STRIDE 72
#define AT_TILE (64 * AT_STRIDE * 2)       // 9216 bytes
#define AT_STAGE (2 * AT_TILE)             // 18432: K, V
#define ATTN_SMEM (2 * AT_STAGE)           // 36864

#define SCALE2 0.1803368801111244f         // 0.125 * log2(e)

__global__ __launch_bounds__(256)
void attn_mma(const __half* __restrict__ qkv_hi,
              const __half* __restrict__ qkv_lo,
              __half* __restrict__ att_hi) {
    extern __shared__ char smem[];
    const uint32_t sb = smem_u32(smem);

    const int tid  = threadIdx.x;
    const int wid  = tid >> 5;
    const int lane = tid & 31;
    const int it = gridDim.x - 1 - blockIdx.x;   // big tiles first
    const int h  = blockIdx.y;
    const int b  = blockIdx.z;
    const size_t hbase = (size_t)b * SEQ * F3 + (size_t)h * 192;

    // ---- Stage Q: hi rows0-63 -> s0t0, hi rows64-127 -> s0t1,
    //               lo rows0-63 -> s1t0, lo rows64-127 -> s1t1 ----
#pragma unroll
    for (int i = 0; i < 4; i++) {
        int idx = tid + 256 * i;      // 0..1023
        int row = idx >> 3, q = idx & 7;
        int tsel = row >> 6, drow = row & 63;
        uint32_t soff = (uint32_t)(tsel * AT_TILE + (drow * AT_STRIDE + q * 8) * 2);
        size_t gq = hbase + (size_t)(it * 128 + row) * F3 + q * 8;
        *(uint4*)(smem + soff)            = *(const uint4*)(qkv_hi + gq);
        *(uint4*)(smem + AT_STAGE + soff) = *(const uint4*)(qkv_lo + gq);
    }
    __syncthreads();

    // Q fragments: warp w owns rows 16*(w&3) + 64*(w>>2)
    uint32_t qh[4][4], ql[4][4];
    {
        uint32_t hb = sb + (wid >> 2) * AT_TILE;
        uint32_t lb = hb + AT_STAGE;
        uint32_t qoff = (uint32_t)((16 * (wid & 3) + (lane & 15)) * AT_STRIDE +
                                   (lane >> 4) * 8) * 2;
#pragma unroll
        for (int ks = 0; ks < 4; ks++) {
            ldsm_x4(hb + qoff + ks * 32, qh[ks]);
            ldsm_x4(lb + qoff + ks * 32, ql[ks]);
        }
    }
    __syncthreads();   // everyone done reading Q before overwrite

    auto load_kv = [&](int stage, int jt) {
        uint32_t sbase = sb + stage * AT_STAGE;
#pragma unroll
        for (int i = 0; i < 2; i++) {
            int idx = tid * 2 + i;
            int row = idx >> 3, q = idx & 7;
            uint32_t soff = (uint32_t)(row * AT_STRIDE + q * 8) * 2;
            size_t gr = hbase + (size_t)(jt * 64 + row) * F3 + q * 8;
            cp_async16(sbase + soff,           qkv_hi + gr + 64);    // K
            cp_async16(sbase + AT_TILE + soff, qkv_hi + gr + 128);   // V
        }
        CP_COMMIT();
    };

    float m2[2] = {-1e30f, -1e30f}, l[2] = {0.f, 0.f};
    float o[8][4];
#pragma unroll
    for (int dt = 0; dt < 8; dt++)
#pragma unroll
        for (int j = 0; j < 4; j++) o[dt][j] = 0.0f;

    const int rbase = 128 * it + 16 * (wid & 3) + 64 * (wid >> 2);
    const int g  = lane >> 2;
    const int t2 = (lane & 3) * 2;
    const uint32_t koff = (uint32_t)(((lane >> 4) * 8 + (lane & 7)) * AT_STRIDE +
                                     ((lane >> 3) & 1) * 8) * 2;
    const uint32_t voff = (uint32_t)((lane & 15) * AT_STRIDE + (lane >> 4) * 8) * 2;

    const int jt_max = 2 * it + 2;
    load_kv(0, 0);

    for (int jt = 0; jt < jt_max; jt++) {
        const bool pref = (jt + 1 < jt_max);
        if (pref) load_kv((jt + 1) & 1, jt + 1);
        if (pref) CP_WAIT1(); else CP_WAIT0();
        __syncthreads();

        const uint32_t KB = sb + (jt & 1) * AT_STAGE;
        const uint32_t VB = KB + AT_TILE;

        // ---- S = (Qhi + Qlo) K^T : 2 passes ----
        float s[8][4];
#pragma unroll
        for (int nt = 0; nt < 8; nt++)
#pragma unroll
            for (int j = 0; j < 4; j++) s[nt][j] = 0.0f;

#pragma unroll
        for (int ks = 0; ks < 4; ks++) {
            uint32_t kf[4][4];
#pragma unroll
            for (int np = 0; np < 4; np++)
                ldsm_x4(KB + koff + (uint32_t)(np * 16 * AT_STRIDE + ks * 16) * 2, kf[np]);
#pragma unroll
            for (int np = 0; np < 4; np++) {
                mma16816(s[2 * np],     qh[ks], kf[np][0], kf[np][1]);
                mma16816(s[2 * np + 1], qh[ks], kf[np][2], kf[np][3]);
            }
#pragma unroll
            for (int np = 0; np < 4; np++) {
                mma16816(s[2 * np],     ql[ks], kf[np][0], kf[np][1]);
                mma16816(s[2 * np + 1], ql[ks], kf[np][2], kf[np][3]);
            }
        }

        // ---- scale (+ causal mask on diagonal tiles) ----
        const bool diag = (jt >= 2 * it);
#pragma unroll
        for (int nt = 0; nt < 8; nt++)
#pragma unroll
            for (int j = 0; j < 4; j++) {
                float t = s[nt][j] * SCALE2;
                if (diag) {
                    int col = jt * 64 + nt * 8 + t2 + (j & 1);
                    int row = rbase + g + 8 * (j >> 1);
                    if (col > row) t = -1e30f;
                }
                s[nt][j] = t;
            }

        // ---- online softmax ----
        float rmax[2] = {-1e30f, -1e30f};
#pragma unroll
        for (int nt = 0; nt < 8; nt++) {
            rmax[0] = fmaxf(rmax[0], fmaxf(s[nt][0], s[nt][1]));
            rmax[1] = fmaxf(rmax[1], fmaxf(s[nt][2], s[nt][3]));
        }
#pragma unroll
        for (int off = 1; off <= 2; off <<= 1) {
            rmax[0] = fmaxf(rmax[0], __shfl_xor_sync(0xffffffffu, rmax[0], off));
            rmax[1] = fmaxf(rmax[1], __shfl_xor_sync(0xffffffffu, rmax[1], off));
        }
        float alpha[2], rsum[2];
#pragma unroll
        for (int r = 0; r < 2; r++) {
            float mnew = fmaxf(m2[r], rmax[r]);
            alpha[r] = ex2(m2[r] - mnew);
            m2[r] = mnew;
            rsum[r] = 0.f;
        }
#pragma unroll
        for (int nt = 0; nt < 8; nt++) {
            s[nt][0] = ex2(s[nt][0] - m2[0]);
            s[nt][1] = ex2(s[nt][1] - m2[0]);
            s[nt][2] = ex2(s[nt][2] - m2[1]);
            s[nt][3] = ex2(s[nt][3] - m2[1]);
            rsum[0] += s[nt][0] + s[nt][1];
            rsum[1] += s[nt][2] + s[nt][3];
        }
#pragma unroll
        for (int off = 1; off <= 2; off <<= 1) {
            rsum[0] += __shfl_xor_sync(0xffffffffu, rsum[0], off);
            rsum[1] += __shfl_xor_sync(0xffffffffu, rsum[1], off);
        }
#pragma unroll
        for (int r = 0; r < 2; r++) l[r] = l[r] * alpha[r] + rsum[r];
#pragma unroll
        for (int dt = 0; dt < 8; dt++) {
            o[dt][0] *= alpha[0];
            o[dt][1] *= alpha[0];
            o[dt][2] *= alpha[1];
            o[dt][3] *= alpha[1];
        }

        // ---- pack P into hi/lo A-fragments ----
        uint32_t ph[4][4], pl[4][4];
#pragma unroll
        for (int ks = 0; ks < 4; ks++) {
#pragma unroll
            for (int half = 0; half < 2; half++) {
                int nt = 2 * ks + half;
                float p0 = s[nt][0], p1 = s[nt][1], p2 = s[nt][2], p3 = s[nt][3];
                float h0 = __half2float(__float2half_rn(p0));
                float h1 = __half2float(__float2half_rn(p1));
                float h2 = __half2float(__float2half_rn(p2));
                float h3 = __half2float(__float2half_rn(p3));
                ph[ks][2 * half]     = pack_f16(h0, h1);
                ph[ks][2 * half + 1] = pack_f16(h2, h3);
                pl[ks][2 * half]     = pack_f16(p0 - h0, p1 - h1);
                pl[ks][2 * half + 1] = pack_f16(p2 - h2, p3 - h3);
            }
        }

        // ---- O += (Phi + Plo) V : 2 passes ----
#pragma unroll
        for (int ks = 0; ks < 4; ks++) {
            uint32_t vf[4][4];
#pragma unroll
            for (int np = 0; np < 4; np++)
                ldsm_x4_t(VB + voff + (uint32_t)(ks * 16 * AT_STRIDE + np * 16) * 2, vf[np]);
#pragma unroll
            for (int np = 0; np < 4; np++) {
                mma16816(o[2 * np],     ph[ks], vf[np][0], vf[np][1]);
                mma16816(o[2 * np + 1], ph[ks], vf[np][2], vf[np][3]);
            }
#pragma unroll
            for (int np = 0; np < 4; np++) {
                mma16816(o[2 * np],     pl[ks], vf[np][0], vf[np][1]);
                mma16816(o[2 * np + 1], pl[ks], vf[np][2], vf[np][3]);
            }
        }
        __syncthreads();
    }

    // ---- epilogue: O/l -> att hi (single fp16) ----
    float inv0 = 1.0f / l[0], inv1 = 1.0f / l[1];
#pragma unroll
    for (int dt = 0; dt < 8; dt++) {
        int col = h * 64 + dt * 8 + t2;
        size_t i0 = ((size_t)b * SEQ + rbase + g) * EMB + col;
        size_t i1 = ((size_t)b * SEQ + rbase + g + 8) * EMB + col;
        *(uint32_t*)(att_hi + i0) = pack_f16(o[dt][0] * inv0, o[dt][1] * inv0);
        *(uint32_t*)(att_hi + i1) = pack_f16(o[dt][2] * inv1, o[dt][3] * inv1);
    }
}

// ---------------------------------------------------------------------------
// Launch
// ---------------------------------------------------------------------------
extern "C" void kernel_launch(void* const* d_in, const int* in_sizes, int n_in,
                              void* d_out, int out_size) {
    const float* x      = (const float*)d_in[0];
    const float* w_qkv  = (const float*)d_in[1];
    const float* w_out  = (const float*)d_in[2];
    const float* b_out  = (const float*)d_in[3];
    float* out = (float*)d_out;

    __half *x_hi, *x_lo, *wq_hi, *wo_hi, *qkv_hi, *qkv_lo, *a_hi;
    cudaGetSymbolAddress((void**)&x_hi,   g_x_hi);
    cudaGetSymbolAddress((void**)&x_lo,   g_x_lo);
    cudaGetSymbolAddress((void**)&wq_hi,  g_wqkv_hi);
    cudaGetSymbolAddress((void**)&wo_hi,  g_wout_hi);
    cudaGetSymbolAddress((void**)&qkv_hi, g_qkv_hi);
    cudaGetSymbolAddress((void**)&qkv_lo, g_qkv_lo);
    cudaGetSymbolAddress((void**)&a_hi,   g_att_hi);

    cudaFuncSetAttribute(attn_mma,
                         cudaFuncAttributeMaxDynamicSharedMemorySize, ATTN_SMEM);
    cudaFuncSetAttribute((const void*)gemm_mma<1, false, true>,
                         cudaFuncAttributeMaxDynamicSharedMemorySize, GEMM_SMEM);
    cudaFuncSetAttribute((const void*)gemm_mma<2, true, false>,
                         cudaFuncAttributeMaxDynamicSharedMemorySize, GEMM_SMEM);

    // 0) fp16 splits: x -> hi/lo; weights -> single-rounded (hi only)
    {
        int n4 = ROWS * EMB / 4;
        split_f16<<<(n4 + 255) / 256, 256>>>((const float4*)x,
            (__half2*)x_hi, (__half2*)x_lo, n4);
        n4 = F3 * EMB / 4;
        split_f16<<<(n4 + 255) / 256, 256>>>((const float4*)w_qkv,
            (__half2*)wq_hi, nullptr, n4);
        n4 = EMB * EMB / 4;
        split_f16<<<(n4 + 255) / 256, 256>>>((const float4*)w_out,
            (__half2*)wo_hi, nullptr, n4);
    }

    // 1) QKV projection -> fp16 hi/lo qkv (pass2 only for Q columns)
    gemm_mma<1, false, true><<<dim3(F3 / 128, ROWS / 256), 256, GEMM_SMEM>>>(
        x_hi, x_lo, wq_hi, nullptr, nullptr, qkv_hi, qkv_lo, F3, EMB);

    // 2) Tensor-core causal flash attention -> att hi (single fp16)
    attn_mma<<<dim3(SEQ / 128, NH, BS), 256, ATTN_SMEM>>>(qkv_hi, qkv_lo, a_hi);

    // 3) Output projection + bias (single pass) -> fp32 out
    gemm_mma<2, true, false><<<dim3(EMB / 128, ROWS / 256), 256, GEMM_SMEM>>>(
        a_hi, nullptr, wo_hi, b_out, out, nullptr, nullptr, EMB, EMB);
}

// round 10
// speedup vs baseline: 1.9151x; 1.1840x over previous
#include <cuda_runtime.h>
#include <cuda_fp16.h>
#include <cstdint>
#include <math.h>

// Problem constants (fixed shapes)
#define BS   2
#define SEQ  2048
#define EMB  1024
#define NH   16
#define HD   64
#define F3   3072   // 3*EMB
#define ROWS (BS * SEQ)   // 4096

// ---------------------------------------------------------------------------
// Scratch (device globals: allocation-free rule)
// qkv layout is PERMUTED: columns [0,1024) = Q (h*64+d), [1024,2048) = K,
// [2048,3072) = V. Q additionally has an fp16 lo-correction buffer.
// ---------------------------------------------------------------------------
__device__ __half g_x_hi[ROWS * EMB];
__device__ __half g_x_lo[ROWS * EMB];
__device__ __half g_wqkv_hi[F3 * EMB];      // permuted rows: [Q|K|V]
__device__ __half g_wout_hi[EMB * EMB];
__device__ __half g_qkv_hi[ROWS * F3];      // [Q|K|V] per row
__device__ __half g_q_lo[ROWS * EMB];       // lo for Q only
__device__ __half g_att_hi[ROWS * EMB];

// ---------------------------------------------------------------------------
// helpers
// ---------------------------------------------------------------------------
__device__ __forceinline__ uint32_t smem_u32(const void* p) {
    uint32_t a;
    asm("{ .reg .u64 t; cvta.to.shared.u64 t, %1; cvt.u32.u64 %0, t; }" : "=r"(a) : "l"(p));
    return a;
}
__device__ __forceinline__ void ldsm_x4(uint32_t addr, uint32_t r[4]) {
    asm volatile("ldmatrix.sync.aligned.m8n8.x4.shared.b16 {%0,%1,%2,%3}, [%4];"
                 : "=r"(r[0]), "=r"(r[1]), "=r"(r[2]), "=r"(r[3]) : "r"(addr));
}
__device__ __forceinline__ void ldsm_x4_t(uint32_t addr, uint32_t r[4]) {
    asm volatile("ldmatrix.sync.aligned.m8n8.x4.trans.shared.b16 {%0,%1,%2,%3}, [%4];"
                 : "=r"(r[0]), "=r"(r[1]), "=r"(r[2]), "=r"(r[3]) : "r"(addr));
}
__device__ __forceinline__ void mma16816(float c[4], const uint32_t a[4],
                                         const uint32_t b0, const uint32_t b1) {
    asm volatile(
        "mma.sync.aligned.m16n8k16.row.col.f32.f16.f16.f32 "
        "{%0,%1,%2,%3}, {%4,%5,%6,%7}, {%8,%9}, {%0,%1,%2,%3};"
        : "+f"(c[0]), "+f"(c[1]), "+f"(c[2]), "+f"(c[3])
        : "r"(a[0]), "r"(a[1]), "r"(a[2]), "r"(a[3]), "r"(b0), "r"(b1));
}
__device__ __forceinline__ uint32_t pack_f16(float lo, float hi) {
    __half2 h = __floats2half2_rn(lo, hi);
    return *(uint32_t*)&h;
}
__device__ __forceinline__ float ex2(float x) {
    float r;
    asm("ex2.approx.ftz.f32 %0, %1;" : "=f"(r) : "f"(x));
    return r;
}
__device__ __forceinline__ void cp_async16(uint32_t dst, const void* src) {
    asm volatile("cp.async.cg.shared.global [%0], [%1], 16;" :: "r"(dst), "l"(src));
}
#define CP_COMMIT() asm volatile("cp.async.commit_group;" ::: "memory")
#define CP_WAIT1()  asm volatile("cp.async.wait_group 1;" ::: "memory")
#define CP_WAIT0()  asm volatile("cp.async.wait_group 0;" ::: "memory")

// ---------------------------------------------------------------------------
// fp16 hi/lo split (float4 vectorized). hi alone = single-rounded value.
// ---------------------------------------------------------------------------
__global__ void split_f16(const float4* __restrict__ in,
                          __half2* __restrict__ hi,
                          __half2* __restrict__ lo, int n4) {
    int i = blockIdx.x * blockDim.x + threadIdx.x;
    if (i >= n4) return;
    float4 v = in[i];
    __half h0 = __float2half_rn(v.x);
    __half h1 = __float2half_rn(v.y);
    __half h2 = __float2half_rn(v.z);
    __half h3 = __float2half_rn(v.w);
    hi[2 * i]     = __half2(h0, h1);
    hi[2 * i + 1] = __half2(h2, h3);
    if (lo) {
        __half l0 = __float2half_rn(v.x - __half2float(h0));
        __half l1 = __float2half_rn(v.y - __half2float(h1));
        __half l2 = __float2half_rn(v.z - __half2float(h2));
        __half l3 = __float2half_rn(v.w - __half2float(h3));
        lo[2 * i]     = __half2(l0, l1);
        lo[2 * i + 1] = __half2(l2, l3);
    }
}

// Permuting split for w_qkv: dst row r (r<1024: Q col r; r<2048: K; else V)
// maps to src row h*192 + m*64 + d where m=r/1024, h=(r%1024)/64, d=r%64.
__global__ void split_f16_perm(const float4* __restrict__ in,
                               __half2* __restrict__ hi) {
    int idx = blockIdx.x * blockDim.x + threadIdx.x;   // over F3 * (EMB/4)
    if (idx >= F3 * (EMB / 4)) return;
    int r = idx >> 8;            // EMB/4 = 256 float4 per row
    int q = idx & 255;
    int m = r >> 10;
    int within = r & 1023;
    int hsrc = (within >> 6) * 192 + m * 64 + (within & 63);
    float4 v = in[(size_t)hsrc * 256 + q];
    hi[2 * idx]     = __half2(__float2half_rn(v.x), __float2half_rn(v.y));
    hi[2 * idx + 1] = __half2(__float2half_rn(v.z), __float2half_rn(v.w));
}

// ---------------------------------------------------------------------------
// mma.sync fp16 GEMM, cp.async double-buffered.
// CTA tile 256x128, 8 warps, warp tile 64x64, BK=32.
// MODE 1: QKV (permuted cols) — pass2 + lo-output only for n0 < EMB (CTA-uniform).
// MODE 2: single pass (Ahi*B only).
// ---------------------------------------------------------------------------
#define SA_STRIDE 40
#define ATILE_B (256 * SA_STRIDE * 2)           // 20480
#define BTILE_B (128 * SA_STRIDE * 2)           // 10240
#define STAGE_B (2 * ATILE_B + BTILE_B)         // 51200
#define GEMM_SMEM (2 * STAGE_B)                 // 102400

template <int MODE, bool HAS_BIAS, bool SPLIT_OUT>
__global__ __launch_bounds__(256, 1)
void gemm_mma(const __half* __restrict__ Ahi, const __half* __restrict__ Alo,
              const __half* __restrict__ B,
              const float* __restrict__ bias, float* __restrict__ C,
              __half* __restrict__ Chi, __half* __restrict__ Clo,
              int N, int K) {
    extern __shared__ char smem[];
    const uint32_t sb = smem_u32(smem);

    const int tid  = threadIdx.x;
    const int wid  = tid >> 5;
    const int lane = tid & 31;
    const int n0 = blockIdx.x * 128;
    const int m0 = blockIdx.y * 256;
    const int wm = (wid & 3) * 64;
    const int wn = (wid >> 2) * 64;

    // CTA-uniform: run the Alo pass? (MODE 1: only Q column block)
    const bool do2 = (MODE == 1) ? (n0 < EMB) : false;

    const int trow  = lane & 7;
    const int tquad = lane >> 3;
    const int a_row_off = (tquad & 1) * 8 + trow;
    const int a_col_off = (tquad >> 1) * 8;
    const int b_row_off = (tquad >> 1) * 8 + trow;
    const int b_col_off = (tquad & 1) * 8;

    float acc[4][8][4];
#pragma unroll
    for (int mt = 0; mt < 4; mt++)
#pragma unroll
        for (int nt = 0; nt < 8; nt++)
#pragma unroll
            for (int j = 0; j < 4; j++) acc[mt][nt][j] = 0.0f;

    auto load_stage = [&](int stage, int k0) {
        uint32_t s0 = sb + stage * STAGE_B;
#pragma unroll
        for (int i = 0; i < 4; i++) {
            int idx = tid + 256 * i;
            int row = idx >> 2, q = idx & 3;
            uint32_t soff = (uint32_t)(row * SA_STRIDE + q * 8) * 2;
            size_t ga = (size_t)(m0 + row) * K + k0 + q * 8;
            cp_async16(s0 + soff, Ahi + ga);
            if (do2) cp_async16(s0 + ATILE_B + soff, Alo + ga);
        }
#pragma unroll
        for (int i = 0; i < 2; i++) {
            int idx = tid + 256 * i;
            int row = idx >> 2, q = idx & 3;
            uint32_t soff = (uint32_t)(row * SA_STRIDE + q * 8) * 2;
            size_t gb = (size_t)(n0 + row) * K + k0 + q * 8;
            cp_async16(s0 + 2 * ATILE_B + soff, B + gb);
        }
        CP_COMMIT();
    };

    const int NC = K >> 5;
    load_stage(0, 0);

    for (int c = 0; c < NC; c++) {
        const bool pref = (c + 1 < NC);
        if (pref) load_stage((c + 1) & 1, (c + 1) * 32);
        if (pref) CP_WAIT1(); else CP_WAIT0();
        __syncthreads();

        const uint32_t AH = sb + (c & 1) * STAGE_B;
        const uint32_t AL = AH + ATILE_B;
        const uint32_t BB = AH + 2 * ATILE_B;

#pragma unroll
        for (int ks = 0; ks < 2; ks++) {
            const int kk = ks * 16;
            uint32_t ah[4][4], bf[4][4];

#pragma unroll
            for (int mt = 0; mt < 4; mt++)
                ldsm_x4(AH + (uint32_t)((wm + mt * 16 + a_row_off) * SA_STRIDE +
                                        kk + a_col_off) * 2, ah[mt]);
#pragma unroll
            for (int np = 0; np < 4; np++)
                ldsm_x4(BB + (uint32_t)((wn + np * 16 + b_row_off) * SA_STRIDE +
                                        kk + b_col_off) * 2, bf[np]);
            // pass 1: Ahi * B
#pragma unroll
            for (int mt = 0; mt < 4; mt++)
#pragma unroll
                for (int np = 0; np < 4; np++) {
                    mma16816(acc[mt][2 * np],     ah[mt], bf[np][0], bf[np][1]);
                    mma16816(acc[mt][2 * np + 1], ah[mt], bf[np][2], bf[np][3]);
                }
            // pass 2: Alo * B (CTA-uniform)
            if (do2) {
                uint32_t al[4][4];
#pragma unroll
                for (int mt = 0; mt < 4; mt++)
                    ldsm_x4(AL + (uint32_t)((wm + mt * 16 + a_row_off) * SA_STRIDE +
                                            kk + a_col_off) * 2, al[mt]);
#pragma unroll
                for (int mt = 0; mt < 4; mt++)
#pragma unroll
                    for (int np = 0; np < 4; np++) {
                        mma16816(acc[mt][2 * np],     al[mt], bf[np][0], bf[np][1]);
                        mma16816(acc[mt][2 * np + 1], al[mt], bf[np][2], bf[np][3]);
                    }
            }
        }
        __syncthreads();
    }

    const int g  = lane >> 2;
    const int t2 = (lane & 3) * 2;
#pragma unroll
    for (int mt = 0; mt < 4; mt++) {
        int mrow0 = m0 + wm + mt * 16 + g;
#pragma unroll
        for (int nt = 0; nt < 8; nt++) {
            int n = n0 + wn + nt * 8 + t2;
            float b0 = 0.f, b1 = 0.f;
            if (HAS_BIAS) { b0 = bias[n]; b1 = bias[n + 1]; }
            float v00 = acc[mt][nt][0] + b0, v01 = acc[mt][nt][1] + b1;
            float v10 = acc[mt][nt][2] + b0, v11 = acc[mt][nt][3] + b1;
            if (SPLIT_OUT) {
                size_t i0 = (size_t)mrow0 * N + n;
                size_t i1 = (size_t)(mrow0 + 8) * N + n;
                float h00 = __half2float(__float2half_rn(v00));
                float h01 = __half2float(__float2half_rn(v01));
                float h10 = __half2float(__float2half_rn(v10));
                float h11 = __half2float(__float2half_rn(v11));
                *(uint32_t*)(Chi + i0) = pack_f16(h00, h01);
                *(uint32_t*)(Chi + i1) = pack_f16(h10, h11);
                if (do2) {   // Q columns: store lo correction at EMB stride
                    size_t j0 = (size_t)mrow0 * EMB + n;
                    size_t j1 = (size_t)(mrow0 + 8) * EMB + n;
                    *(uint32_t*)(Clo + j0) = pack_f16(v00 - h00, v01 - h01);
                    *(uint32_t*)(Clo + j1) = pack_f16(v10 - h10, v11 - h11);
                }
            } else {
                *(float2*)(C + (size_t)mrow0 * N + n)       = make_float2(v00, v01);
                *(float2*)(C + (size_t)(mrow0 + 8) * N + n) = make_float2(v10, v11);
            }
        }
    }
}

// ---------------------------------------------------------------------------
// Tensor-core causal flash attention: Q split hi/lo (2-pass S), K, V, P single
// fp16 (1-pass PV). BM=128, BN=64, HD=64, 8 warps, cp.async double-buffered.
// qkv_hi layout: [row][ Q(0..1023) | K(1024..2047) | V(2048..3071) ], col h*64+d.
// ---------------------------------------------------------------------------
#define AT_STRIDE 72
#define AT_TILE (64 * AT_STRIDE * 2)       // 9216 bytes
#define AT_STAGE (2 * AT_TILE)             // 18432: K, V
#define ATTN_SMEM (2 * AT_STAGE)           // 36864

#define SCALE2 0.1803368801111244f         // 0.125 * log2(e)

__global__ __launch_bounds__(256)
void attn_mma(const __half* __restrict__ qkv_hi,
              const __half* __restrict__ q_lo,
              __half* __restrict__ att_hi) {
    extern __shared__ char smem[];
    const uint32_t sb = smem_u32(smem);

    const int tid  = threadIdx.x;
    const int wid  = tid >> 5;
    const int lane = tid & 31;
    const int it = gridDim.x - 1 - blockIdx.x;   // big tiles first
    const int h  = blockIdx.y;
    const int b  = blockIdx.z;
    const int hc = h * 64;
    const size_t rowbase = (size_t)b * SEQ;

    // ---- Stage Q: hi rows0-63 -> s0t0, hi rows64-127 -> s0t1,
    //               lo rows0-63 -> s1t0, lo rows64-127 -> s1t1 ----
#pragma unroll
    for (int i = 0; i < 4; i++) {
        int idx = tid + 256 * i;      // 0..1023
        int row = idx >> 3, q = idx & 7;
        int tsel = row >> 6, drow = row & 63;
        uint32_t soff = (uint32_t)(tsel * AT_TILE + (drow * AT_STRIDE + q * 8) * 2);
        size_t grow = rowbase + it * 128 + row;
        *(uint4*)(smem + soff)            = *(const uint4*)(qkv_hi + grow * F3 + hc + q * 8);
        *(uint4*)(smem + AT_STAGE + soff) = *(const uint4*)(q_lo + grow * EMB + hc + q * 8);
    }
    __syncthreads();

    // Q fragments: warp w owns rows 16*(w&3) + 64*(w>>2)
    uint32_t qh[4][4], ql[4][4];
    {
        uint32_t hb = sb + (wid >> 2) * AT_TILE;
        uint32_t lb = hb + AT_STAGE;
        uint32_t qoff = (uint32_t)((16 * (wid & 3) + (lane & 15)) * AT_STRIDE +
                                   (lane >> 4) * 8) * 2;
#pragma unroll
        for (int ks = 0; ks < 4; ks++) {
            ldsm_x4(hb + qoff + ks * 32, qh[ks]);
            ldsm_x4(lb + qoff + ks * 32, ql[ks]);
        }
    }
    __syncthreads();   // everyone done reading Q before overwrite

    auto load_kv = [&](int stage, int jt) {
        uint32_t sbase = sb + stage * AT_STAGE;
#pragma unroll
        for (int i = 0; i < 2; i++) {
            int idx = tid * 2 + i;
            int row = idx >> 3, q = idx & 7;
            uint32_t soff = (uint32_t)(row * AT_STRIDE + q * 8) * 2;
            size_t grow = rowbase + jt * 64 + row;
            cp_async16(sbase + soff,           qkv_hi + grow * F3 + EMB + hc + q * 8);     // K
            cp_async16(sbase + AT_TILE + soff, qkv_hi + grow * F3 + 2 * EMB + hc + q * 8); // V
        }
        CP_COMMIT();
    };

    float m2[2] = {-1e30f, -1e30f}, l[2] = {0.f, 0.f};
    float o[8][4];
#pragma unroll
    for (int dt = 0; dt < 8; dt++)
#pragma unroll
        for (int j = 0; j < 4; j++) o[dt][j] = 0.0f;

    const int rbase = 128 * it + 16 * (wid & 3) + 64 * (wid >> 2);
    const int g  = lane >> 2;
    const int t2 = (lane & 3) * 2;
    const uint32_t koff = (uint32_t)(((lane >> 4) * 8 + (lane & 7)) * AT_STRIDE +
                                     ((lane >> 3) & 1) * 8) * 2;
    const uint32_t voff = (uint32_t)((lane & 15) * AT_STRIDE + (lane >> 4) * 8) * 2;

    const int jt_max = 2 * it + 2;
    load_kv(0, 0);

    for (int jt = 0; jt < jt_max; jt++) {
        const bool pref = (jt + 1 < jt_max);
        if (pref) load_kv((jt + 1) & 1, jt + 1);
        if (pref) CP_WAIT1(); else CP_WAIT0();
        __syncthreads();

        const uint32_t KB = sb + (jt & 1) * AT_STAGE;
        const uint32_t VB = KB + AT_TILE;

        // ---- S = (Qhi + Qlo) K^T : 2 passes ----
        float s[8][4];
#pragma unroll
        for (int nt = 0; nt < 8; nt++)
#pragma unroll
            for (int j = 0; j < 4; j++) s[nt][j] = 0.0f;

#pragma unroll
        for (int ks = 0; ks < 4; ks++) {
            uint32_t kf[4][4];
#pragma unroll
            for (int np = 0; np < 4; np++)
                ldsm_x4(KB + koff + (uint32_t)(np * 16 * AT_STRIDE + ks * 16) * 2, kf[np]);
#pragma unroll
            for (int np = 0; np < 4; np++) {
                mma16816(s[2 * np],     qh[ks], kf[np][0], kf[np][1]);
                mma16816(s[2 * np + 1], qh[ks], kf[np][2], kf[np][3]);
            }
#pragma unroll
            for (int np = 0; np < 4; np++) {
                mma16816(s[2 * np],     ql[ks], kf[np][0], kf[np][1]);
                mma16816(s[2 * np + 1], ql[ks], kf[np][2], kf[np][3]);
            }
        }

        // ---- scale (+ causal mask on diagonal tiles) ----
        const bool diag = (jt >= 2 * it);
#pragma unroll
        for (int nt = 0; nt < 8; nt++)
#pragma unroll
            for (int j = 0; j < 4; j++) {
                float t = s[nt][j] * SCALE2;
                if (diag) {
                    int col = jt * 64 + nt * 8 + t2 + (j & 1);
                    int row = rbase + g + 8 * (j >> 1);
                    if (col > row) t = -1e30f;
                }
                s[nt][j] = t;
            }

        // ---- online softmax ----
        float rmax[2] = {-1e30f, -1e30f};
#pragma unroll
        for (int nt = 0; nt < 8; nt++) {
            rmax[0] = fmaxf(rmax[0], fmaxf(s[nt][0], s[nt][1]));
            rmax[1] = fmaxf(rmax[1], fmaxf(s[nt][2], s[nt][3]));
        }
#pragma unroll
        for (int off = 1; off <= 2; off <<= 1) {
            rmax[0] = fmaxf(rmax[0], __shfl_xor_sync(0xffffffffu, rmax[0], off));
            rmax[1] = fmaxf(rmax[1], __shfl_xor_sync(0xffffffffu, rmax[1], off));
        }
        float alpha[2], rsum[2];
#pragma unroll
        for (int r = 0; r < 2; r++) {
            float mnew = fmaxf(m2[r], rmax[r]);
            alpha[r] = ex2(m2[r] - mnew);
            m2[r] = mnew;
            rsum[r] = 0.f;
        }
#pragma unroll
        for (int nt = 0; nt < 8; nt++) {
            s[nt][0] = ex2(s[nt][0] - m2[0]);
            s[nt][1] = ex2(s[nt][1] - m2[0]);
            s[nt][2] = ex2(s[nt][2] - m2[1]);
            s[nt][3] = ex2(s[nt][3] - m2[1]);
            rsum[0] += s[nt][0] + s[nt][1];
            rsum[1] += s[nt][2] + s[nt][3];
        }
#pragma unroll
        for (int off = 1; off <= 2; off <<= 1) {
            rsum[0] += __shfl_xor_sync(0xffffffffu, rsum[0], off);
            rsum[1] += __shfl_xor_sync(0xffffffffu, rsum[1], off);
        }
#pragma unroll
        for (int r = 0; r < 2; r++) l[r] = l[r] * alpha[r] + rsum[r];
#pragma unroll
        for (int dt = 0; dt < 8; dt++) {
            o[dt][0] *= alpha[0];
            o[dt][1] *= alpha[0];
            o[dt][2] *= alpha[1];
            o[dt][3] *= alpha[1];
        }

        // ---- pack P (single fp16) ----
        uint32_t ph[4][4];
#pragma unroll
        for (int ks = 0; ks < 4; ks++) {
#pragma unroll
            for (int half = 0; half < 2; half++) {
                int nt = 2 * ks + half;
                ph[ks][2 * half]     = pack_f16(s[nt][0], s[nt][1]);
                ph[ks][2 * half + 1] = pack_f16(s[nt][2], s[nt][3]);
            }
        }

        // ---- O += P V : 1 pass ----
#pragma unroll
        for (int ks = 0; ks < 4; ks++) {
            uint32_t vf[4][4];
#pragma unroll
            for (int np = 0; np < 4; np++)
                ldsm_x4_t(VB + voff + (uint32_t)(ks * 16 * AT_STRIDE + np * 16) * 2, vf[np]);
#pragma unroll
            for (int np = 0; np < 4; np++) {
                mma16816(o[2 * np],     ph[ks], vf[np][0], vf[np][1]);
                mma16816(o[2 * np + 1], ph[ks], vf[np][2], vf[np][3]);
            }
        }
        __syncthreads();
    }

    // ---- epilogue: O/l -> att hi (single fp16) ----
    float inv0 = 1.0f / l[0], inv1 = 1.0f / l[1];
#pragma unroll
    for (int dt = 0; dt < 8; dt++) {
        int col = hc + dt * 8 + t2;
        size_t i0 = (rowbase + rbase + g) * EMB + col;
        size_t i1 = (rowbase + rbase + g + 8) * EMB + col;
        *(uint32_t*)(att_hi + i0) = pack_f16(o[dt][0] * inv0, o[dt][1] * inv0);
        *(uint32_t*)(att_hi + i1) = pack_f16(o[dt][2] * inv1, o[dt][3] * inv1);
    }
}

// ---------------------------------------------------------------------------
// Launch
// ---------------------------------------------------------------------------
extern "C" void kernel_launch(void* const* d_in, const int* in_sizes, int n_in,
                              void* d_out, int out_size) {
    const float* x      = (const float*)d_in[0];
    const float* w_qkv  = (const float*)d_in[1];
    const float* w_out  = (const float*)d_in[2];
    const float* b_out  = (const float*)d_in[3];
    float* out = (float*)d_out;

    __half *x_hi, *x_lo, *wq_hi, *wo_hi, *qkv_hi, *q_lo, *a_hi;
    cudaGetSymbolAddress((void**)&x_hi,   g_x_hi);
    cudaGetSymbolAddress((void**)&x_lo,   g_x_lo);
    cudaGetSymbolAddress((void**)&wq_hi,  g_wqkv_hi);
    cudaGetSymbolAddress((void**)&wo_hi,  g_wout_hi);
    cudaGetSymbolAddress((void**)&qkv_hi, g_qkv_hi);
    cudaGetSymbolAddress((void**)&q_lo,   g_q_lo);
    cudaGetSymbolAddress((void**)&a_hi,   g_att_hi);

    cudaFuncSetAttribute(attn_mma,
                         cudaFuncAttributeMaxDynamicSharedMemorySize, ATTN_SMEM);
    cudaFuncSetAttribute((const void*)gemm_mma<1, false, true>,
                         cudaFuncAttributeMaxDynamicSharedMemorySize, GEMM_SMEM);
    cudaFuncSetAttribute((const void*)gemm_mma<2, true, false>,
                         cudaFuncAttributeMaxDynamicSharedMemorySize, GEMM_SMEM);

    // 0) fp16 splits: x -> hi/lo; w_qkv -> permuted [Q|K|V] hi; w_out -> hi
    {
        int n4 = ROWS * EMB / 4;
        split_f16<<<(n4 + 255) / 256, 256>>>((const float4*)x,
            (__half2*)x_hi, (__half2*)x_lo, n4);
        int nperm = F3 * (EMB / 4);
        split_f16_perm<<<(nperm + 255) / 256, 256>>>((const float4*)w_qkv,
            (__half2*)wq_hi);
        n4 = EMB * EMB / 4;
        split_f16<<<(n4 + 255) / 256, 256>>>((const float4*)w_out,
            (__half2*)wo_hi, nullptr, n4);
    }

    // 1) QKV projection -> permuted qkv_hi (+ q_lo for Q block)
    gemm_mma<1, false, true><<<dim3(F3 / 128, ROWS / 256), 256, GEMM_SMEM>>>(
        x_hi, x_lo, wq_hi, nullptr, nullptr, qkv_hi, q_lo, F3, EMB);

    // 2) Tensor-core causal flash attention -> att hi (single fp16)
    attn_mma<<<dim3(SEQ / 128, NH, BS), 256, ATTN_SMEM>>>(qkv_hi, q_lo, a_hi);

    // 3) Output projection + bias (single pass) -> fp32 out
    gemm_mma<2, true, false><<<dim3(EMB / 128, ROWS / 256), 256, GEMM_SMEM>>>(
        a_hi, nullptr, wo_hi, b_out, out, nullptr, nullptr, EMB, EMB);
}

// round 11
// speedup vs baseline: 2.3238x; 1.2134x over previous
#include <cuda_runtime.h>
#include <cuda_fp16.h>
#include <cstdint>
#include <math.h>

// Problem constants (fixed shapes)
#define BS   2
#define SEQ  2048
#define EMB  1024
#define NH   16
#define HD   64
#define F3   3072   // 3*EMB
#define ROWS (BS * SEQ)   // 4096

// ---------------------------------------------------------------------------
// Scratch (device globals: allocation-free rule)
// qkv layout PERMUTED: cols [0,1024) = Q (h*64+d), [1024,2048) = K, [2048,3072) = V.
// ---------------------------------------------------------------------------
__device__ __half g_x_hi[ROWS * EMB];
__device__ __half g_wqkv_hi[F3 * EMB];      // permuted rows: [Q|K|V]
__device__ __half g_wout_hi[EMB * EMB];
__device__ __half g_qkv_hi[ROWS * F3];      // [Q|K|V] per row
__device__ __half g_att_hi[ROWS * EMB];

// ---------------------------------------------------------------------------
// helpers
// ---------------------------------------------------------------------------
__device__ __forceinline__ uint32_t smem_u32(const void* p) {
    uint32_t a;
    asm("{ .reg .u64 t; cvta.to.shared.u64 t, %1; cvt.u32.u64 %0, t; }" : "=r"(a) : "l"(p));
    return a;
}
__device__ __forceinline__ void ldsm_x4(uint32_t addr, uint32_t r[4]) {
    asm volatile("ldmatrix.sync.aligned.m8n8.x4.shared.b16 {%0,%1,%2,%3}, [%4];"
                 : "=r"(r[0]), "=r"(r[1]), "=r"(r[2]), "=r"(r[3]) : "r"(addr));
}
__device__ __forceinline__ void ldsm_x4_t(uint32_t addr, uint32_t r[4]) {
    asm volatile("ldmatrix.sync.aligned.m8n8.x4.trans.shared.b16 {%0,%1,%2,%3}, [%4];"
                 : "=r"(r[0]), "=r"(r[1]), "=r"(r[2]), "=r"(r[3]) : "r"(addr));
}
__device__ __forceinline__ void mma16816(float c[4], const uint32_t a[4],
                                         const uint32_t b0, const uint32_t b1) {
    asm volatile(
        "mma.sync.aligned.m16n8k16.row.col.f32.f16.f16.f32 "
        "{%0,%1,%2,%3}, {%4,%5,%6,%7}, {%8,%9}, {%0,%1,%2,%3};"
        : "+f"(c[0]), "+f"(c[1]), "+f"(c[2]), "+f"(c[3])
        : "r"(a[0]), "r"(a[1]), "r"(a[2]), "r"(a[3]), "r"(b0), "r"(b1));
}
__device__ __forceinline__ uint32_t pack_f16(float lo, float hi) {
    __half2 h = __floats2half2_rn(lo, hi);
    return *(uint32_t*)&h;
}
__device__ __forceinline__ float ex2(float x) {
    float r;
    asm("ex2.approx.ftz.f32 %0, %1;" : "=f"(r) : "f"(x));
    return r;
}
__device__ __forceinline__ void cp_async16(uint32_t dst, const void* src) {
    asm volatile("cp.async.cg.shared.global [%0], [%1], 16;" :: "r"(dst), "l"(src));
}
#define CP_COMMIT() asm volatile("cp.async.commit_group;" ::: "memory")
#define CP_WAIT1()  asm volatile("cp.async.wait_group 1;" ::: "memory")
#define CP_WAIT0()  asm volatile("cp.async.wait_group 0;" ::: "memory")

// ---------------------------------------------------------------------------
// fp16 round (float4 vectorized)
// ---------------------------------------------------------------------------
__global__ void round_f16(const float4* __restrict__ in,
                          __half2* __restrict__ hi, int n4) {
    int i = blockIdx.x * blockDim.x + threadIdx.x;
    if (i >= n4) return;
    float4 v = in[i];
    hi[2 * i]     = __half2(__float2half_rn(v.x), __float2half_rn(v.y));
    hi[2 * i + 1] = __half2(__float2half_rn(v.z), __float2half_rn(v.w));
}

// Permuting round for w_qkv: dst row r (r<1024: Q; <2048: K; else V) maps to
// src row h*192 + m*64 + d where m=r/1024, h=(r%1024)/64, d=r%64.
__global__ void round_f16_perm(const float4* __restrict__ in,
                               __half2* __restrict__ hi) {
    int idx = blockIdx.x * blockDim.x + threadIdx.x;   // over F3 * (EMB/4)
    if (idx >= F3 * (EMB / 4)) return;
    int r = idx >> 8;            // EMB/4 = 256 float4 per row
    int q = idx & 255;
    int m = r >> 10;
    int within = r & 1023;
    int hsrc = (within >> 6) * 192 + m * 64 + (within & 63);
    float4 v = in[(size_t)hsrc * 256 + q];
    hi[2 * idx]     = __half2(__float2half_rn(v.x), __float2half_rn(v.y));
    hi[2 * idx + 1] = __half2(__float2half_rn(v.z), __float2half_rn(v.w));
}

// ---------------------------------------------------------------------------
// mma.sync fp16 GEMM (single pass), cp.async double-buffered.
// CTA tile 256x128, 8 warps, warp tile 64x64, BK=32.
// ---------------------------------------------------------------------------
#define SA_STRIDE 40
#define ATILE_B (256 * SA_STRIDE * 2)           // 20480
#define BTILE_B (128 * SA_STRIDE * 2)           // 10240
#define STAGE_B (ATILE_B + BTILE_B)             // 30720
#define GEMM_SMEM (2 * STAGE_B)                 // 61440

template <bool HAS_BIAS, bool OUT_F16>
__global__ __launch_bounds__(256, 1)
void gemm_mma(const __half* __restrict__ A, const __half* __restrict__ B,
              const float* __restrict__ bias, float* __restrict__ C,
              __half* __restrict__ Ch, int N, int K) {
    extern __shared__ char smem[];
    const uint32_t sb = smem_u32(smem);

    const int tid  = threadIdx.x;
    const int wid  = tid >> 5;
    const int lane = tid & 31;
    const int n0 = blockIdx.x * 128;
    const int m0 = blockIdx.y * 256;
    const int wm = (wid & 3) * 64;
    const int wn = (wid >> 2) * 64;

    const int trow  = lane & 7;
    const int tquad = lane >> 3;
    const int a_row_off = (tquad & 1) * 8 + trow;
    const int a_col_off = (tquad >> 1) * 8;
    const int b_row_off = (tquad >> 1) * 8 + trow;
    const int b_col_off = (tquad & 1) * 8;

    float acc[4][8][4];
#pragma unroll
    for (int mt = 0; mt < 4; mt++)
#pragma unroll
        for (int nt = 0; nt < 8; nt++)
#pragma unroll
            for (int j = 0; j < 4; j++) acc[mt][nt][j] = 0.0f;

    auto load_stage = [&](int stage, int k0) {
        uint32_t s0 = sb + stage * STAGE_B;
#pragma unroll
        for (int i = 0; i < 4; i++) {
            int idx = tid + 256 * i;
            int row = idx >> 2, q = idx & 3;
            uint32_t soff = (uint32_t)(row * SA_STRIDE + q * 8) * 2;
            cp_async16(s0 + soff, A + (size_t)(m0 + row) * K + k0 + q * 8);
        }
#pragma unroll
        for (int i = 0; i < 2; i++) {
            int idx = tid + 256 * i;
            int row = idx >> 2, q = idx & 3;
            uint32_t soff = (uint32_t)(row * SA_STRIDE + q * 8) * 2;
            cp_async16(s0 + ATILE_B + soff, B + (size_t)(n0 + row) * K + k0 + q * 8);
        }
        CP_COMMIT();
    };

    const int NC = K >> 5;
    load_stage(0, 0);

    for (int c = 0; c < NC; c++) {
        const bool pref = (c + 1 < NC);
        if (pref) load_stage((c + 1) & 1, (c + 1) * 32);
        if (pref) CP_WAIT1(); else CP_WAIT0();
        __syncthreads();

        const uint32_t AT = sb + (c & 1) * STAGE_B;
        const uint32_t BT = AT + ATILE_B;

#pragma unroll
        for (int ks = 0; ks < 2; ks++) {
            const int kk = ks * 16;
            uint32_t af[4][4], bf[4][4];
#pragma unroll
            for (int mt = 0; mt < 4; mt++)
                ldsm_x4(AT + (uint32_t)((wm + mt * 16 + a_row_off) * SA_STRIDE +
                                        kk + a_col_off) * 2, af[mt]);
#pragma unroll
            for (int np = 0; np < 4; np++)
                ldsm_x4(BT + (uint32_t)((wn + np * 16 + b_row_off) * SA_STRIDE +
                                        kk + b_col_off) * 2, bf[np]);
#pragma unroll
            for (int mt = 0; mt < 4; mt++)
#pragma unroll
                for (int np = 0; np < 4; np++) {
                    mma16816(acc[mt][2 * np],     af[mt], bf[np][0], bf[np][1]);
                    mma16816(acc[mt][2 * np + 1], af[mt], bf[np][2], bf[np][3]);
                }
        }
        __syncthreads();
    }

    const int g  = lane >> 2;
    const int t2 = (lane & 3) * 2;
#pragma unroll
    for (int mt = 0; mt < 4; mt++) {
        int mrow0 = m0 + wm + mt * 16 + g;
#pragma unroll
        for (int nt = 0; nt < 8; nt++) {
            int n = n0 + wn + nt * 8 + t2;
            float b0 = 0.f, b1 = 0.f;
            if (HAS_BIAS) { b0 = bias[n]; b1 = bias[n + 1]; }
            float v00 = acc[mt][nt][0] + b0, v01 = acc[mt][nt][1] + b1;
            float v10 = acc[mt][nt][2] + b0, v11 = acc[mt][nt][3] + b1;
            if (OUT_F16) {
                *(uint32_t*)(Ch + (size_t)mrow0 * N + n)       = pack_f16(v00, v01);
                *(uint32_t*)(Ch + (size_t)(mrow0 + 8) * N + n) = pack_f16(v10, v11);
            } else {
                *(float2*)(C + (size_t)mrow0 * N + n)       = make_float2(v00, v01);
                *(float2*)(C + (size_t)(mrow0 + 8) * N + n) = make_float2(v10, v11);
            }
        }
    }
}

// ---------------------------------------------------------------------------
// Tensor-core causal flash attention, full fp16 operands (Q,K,V,P single),
// fp32 accum. BM=128, BN=64, HD=64, 8 warps, cp.async double-buffered.
// qkv_hi layout: [row][ Q | K | V ], col h*64+d within each block.
// ---------------------------------------------------------------------------
#define AT_STRIDE 72
#define AT_TILE (64 * AT_STRIDE * 2)       // 9216 bytes
#define AT_STAGE (2 * AT_TILE)             // 18432: K, V
#define ATTN_SMEM (2 * AT_STAGE)           // 36864

#define SCALE2 0.1803368801111244f         // 0.125 * log2(e)

__global__ __launch_bounds__(256)
void attn_mma(const __half* __restrict__ qkv_hi,
              __half* __restrict__ att_hi) {
    extern __shared__ char smem[];
    const uint32_t sb = smem_u32(smem);

    const int tid  = threadIdx.x;
    const int wid  = tid >> 5;
    const int lane = tid & 31;
    const int it = gridDim.x - 1 - blockIdx.x;   // big tiles first
    const int h  = blockIdx.y;
    const int b  = blockIdx.z;
    const int hc = h * 64;
    const size_t rowbase = (size_t)b * SEQ;

    // ---- Stage Q (128x64 fp16) through stage-0 buffers ----
#pragma unroll
    for (int i = 0; i < 4; i++) {
        int idx = tid + 256 * i;      // 0..1023
        int row = idx >> 3, q = idx & 7;
        int tsel = row >> 6, drow = row & 63;
        uint32_t soff = (uint32_t)(tsel * AT_TILE + (drow * AT_STRIDE + q * 8) * 2);
        size_t grow = rowbase + it * 128 + row;
        *(uint4*)(smem + soff) = *(const uint4*)(qkv_hi + grow * F3 + hc + q * 8);
    }
    __syncthreads();

    // Q fragments: warp w owns rows 16*(w&3) + 64*(w>>2)
    uint32_t qh[4][4];
    {
        uint32_t hb = sb + (wid >> 2) * AT_TILE;
        uint32_t qoff = (uint32_t)((16 * (wid & 3) + (lane & 15)) * AT_STRIDE +
                                   (lane >> 4) * 8) * 2;
#pragma unroll
        for (int ks = 0; ks < 4; ks++)
            ldsm_x4(hb + qoff + ks * 32, qh[ks]);
    }
    __syncthreads();   // everyone done reading Q before overwrite

    auto load_kv = [&](int stage, int jt) {
        uint32_t sbase = sb + stage * AT_STAGE;
#pragma unroll
        for (int i = 0; i < 2; i++) {
            int idx = tid * 2 + i;
            int row = idx >> 3, q = idx & 7;
            uint32_t soff = (uint32_t)(row * AT_STRIDE + q * 8) * 2;
            size_t grow = rowbase + jt * 64 + row;
            cp_async16(sbase + soff,           qkv_hi + grow * F3 + EMB + hc + q * 8);     // K
            cp_async16(sbase + AT_TILE + soff, qkv_hi + grow * F3 + 2 * EMB + hc + q * 8); // V
        }
        CP_COMMIT();
    };

    float m2[2] = {-1e30f, -1e30f}, l[2] = {0.f, 0.f};
    float o[8][4];
#pragma unroll
    for (int dt = 0; dt < 8; dt++)
#pragma unroll
        for (int j = 0; j < 4; j++) o[dt][j] = 0.0f;

    const int rbase = 128 * it + 16 * (wid & 3) + 64 * (wid >> 2);
    const int g  = lane >> 2;
    const int t2 = (lane & 3) * 2;
    const uint32_t koff = (uint32_t)(((lane >> 4) * 8 + (lane & 7)) * AT_STRIDE +
                                     ((lane >> 3) & 1) * 8) * 2;
    const uint32_t voff = (uint32_t)((lane & 15) * AT_STRIDE + (lane >> 4) * 8) * 2;

    const int jt_max = 2 * it + 2;
    load_kv(0, 0);

    for (int jt = 0; jt < jt_max; jt++) {
        const bool pref = (jt + 1 < jt_max);
        if (pref) load_kv((jt + 1) & 1, jt + 1);
        if (pref) CP_WAIT1(); else CP_WAIT0();
        __syncthreads();

        const uint32_t KB = sb + (jt & 1) * AT_STAGE;
        const uint32_t VB = KB + AT_TILE;

        // ---- S = Q K^T : 1 pass ----
        float s[8][4];
#pragma unroll
        for (int nt = 0; nt < 8; nt++)
#pragma unroll
            for (int j = 0; j < 4; j++) s[nt][j] = 0.0f;

#pragma unroll
        for (int ks = 0; ks < 4; ks++) {
            uint32_t kf[4][4];
#pragma unroll
            for (int np = 0; np < 4; np++)
                ldsm_x4(KB + koff + (uint32_t)(np * 16 * AT_STRIDE + ks * 16) * 2, kf[np]);
#pragma unroll
            for (int np = 0; np < 4; np++) {
                mma16816(s[2 * np],     qh[ks], kf[np][0], kf[np][1]);
                mma16816(s[2 * np + 1], qh[ks], kf[np][2], kf[np][3]);
            }
        }

        // ---- scale (+ causal mask on diagonal tiles) ----
        const bool diag = (jt >= 2 * it);
#pragma unroll
        for (int nt = 0; nt < 8; nt++)
#pragma unroll
            for (int j = 0; j < 4; j++) {
                float t = s[nt][j] * SCALE2;
                if (diag) {
                    int col = jt * 64 + nt * 8 + t2 + (j & 1);
                    int row = rbase + g + 8 * (j >> 1);
                    if (col > row) t = -1e30f;
                }
                s[nt][j] = t;
            }

        // ---- online softmax ----
        float rmax[2] = {-1e30f, -1e30f};
#pragma unroll
        for (int nt = 0; nt < 8; nt++) {
            rmax[0] = fmaxf(rmax[0], fmaxf(s[nt][0], s[nt][1]));
            rmax[1] = fmaxf(rmax[1], fmaxf(s[nt][2], s[nt][3]));
        }
#pragma unroll
        for (int off = 1; off <= 2; off <<= 1) {
            rmax[0] = fmaxf(rmax[0], __shfl_xor_sync(0xffffffffu, rmax[0], off));
            rmax[1] = fmaxf(rmax[1], __shfl_xor_sync(0xffffffffu, rmax[1], off));
        }
        float alpha[2], rsum[2];
#pragma unroll
        for (int r = 0; r < 2; r++) {
            float mnew = fmaxf(m2[r], rmax[r]);
            alpha[r] = ex2(m2[r] - mnew);
            m2[r] = mnew;
            rsum[r] = 0.f;
        }
#pragma unroll
        for (int nt = 0; nt < 8; nt++) {
            s[nt][0] = ex2(s[nt][0] - m2[0]);
            s[nt][1] = ex2(s[nt][1] - m2[0]);
            s[nt][2] = ex2(s[nt][2] - m2[1]);
            s[nt][3] = ex2(s[nt][3] - m2[1]);
            rsum[0] += s[nt][0] + s[nt][1];
            rsum[1] += s[nt][2] + s[nt][3];
        }
#pragma unroll
        for (int off = 1; off <= 2; off <<= 1) {
            rsum[0] += __shfl_xor_sync(0xffffffffu, rsum[0], off);
            rsum[1] += __shfl_xor_sync(0xffffffffu, rsum[1], off);
        }
#pragma unroll
        for (int r = 0; r < 2; r++) l[r] = l[r] * alpha[r] + rsum[r];
#pragma unroll
        for (int dt = 0; dt < 8; dt++) {
            o[dt][0] *= alpha[0];
            o[dt][1] *= alpha[0];
            o[dt][2] *= alpha[1];
            o[dt][3] *= alpha[1];
        }

        // ---- pack P (single fp16) ----
        uint32_t ph[4][4];
#pragma unroll
        for (int ks = 0; ks < 4; ks++) {
#pragma unroll
            for (int half = 0; half < 2; half++) {
                int nt = 2 * ks + half;
                ph[ks][2 * half]     = pack_f16(s[nt][0], s[nt][1]);
                ph[ks][2 * half + 1] = pack_f16(s[nt][2], s[nt][3]);
            }
        }

        // ---- O += P V : 1 pass ----
#pragma unroll
        for (int ks = 0; ks < 4; ks++) {
            uint32_t vf[4][4];
#pragma unroll
            for (int np = 0; np < 4; np++)
                ldsm_x4_t(VB + voff + (uint32_t)(ks * 16 * AT_STRIDE + np * 16) * 2, vf[np]);
#pragma unroll
            for (int np = 0; np < 4; np++) {
                mma16816(o[2 * np],     ph[ks], vf[np][0], vf[np][1]);
                mma16816(o[2 * np + 1], ph[ks], vf[np][2], vf[np][3]);
            }
        }
        __syncthreads();
    }

    // ---- epilogue: O/l -> att (fp16) ----
    float inv0 = 1.0f / l[0], inv1 = 1.0f / l[1];
#pragma unroll
    for (int dt = 0; dt < 8; dt++) {
        int col = hc + dt * 8 + t2;
        size_t i0 = (rowbase + rbase + g) * EMB + col;
        size_t i1 = (rowbase + rbase + g + 8) * EMB + col;
        *(uint32_t*)(att_hi + i0) = pack_f16(o[dt][0] * inv0, o[dt][1] * inv0);
        *(uint32_t*)(att_hi + i1) = pack_f16(o[dt][2] * inv1, o[dt][3] * inv1);
    }
}

// ---------------------------------------------------------------------------
// Launch
// ---------------------------------------------------------------------------
extern "C" void kernel_launch(void* const* d_in, const int* in_sizes, int n_in,
                              void* d_out, int out_size) {
    const float* x      = (const float*)d_in[0];
    const float* w_qkv  = (const float*)d_in[1];
    const float* w_out  = (const float*)d_in[2];
    const float* b_out  = (const float*)d_in[3];
    float* out = (float*)d_out;

    __half *x_hi, *wq_hi, *wo_hi, *qkv_hi, *a_hi;
    cudaGetSymbolAddress((void**)&x_hi,   g_x_hi);
    cudaGetSymbolAddress((void**)&wq_hi,  g_wqkv_hi);
    cudaGetSymbolAddress((void**)&wo_hi,  g_wout_hi);
    cudaGetSymbolAddress((void**)&qkv_hi, g_qkv_hi);
    cudaGetSymbolAddress((void**)&a_hi,   g_att_hi);

    cudaFuncSetAttribute(attn_mma,
                         cudaFuncAttributeMaxDynamicSharedMemorySize, ATTN_SMEM);
    cudaFuncSetAttribute((const void*)gemm_mma<false, true>,
                         cudaFuncAttributeMaxDynamicSharedMemorySize, GEMM_SMEM);
    cudaFuncSetAttribute((const void*)gemm_mma<true, false>,
                         cudaFuncAttributeMaxDynamicSharedMemorySize, GEMM_SMEM);

    // 0) fp16 rounds: x; w_qkv (permuted [Q|K|V]); w_out
    {
        int n4 = ROWS * EMB / 4;
        round_f16<<<(n4 + 255) / 256, 256>>>((const float4*)x, (__half2*)x_hi, n4);
        int nperm = F3 * (EMB / 4);
        round_f16_perm<<<(nperm + 255) / 256, 256>>>((const float4*)w_qkv,
            (__half2*)wq_hi);
        n4 = EMB * EMB / 4;
        round_f16<<<(n4 + 255) / 256, 256>>>((const float4*)w_out, (__half2*)wo_hi, n4);
    }

    // 1) QKV projection (single pass) -> permuted qkv fp16
    gemm_mma<false, true><<<dim3(F3 / 128, ROWS / 256), 256, GEMM_SMEM>>>(
        x_hi, wq_hi, nullptr, nullptr, qkv_hi, F3, EMB);

    // 2) Tensor-core causal flash attention -> att fp16
    attn_mma<<<dim3(SEQ / 128, NH, BS), 256, ATTN_SMEM>>>(qkv_hi, a_hi);

    // 3) Output projection + bias (single pass) -> fp32 out
    gemm_mma<true, false><<<dim3(EMB / 128, ROWS / 256), 256, GEMM_SMEM>>>(
        a_hi, wo_hi, b_out, out, nullptr, EMB, EMB);
}

// round 12
// speedup vs baseline: 2.5106x; 1.0804x over previous
#include <cuda_runtime.h>
#include <cuda_fp16.h>
#include <cstdint>
#include <math.h>

// Problem constants (fixed shapes)
#define BS   2
#define SEQ  2048
#define EMB  1024
#define NH   16
#define HD   64
#define F3   3072   // 3*EMB
#define ROWS (BS * SEQ)   // 4096

// ---------------------------------------------------------------------------
// Scratch (device globals: allocation-free rule)
// qkv layout PERMUTED: cols [0,1024) = Q (h*64+d), [1024,2048) = K, [2048,3072) = V.
// ---------------------------------------------------------------------------
__device__ __half g_x_hi[ROWS * EMB];
__device__ __half g_wqkv_hi[F3 * EMB];      // permuted rows: [Q|K|V]
__device__ __half g_wout_hi[EMB * EMB];
__device__ __half g_qkv_hi[ROWS * F3];      // [Q|K|V] per row
__device__ __half g_att_hi[ROWS * EMB];

// ---------------------------------------------------------------------------
// helpers
// ---------------------------------------------------------------------------
__device__ __forceinline__ uint32_t smem_u32(const void* p) {
    uint32_t a;
    asm("{ .reg .u64 t; cvta.to.shared.u64 t, %1; cvt.u32.u64 %0, t; }" : "=r"(a) : "l"(p));
    return a;
}
__device__ __forceinline__ void ldsm_x4(uint32_t addr, uint32_t r[4]) {
    asm volatile("ldmatrix.sync.aligned.m8n8.x4.shared.b16 {%0,%1,%2,%3}, [%4];"
                 : "=r"(r[0]), "=r"(r[1]), "=r"(r[2]), "=r"(r[3]) : "r"(addr));
}
__device__ __forceinline__ void ldsm_x4_t(uint32_t addr, uint32_t r[4]) {
    asm volatile("ldmatrix.sync.aligned.m8n8.x4.trans.shared.b16 {%0,%1,%2,%3}, [%4];"
                 : "=r"(r[0]), "=r"(r[1]), "=r"(r[2]), "=r"(r[3]) : "r"(addr));
}
__device__ __forceinline__ void mma16816(float c[4], const uint32_t a[4],
                                         const uint32_t b0, const uint32_t b1) {
    asm volatile(
        "mma.sync.aligned.m16n8k16.row.col.f32.f16.f16.f32 "
        "{%0,%1,%2,%3}, {%4,%5,%6,%7}, {%8,%9}, {%0,%1,%2,%3};"
        : "+f"(c[0]), "+f"(c[1]), "+f"(c[2]), "+f"(c[3])
        : "r"(a[0]), "r"(a[1]), "r"(a[2]), "r"(a[3]), "r"(b0), "r"(b1));
}
__device__ __forceinline__ uint32_t pack_f16(float lo, float hi) {
    __half2 h = __floats2half2_rn(lo, hi);
    return *(uint32_t*)&h;
}
__device__ __forceinline__ float ex2(float x) {
    float r;
    asm("ex2.approx.ftz.f32 %0, %1;" : "=f"(r) : "f"(x));
    return r;
}
__device__ __forceinline__ void cp_async16(uint32_t dst, const void* src) {
    asm volatile("cp.async.cg.shared.global [%0], [%1], 16;" :: "r"(dst), "l"(src));
}
#define CP_COMMIT() asm volatile("cp.async.commit_group;" ::: "memory")
#define CP_WAIT1()  asm volatile("cp.async.wait_group 1;" ::: "memory")
#define CP_WAIT0()  asm volatile("cp.async.wait_group 0;" ::: "memory")

// ---------------------------------------------------------------------------
// fp16 round (float4 vectorized)
// ---------------------------------------------------------------------------
__global__ void round_f16(const float4* __restrict__ in,
                          __half2* __restrict__ hi, int n4) {
    int i = blockIdx.x * blockDim.x + threadIdx.x;
    if (i >= n4) return;
    float4 v = in[i];
    hi[2 * i]     = __half2(__float2half_rn(v.x), __float2half_rn(v.y));
    hi[2 * i + 1] = __half2(__float2half_rn(v.z), __float2half_rn(v.w));
}

// Permuting round for w_qkv: dst row r (r<1024: Q; <2048: K; else V) maps to
// src row h*192 + m*64 + d where m=r/1024, h=(r%1024)/64, d=r%64.
__global__ void round_f16_perm(const float4* __restrict__ in,
                               __half2* __restrict__ hi) {
    int idx = blockIdx.x * blockDim.x + threadIdx.x;   // over F3 * (EMB/4)
    if (idx >= F3 * (EMB / 4)) return;
    int r = idx >> 8;            // EMB/4 = 256 float4 per row
    int q = idx & 255;
    int m = r >> 10;
    int within = r & 1023;
    int hsrc = (within >> 6) * 192 + m * 64 + (within & 63);
    float4 v = in[(size_t)hsrc * 256 + q];
    hi[2 * idx]     = __half2(__float2half_rn(v.x), __float2half_rn(v.y));
    hi[2 * idx + 1] = __half2(__float2half_rn(v.z), __float2half_rn(v.w));
}

// ---------------------------------------------------------------------------
// mma.sync fp16 GEMM (single pass), cp.async double-buffered, BK=64.
// CTA tile 256x128, 8 warps, warp tile 64x64. 4 k-steps (128 MMAs) per region.
// ---------------------------------------------------------------------------
#define SA_STRIDE 72
#define ATILE_B (256 * SA_STRIDE * 2)           // 36864
#define BTILE_B (128 * SA_STRIDE * 2)           // 18432
#define STAGE_B (ATILE_B + BTILE_B)             // 55296
#define GEMM_SMEM (2 * STAGE_B)                 // 110592

template <bool HAS_BIAS, bool OUT_F16>
__global__ __launch_bounds__(256, 1)
void gemm_mma(const __half* __restrict__ A, const __half* __restrict__ B,
              const float* __restrict__ bias, float* __restrict__ C,
              __half* __restrict__ Ch, int N, int K) {
    extern __shared__ char smem[];
    const uint32_t sb = smem_u32(smem);

    const int tid  = threadIdx.x;
    const int wid  = tid >> 5;
    const int lane = tid & 31;
    const int n0 = blockIdx.x * 128;
    const int m0 = blockIdx.y * 256;
    const int wm = (wid & 3) * 64;
    const int wn = (wid >> 2) * 64;

    const int trow  = lane & 7;
    const int tquad = lane >> 3;
    const int a_row_off = (tquad & 1) * 8 + trow;
    const int a_col_off = (tquad >> 1) * 8;
    const int b_row_off = (tquad >> 1) * 8 + trow;
    const int b_col_off = (tquad & 1) * 8;

    float acc[4][8][4];
#pragma unroll
    for (int mt = 0; mt < 4; mt++)
#pragma unroll
        for (int nt = 0; nt < 8; nt++)
#pragma unroll
            for (int j = 0; j < 4; j++) acc[mt][nt][j] = 0.0f;

    // stage loader: A 256x64 (8 x16B per thread), B 128x64 (4 x16B per thread)
    auto load_stage = [&](int stage, int k0) {
        uint32_t s0 = sb + stage * STAGE_B;
#pragma unroll
        for (int i = 0; i < 8; i++) {
            int idx = tid + 256 * i;          // 0..2047
            int row = idx >> 3, q = idx & 7;
            uint32_t soff = (uint32_t)(row * SA_STRIDE + q * 8) * 2;
            cp_async16(s0 + soff, A + (size_t)(m0 + row) * K + k0 + q * 8);
        }
#pragma unroll
        for (int i = 0; i < 4; i++) {
            int idx = tid + 256 * i;          // 0..1023
            int row = idx >> 3, q = idx & 7;
            uint32_t soff = (uint32_t)(row * SA_STRIDE + q * 8) * 2;
            cp_async16(s0 + ATILE_B + soff, B + (size_t)(n0 + row) * K + k0 + q * 8);
        }
        CP_COMMIT();
    };

    const int NC = K >> 6;   // chunks of 64
    load_stage(0, 0);

    for (int c = 0; c < NC; c++) {
        const bool pref = (c + 1 < NC);
        if (pref) load_stage((c + 1) & 1, (c + 1) * 64);
        if (pref) CP_WAIT1(); else CP_WAIT0();
        __syncthreads();

        const uint32_t AT = sb + (c & 1) * STAGE_B;
        const uint32_t BT = AT + ATILE_B;

#pragma unroll
        for (int ks = 0; ks < 4; ks++) {
            const int kk = ks * 16;
            uint32_t af[4][4], bf[4][4];
#pragma unroll
            for (int mt = 0; mt < 4; mt++)
                ldsm_x4(AT + (uint32_t)((wm + mt * 16 + a_row_off) * SA_STRIDE +
                                        kk + a_col_off) * 2, af[mt]);
#pragma unroll
            for (int np = 0; np < 4; np++)
                ldsm_x4(BT + (uint32_t)((wn + np * 16 + b_row_off) * SA_STRIDE +
                                        kk + b_col_off) * 2, bf[np]);
#pragma unroll
            for (int mt = 0; mt < 4; mt++)
#pragma unroll
                for (int np = 0; np < 4; np++) {
                    mma16816(acc[mt][2 * np],     af[mt], bf[np][0], bf[np][1]);
                    mma16816(acc[mt][2 * np + 1], af[mt], bf[np][2], bf[np][3]);
                }
        }
        __syncthreads();
    }

    const int g  = lane >> 2;
    const int t2 = (lane & 3) * 2;
#pragma unroll
    for (int mt = 0; mt < 4; mt++) {
        int mrow0 = m0 + wm + mt * 16 + g;
#pragma unroll
        for (int nt = 0; nt < 8; nt++) {
            int n = n0 + wn + nt * 8 + t2;
            float b0 = 0.f, b1 = 0.f;
            if (HAS_BIAS) { b0 = bias[n]; b1 = bias[n + 1]; }
            float v00 = acc[mt][nt][0] + b0, v01 = acc[mt][nt][1] + b1;
            float v10 = acc[mt][nt][2] + b0, v11 = acc[mt][nt][3] + b1;
            if (OUT_F16) {
                *(uint32_t*)(Ch + (size_t)mrow0 * N + n)       = pack_f16(v00, v01);
                *(uint32_t*)(Ch + (size_t)(mrow0 + 8) * N + n) = pack_f16(v10, v11);
            } else {
                *(float2*)(C + (size_t)mrow0 * N + n)       = make_float2(v00, v01);
                *(float2*)(C + (size_t)(mrow0 + 8) * N + n) = make_float2(v10, v11);
            }
        }
    }
}

// ---------------------------------------------------------------------------
// Tensor-core causal flash attention, full fp16 operands (Q,K,V,P single),
// fp32 accum. BM=128, BN=64, HD=64, 8 warps, cp.async double-buffered.
// qkv layout: [row][ Q | K | V ], col h*64+d within each block.
// ---------------------------------------------------------------------------
#define AT_STRIDE 72
#define AT_TILE (64 * AT_STRIDE * 2)       // 9216 bytes
#define AT_STAGE (2 * AT_TILE)             // 18432: K, V
#define ATTN_SMEM (2 * AT_STAGE)           // 36864

#define SCALE2 0.1803368801111244f         // 0.125 * log2(e)

__global__ __launch_bounds__(256)
void attn_mma(const __half* __restrict__ qkv_hi,
              __half* __restrict__ att_hi) {
    extern __shared__ char smem[];
    const uint32_t sb = smem_u32(smem);

    const int tid  = threadIdx.x;
    const int wid  = tid >> 5;
    const int lane = tid & 31;
    const int it = gridDim.x - 1 - blockIdx.x;   // big tiles first
    const int h  = blockIdx.y;
    const int b  = blockIdx.z;
    const int hc = h * 64;
    const size_t rowbase = (size_t)b * SEQ;

    // ---- Stage Q (128x64 fp16) through stage-0 buffers ----
#pragma unroll
    for (int i = 0; i < 4; i++) {
        int idx = tid + 256 * i;      // 0..1023
        int row = idx >> 3, q = idx & 7;
        int tsel = row >> 6, drow = row & 63;
        uint32_t soff = (uint32_t)(tsel * AT_TILE + (drow * AT_STRIDE + q * 8) * 2);
        size_t grow = rowbase + it * 128 + row;
        *(uint4*)(smem + soff) = *(const uint4*)(qkv_hi + grow * F3 + hc + q * 8);
    }
    __syncthreads();

    // Q fragments: warp w owns rows 16*(w&3) + 64*(w>>2)
    uint32_t qh[4][4];
    {
        uint32_t hb = sb + (wid >> 2) * AT_TILE;
        uint32_t qoff = (uint32_t)((16 * (wid & 3) + (lane & 15)) * AT_STRIDE +
                                   (lane >> 4) * 8) * 2;
#pragma unroll
        for (int ks = 0; ks < 4; ks++)
            ldsm_x4(hb + qoff + ks * 32, qh[ks]);
    }
    __syncthreads();   // everyone done reading Q before overwrite

    auto load_kv = [&](int stage, int jt) {
        uint32_t sbase = sb + stage * AT_STAGE;
#pragma unroll
        for (int i = 0; i < 2; i++) {
            int idx = tid * 2 + i;
            int row = idx >> 3, q = idx & 7;
            uint32_t soff = (uint32_t)(row * AT_STRIDE + q * 8) * 2;
            size_t grow = rowbase + jt * 64 + row;
            cp_async16(sbase + soff,           qkv_hi + grow * F3 + EMB + hc + q * 8);     // K
            cp_async16(sbase + AT_TILE + soff, qkv_hi + grow * F3 + 2 * EMB + hc + q * 8); // V
        }
        CP_COMMIT();
    };

    float m2[2] = {-1e30f, -1e30f}, l[2] = {0.f, 0.f};
    float o[8][4];
#pragma unroll
    for (int dt = 0; dt < 8; dt++)
#pragma unroll
        for (int j = 0; j < 4; j++) o[dt][j] = 0.0f;

    const int rbase = 128 * it + 16 * (wid & 3) + 64 * (wid >> 2);
    const int g  = lane >> 2;
    const int t2 = (lane & 3) * 2;
    const uint32_t koff = (uint32_t)(((lane >> 4) * 8 + (lane & 7)) * AT_STRIDE +
                                     ((lane >> 3) & 1) * 8) * 2;
    const uint32_t voff = (uint32_t)((lane & 15) * AT_STRIDE + (lane >> 4) * 8) * 2;

    const int jt_max = 2 * it + 2;
    load_kv(0, 0);

    for (int jt = 0; jt < jt_max; jt++) {
        const bool pref = (jt + 1 < jt_max);
        if (pref) load_kv((jt + 1) & 1, jt + 1);
        if (pref) CP_WAIT1(); else CP_WAIT0();
        __syncthreads();

        const uint32_t KB = sb + (jt & 1) * AT_STAGE;
        const uint32_t VB = KB + AT_TILE;

        // ---- S = Q K^T : 1 pass ----
        float s[8][4];
#pragma unroll
        for (int nt = 0; nt < 8; nt++)
#pragma unroll
            for (int j = 0; j < 4; j++) s[nt][j] = 0.0f;

#pragma unroll
        for (int ks = 0; ks < 4; ks++) {
            uint32_t kf[4][4];
#pragma unroll
            for (int np = 0; np < 4; np++)
                ldsm_x4(KB + koff + (uint32_t)(np * 16 * AT_STRIDE + ks * 16) * 2, kf[np]);
#pragma unroll
            for (int np = 0; np < 4; np++) {
                mma16816(s[2 * np],     qh[ks], kf[np][0], kf[np][1]);
                mma16816(s[2 * np + 1], qh[ks], kf[np][2], kf[np][3]);
            }
        }

        // ---- scale (+ causal mask on diagonal tiles) ----
        const bool diag = (jt >= 2 * it);
#pragma unroll
        for (int nt = 0; nt < 8; nt++)
#pragma unroll
            for (int j = 0; j < 4; j++) {
                float t = s[nt][j] * SCALE2;
                if (diag) {
                    int col = jt * 64 + nt * 8 + t2 + (j & 1);
                    int row = rbase + g + 8 * (j >> 1);
                    if (col > row) t = -1e30f;
                }
                s[nt][j] = t;
            }

        // ---- online softmax ----
        float rmax[2] = {-1e30f, -1e30f};
#pragma unroll
        for (int nt = 0; nt < 8; nt++) {
            rmax[0] = fmaxf(rmax[0], fmaxf(s[nt][0], s[nt][1]));
            rmax[1] = fmaxf(rmax[1], fmaxf(s[nt][2], s[nt][3]));
        }
#pragma unroll
        for (int off = 1; off <= 2; off <<= 1) {
            rmax[0] = fmaxf(rmax[0], __shfl_xor_sync(0xffffffffu, rmax[0], off));
            rmax[1] = fmaxf(rmax[1], __shfl_xor_sync(0xffffffffu, rmax[1], off));
        }
        float alpha[2], rsum[2];
#pragma unroll
        for (int r = 0; r < 2; r++) {
            float mnew = fmaxf(m2[r], rmax[r]);
            alpha[r] = ex2(m2[r] - mnew);
            m2[r] = mnew;
            rsum[r] = 0.f;
        }
#pragma unroll
        for (int nt = 0; nt < 8; nt++) {
            s[nt][0] = ex2(s[nt][0] - m2[0]);
            s[nt][1] = ex2(s[nt][1] - m2[0]);
            s[nt][2] = ex2(s[nt][2] - m2[1]);
            s[nt][3] = ex2(s[nt][3] - m2[1]);
            rsum[0] += s[nt][0] + s[nt][1];
            rsum[1] += s[nt][2] + s[nt][3];
        }
#pragma unroll
        for (int off = 1; off <= 2; off <<= 1) {
            rsum[0] += __shfl_xor_sync(0xffffffffu, rsum[0], off);
            rsum[1] += __shfl_xor_sync(0xffffffffu, rsum[1], off);
        }
#pragma unroll
        for (int r = 0; r < 2; r++) l[r] = l[r] * alpha[r] + rsum[r];
#pragma unroll
        for (int dt = 0; dt < 8; dt++) {
            o[dt][0] *= alpha[0];
            o[dt][1] *= alpha[0];
            o[dt][2] *= alpha[1];
            o[dt][3] *= alpha[1];
        }

        // ---- pack P (single fp16) ----
        uint32_t ph[4][4];
#pragma unroll
        for (int ks = 0; ks < 4; ks++) {
#pragma unroll
            for (int half = 0; half < 2; half++) {
                int nt = 2 * ks + half;
                ph[ks][2 * half]     = pack_f16(s[nt][0], s[nt][1]);
                ph[ks][2 * half + 1] = pack_f16(s[nt][2], s[nt][3]);
            }
        }

        // ---- O += P V : 1 pass ----
#pragma unroll
        for (int ks = 0; ks < 4; ks++) {
            uint32_t vf[4][4];
#pragma unroll
            for (int np = 0; np < 4; np++)
                ldsm_x4_t(VB + voff + (uint32_t)(ks * 16 * AT_STRIDE + np * 16) * 2, vf[np]);
#pragma unroll
            for (int np = 0; np < 4; np++) {
                mma16816(o[2 * np],     ph[ks], vf[np][0], vf[np][1]);
                mma16816(o[2 * np + 1], ph[ks], vf[np][2], vf[np][3]);
            }
        }
        __syncthreads();
    }

    // ---- epilogue: O/l -> att (fp16) ----
    float inv0 = 1.0f / l[0], inv1 = 1.0f / l[1];
#pragma unroll
    for (int dt = 0; dt < 8; dt++) {
        int col = hc + dt * 8 + t2;
        size_t i0 = (rowbase + rbase + g) * EMB + col;
        size_t i1 = (rowbase + rbase + g + 8) * EMB + col;
        *(uint32_t*)(att_hi + i0) = pack_f16(o[dt][0] * inv0, o[dt][1] * inv0);
        *(uint32_t*)(att_hi + i1) = pack_f16(o[dt][2] * inv1, o[dt][3] * inv1);
    }
}

// ---------------------------------------------------------------------------
// Launch
// ---------------------------------------------------------------------------
extern "C" void kernel_launch(void* const* d_in, const int* in_sizes, int n_in,
                              void* d_out, int out_size) {
    const float* x      = (const float*)d_in[0];
    const float* w_qkv  = (const float*)d_in[1];
    const float* w_out  = (const float*)d_in[2];
    const float* b_out  = (const float*)d_in[3];
    float* out = (float*)d_out;

    __half *x_hi, *wq_hi, *wo_hi, *qkv_hi, *a_hi;
    cudaGetSymbolAddress((void**)&x_hi,   g_x_hi);
    cudaGetSymbolAddress((void**)&wq_hi,  g_wqkv_hi);
    cudaGetSymbolAddress((void**)&wo_hi,  g_wout_hi);
    cudaGetSymbolAddress((void**)&qkv_hi, g_qkv_hi);
    cudaGetSymbolAddress((void**)&a_hi,   g_att_hi);

    cudaFuncSetAttribute(attn_mma,
                         cudaFuncAttributeMaxDynamicSharedMemorySize, ATTN_SMEM);
    cudaFuncSetAttribute((const void*)gemm_mma<false, true>,
                         cudaFuncAttributeMaxDynamicSharedMemorySize, GEMM_SMEM);
    cudaFuncSetAttribute((const void*)gemm_mma<true, false>,
                         cudaFuncAttributeMaxDynamicSharedMemorySize, GEMM_SMEM);

    // 0) fp16 rounds: x; w_qkv (permuted [Q|K|V]); w_out
    {
        int n4 = ROWS * EMB / 4;
        round_f16<<<(n4 + 255) / 256, 256>>>((const float4*)x, (__half2*)x_hi, n4);
        int nperm = F3 * (EMB / 4);
        round_f16_perm<<<(nperm + 255) / 256, 256>>>((const float4*)w_qkv,
            (__half2*)wq_hi);
        n4 = EMB * EMB / 4;
        round_f16<<<(n4 + 255) / 256, 256>>>((const float4*)w_out, (__half2*)wo_hi, n4);
    }

    // 1) QKV projection (single pass, BK=64) -> permuted qkv fp16
    gemm_mma<false, true><<<dim3(F3 / 128, ROWS / 256), 256, GEMM_SMEM>>>(
        x_hi, wq_hi, nullptr, nullptr, qkv_hi, F3, EMB);

    // 2) Tensor-core causal flash attention -> att fp16
    attn_mma<<<dim3(SEQ / 128, NH, BS), 256, ATTN_SMEM>>>(qkv_hi, a_hi);

    // 3) Output projection + bias (single pass, BK=64) -> fp32 out
    gemm_mma<true, false><<<dim3(EMB / 128, ROWS / 256), 256, GEMM_SMEM>>>(
        a_hi, wo_hi, b_out, out, nullptr, EMB, EMB);
}

// round 13
// speedup vs baseline: 2.6342x; 1.0492x over previous
#include <cuda_runtime.h>
#include <cuda_fp16.h>
#include <cstdint>
#include <math.h>

// Problem constants (fixed shapes)
#define BS   2
#define SEQ  2048
#define EMB  1024
#define NH   16
#define HD   64
#define F3   3072   // 3*EMB
#define ROWS (BS * SEQ)   // 4096

// ---------------------------------------------------------------------------
// Scratch (device globals: allocation-free rule)
// qkv layout PERMUTED: cols [0,1024) = Q (h*64+d), [1024,2048) = K, [2048,3072) = V.
// ---------------------------------------------------------------------------
__device__ __half g_x_hi[ROWS * EMB];
__device__ __half g_wqkv_hi[F3 * EMB];      // permuted rows: [Q|K|V]
__device__ __half g_wout_hi[EMB * EMB];
__device__ __half g_qkv_hi[ROWS * F3];      // [Q|K|V] per row
__device__ __half g_att_hi[ROWS * EMB];

// ---------------------------------------------------------------------------
// helpers
// ---------------------------------------------------------------------------
__device__ __forceinline__ uint32_t smem_u32(const void* p) {
    uint32_t a;
    asm("{ .reg .u64 t; cvta.to.shared.u64 t, %1; cvt.u32.u64 %0, t; }" : "=r"(a) : "l"(p));
    return a;
}
__device__ __forceinline__ void ldsm_x4(uint32_t addr, uint32_t r[4]) {
    asm volatile("ldmatrix.sync.aligned.m8n8.x4.shared.b16 {%0,%1,%2,%3}, [%4];"
                 : "=r"(r[0]), "=r"(r[1]), "=r"(r[2]), "=r"(r[3]) : "r"(addr));
}
__device__ __forceinline__ void ldsm_x4_t(uint32_t addr, uint32_t r[4]) {
    asm volatile("ldmatrix.sync.aligned.m8n8.x4.trans.shared.b16 {%0,%1,%2,%3}, [%4];"
                 : "=r"(r[0]), "=r"(r[1]), "=r"(r[2]), "=r"(r[3]) : "r"(addr));
}
__device__ __forceinline__ void mma16816(float c[4], const uint32_t a[4],
                                         const uint32_t b0, const uint32_t b1) {
    asm volatile(
        "mma.sync.aligned.m16n8k16.row.col.f32.f16.f16.f32 "
        "{%0,%1,%2,%3}, {%4,%5,%6,%7}, {%8,%9}, {%0,%1,%2,%3};"
        : "+f"(c[0]), "+f"(c[1]), "+f"(c[2]), "+f"(c[3])
        : "r"(a[0]), "r"(a[1]), "r"(a[2]), "r"(a[3]), "r"(b0), "r"(b1));
}
__device__ __forceinline__ uint32_t pack_f16(float lo, float hi) {
    __half2 h = __floats2half2_rn(lo, hi);
    return *(uint32_t*)&h;
}
__device__ __forceinline__ float ex2(float x) {
    float r;
    asm("ex2.approx.ftz.f32 %0, %1;" : "=f"(r) : "f"(x));
    return r;
}
__device__ __forceinline__ void cp_async16(uint32_t dst, const void* src) {
    asm volatile("cp.async.cg.shared.global [%0], [%1], 16;" :: "r"(dst), "l"(src));
}
#define CP_COMMIT() asm volatile("cp.async.commit_group;" ::: "memory")
#define CP_WAIT1()  asm volatile("cp.async.wait_group 1;" ::: "memory")
#define CP_WAIT0()  asm volatile("cp.async.wait_group 0;" ::: "memory")

// ---------------------------------------------------------------------------
// fp16 round (float4 vectorized)
// ---------------------------------------------------------------------------
__global__ void round_f16(const float4* __restrict__ in,
                          __half2* __restrict__ hi, int n4) {
    int i = blockIdx.x * blockDim.x + threadIdx.x;
    if (i >= n4) return;
    float4 v = in[i];
    hi[2 * i]     = __half2(__float2half_rn(v.x), __float2half_rn(v.y));
    hi[2 * i + 1] = __half2(__float2half_rn(v.z), __float2half_rn(v.w));
}

// Permuting round for w_qkv: dst row r (r<1024: Q; <2048: K; else V) maps to
// src row h*192 + m*64 + d where m=r/1024, h=(r%1024)/64, d=r%64.
__global__ void round_f16_perm(const float4* __restrict__ in,
                               __half2* __restrict__ hi) {
    int idx = blockIdx.x * blockDim.x + threadIdx.x;   // over F3 * (EMB/4)
    if (idx >= F3 * (EMB / 4)) return;
    int r = idx >> 8;            // EMB/4 = 256 float4 per row
    int q = idx & 255;
    int m = r >> 10;
    int within = r & 1023;
    int hsrc = (within >> 6) * 192 + m * 64 + (within & 63);
    float4 v = in[(size_t)hsrc * 256 + q];
    hi[2 * idx]     = __half2(__float2half_rn(v.x), __float2half_rn(v.y));
    hi[2 * idx + 1] = __half2(__float2half_rn(v.z), __float2half_rn(v.w));
}

// ---------------------------------------------------------------------------
// mma.sync fp16 GEMM (single pass), cp.async double-buffered, BK=128.
// CTA tile 256x128, 8 warps, warp tile 64x64. 8 k-steps (256 MMAs) per region.
// ---------------------------------------------------------------------------
#define SA_STRIDE 136
#define ATILE_B (256 * SA_STRIDE * 2)           // 69632
#define BTILE_B (128 * SA_STRIDE * 2)           // 34816
#define STAGE_B (ATILE_B + BTILE_B)             // 104448
#define GEMM_SMEM (2 * STAGE_B)                 // 208896

template <bool HAS_BIAS, bool OUT_F16>
__global__ __launch_bounds__(256, 1)
void gemm_mma(const __half* __restrict__ A, const __half* __restrict__ B,
              const float* __restrict__ bias, float* __restrict__ C,
              __half* __restrict__ Ch, int N, int K) {
    extern __shared__ char smem[];
    const uint32_t sb = smem_u32(smem);

    const int tid  = threadIdx.x;
    const int wid  = tid >> 5;
    const int lane = tid & 31;
    const int n0 = blockIdx.x * 128;
    const int m0 = blockIdx.y * 256;
    const int wm = (wid & 3) * 64;
    const int wn = (wid >> 2) * 64;

    const int trow  = lane & 7;
    const int tquad = lane >> 3;
    const int a_row_off = (tquad & 1) * 8 + trow;
    const int a_col_off = (tquad >> 1) * 8;
    const int b_row_off = (tquad >> 1) * 8 + trow;
    const int b_col_off = (tquad & 1) * 8;

    float acc[4][8][4];
#pragma unroll
    for (int mt = 0; mt < 4; mt++)
#pragma unroll
        for (int nt = 0; nt < 8; nt++)
#pragma unroll
            for (int j = 0; j < 4; j++) acc[mt][nt][j] = 0.0f;

    // stage loader: A 256x128 (16 x16B per thread), B 128x128 (8 x16B per thread)
    auto load_stage = [&](int stage, int k0) {
        uint32_t s0 = sb + stage * STAGE_B;
#pragma unroll
        for (int i = 0; i < 16; i++) {
            int idx = tid + 256 * i;          // 0..4095
            int row = idx >> 4, q = idx & 15;
            uint32_t soff = (uint32_t)(row * SA_STRIDE + q * 8) * 2;
            cp_async16(s0 + soff, A + (size_t)(m0 + row) * K + k0 + q * 8);
        }
#pragma unroll
        for (int i = 0; i < 8; i++) {
            int idx = tid + 256 * i;          // 0..2047
            int row = idx >> 4, q = idx & 15;
            uint32_t soff = (uint32_t)(row * SA_STRIDE + q * 8) * 2;
            cp_async16(s0 + ATILE_B + soff, B + (size_t)(n0 + row) * K + k0 + q * 8);
        }
        CP_COMMIT();
    };

    const int NC = K >> 7;   // chunks of 128
    load_stage(0, 0);

    for (int c = 0; c < NC; c++) {
        const bool pref = (c + 1 < NC);
        if (pref) load_stage((c + 1) & 1, (c + 1) * 128);
        if (pref) CP_WAIT1(); else CP_WAIT0();
        __syncthreads();

        const uint32_t AT = sb + (c & 1) * STAGE_B;
        const uint32_t BT = AT + ATILE_B;

#pragma unroll
        for (int ks = 0; ks < 8; ks++) {
            const int kk = ks * 16;
            uint32_t af[4][4], bf[4][4];
#pragma unroll
            for (int mt = 0; mt < 4; mt++)
                ldsm_x4(AT + (uint32_t)((wm + mt * 16 + a_row_off) * SA_STRIDE +
                                        kk + a_col_off) * 2, af[mt]);
#pragma unroll
            for (int np = 0; np < 4; np++)
                ldsm_x4(BT + (uint32_t)((wn + np * 16 + b_row_off) * SA_STRIDE +
                                        kk + b_col_off) * 2, bf[np]);
#pragma unroll
            for (int mt = 0; mt < 4; mt++)
#pragma unroll
                for (int np = 0; np < 4; np++) {
                    mma16816(acc[mt][2 * np],     af[mt], bf[np][0], bf[np][1]);
                    mma16816(acc[mt][2 * np + 1], af[mt], bf[np][2], bf[np][3]);
                }
        }
        __syncthreads();
    }

    const int g  = lane >> 2;
    const int t2 = (lane & 3) * 2;
#pragma unroll
    for (int mt = 0; mt < 4; mt++) {
        int mrow0 = m0 + wm + mt * 16 + g;
#pragma unroll
        for (int nt = 0; nt < 8; nt++) {
            int n = n0 + wn + nt * 8 + t2;
            float b0 = 0.f, b1 = 0.f;
            if (HAS_BIAS) { b0 = bias[n]; b1 = bias[n + 1]; }
            float v00 = acc[mt][nt][0] + b0, v01 = acc[mt][nt][1] + b1;
            float v10 = acc[mt][nt][2] + b0, v11 = acc[mt][nt][3] + b1;
            if (OUT_F16) {
                *(uint32_t*)(Ch + (size_t)mrow0 * N + n)       = pack_f16(v00, v01);
                *(uint32_t*)(Ch + (size_t)(mrow0 + 8) * N + n) = pack_f16(v10, v11);
            } else {
                *(float2*)(C + (size_t)mrow0 * N + n)       = make_float2(v00, v01);
                *(float2*)(C + (size_t)(mrow0 + 8) * N + n) = make_float2(v10, v11);
            }
        }
    }
}

// ---------------------------------------------------------------------------
// Tensor-core causal flash attention, full fp16 operands, fp32 accum.
// BM=128, BN=128, HD=64, 8 warps, cp.async double-buffered.
// qkv layout: [row][ Q | K | V ], col h*64+d within each block.
// ---------------------------------------------------------------------------
#define AT_STRIDE 72
#define AT_TILE (128 * AT_STRIDE * 2)      // 18432 bytes (128 rows x 64 cols)
#define AT_STAGE (2 * AT_TILE)             // 36864: K, V
#define ATTN_SMEM (2 * AT_STAGE)           // 73728

#define SCALE2 0.1803368801111244f         // 0.125 * log2(e)

__global__ __launch_bounds__(256)
void attn_mma(const __half* __restrict__ qkv_hi,
              __half* __restrict__ att_hi) {
    extern __shared__ char smem[];
    const uint32_t sb = smem_u32(smem);

    const int tid  = threadIdx.x;
    const int wid  = tid >> 5;
    const int lane = tid & 31;
    const int it = gridDim.x - 1 - blockIdx.x;   // big tiles first
    const int h  = blockIdx.y;
    const int b  = blockIdx.z;
    const int hc = h * 64;
    const size_t rowbase = (size_t)b * SEQ;

    // ---- Stage Q (128x64 fp16) into stage-0 K-tile ----
#pragma unroll
    for (int i = 0; i < 4; i++) {
        int idx = tid + 256 * i;      // 0..1023
        int row = idx >> 3, q = idx & 7;
        uint32_t soff = (uint32_t)(row * AT_STRIDE + q * 8) * 2;
        size_t grow = rowbase + it * 128 + row;
        *(uint4*)(smem + soff) = *(const uint4*)(qkv_hi + grow * F3 + hc + q * 8);
    }
    __syncthreads();

    // Q fragments: warp w owns rows 16*(w&3) + 64*(w>>2)
    uint32_t qh[4][4];
    {
        uint32_t qoff = (uint32_t)((16 * (wid & 3) + 64 * (wid >> 2) + (lane & 15)) * AT_STRIDE +
                                   (lane >> 4) * 8) * 2;
#pragma unroll
        for (int ks = 0; ks < 4; ks++)
            ldsm_x4(sb + qoff + ks * 32, qh[ks]);
    }
    __syncthreads();   // everyone done reading Q before overwrite

    // load K,V tiles of 128 rows (jt counts 128-row tiles)
    auto load_kv = [&](int stage, int jt) {
        uint32_t sbase = sb + stage * AT_STAGE;
#pragma unroll
        for (int i = 0; i < 4; i++) {
            int idx = tid + 256 * i;      // 0..1023
            int row = idx >> 3, q = idx & 7;
            uint32_t soff = (uint32_t)(row * AT_STRIDE + q * 8) * 2;
            size_t grow = rowbase + jt * 128 + row;
            cp_async16(sbase + soff,           qkv_hi + grow * F3 + EMB + hc + q * 8);     // K
            cp_async16(sbase + AT_TILE + soff, qkv_hi + grow * F3 + 2 * EMB + hc + q * 8); // V
        }
        CP_COMMIT();
    };

    float m2[2] = {-1e30f, -1e30f}, l[2] = {0.f, 0.f};
    float o[8][4];
#pragma unroll
    for (int dt = 0; dt < 8; dt++)
#pragma unroll
        for (int j = 0; j < 4; j++) o[dt][j] = 0.0f;

    const int rbase = 128 * it + 16 * (wid & 3) + 64 * (wid >> 2);
    const int g  = lane >> 2;
    const int t2 = (lane & 3) * 2;
    const uint32_t koff = (uint32_t)(((lane >> 4) * 8 + (lane & 7)) * AT_STRIDE +
                                     ((lane >> 3) & 1) * 8) * 2;
    const uint32_t voff = (uint32_t)((lane & 15) * AT_STRIDE + (lane >> 4) * 8) * 2;

    const int jt_max = it + 1;
    load_kv(0, 0);

    for (int jt = 0; jt < jt_max; jt++) {
        const bool pref = (jt + 1 < jt_max);
        if (pref) load_kv((jt + 1) & 1, jt + 1);
        if (pref) CP_WAIT1(); else CP_WAIT0();
        __syncthreads();

        const uint32_t KB = sb + (jt & 1) * AT_STAGE;
        const uint32_t VB = KB + AT_TILE;

        // ---- S = Q K^T (16x128 per warp) ----
        float s[16][4];
#pragma unroll
        for (int nt = 0; nt < 16; nt++)
#pragma unroll
            for (int j = 0; j < 4; j++) s[nt][j] = 0.0f;

#pragma unroll
        for (int ks = 0; ks < 4; ks++) {
            uint32_t kf[8][4];
#pragma unroll
            for (int np = 0; np < 8; np++)
                ldsm_x4(KB + koff + (uint32_t)(np * 16 * AT_STRIDE + ks * 16) * 2, kf[np]);
#pragma unroll
            for (int np = 0; np < 8; np++) {
                mma16816(s[2 * np],     qh[ks], kf[np][0], kf[np][1]);
                mma16816(s[2 * np + 1], qh[ks], kf[np][2], kf[np][3]);
            }
        }

        // ---- scale (+ causal mask on diagonal tile) ----
        const bool diag = (jt == it);
#pragma unroll
        for (int nt = 0; nt < 16; nt++)
#pragma unroll
            for (int j = 0; j < 4; j++) {
                float t = s[nt][j] * SCALE2;
                if (diag) {
                    int col = jt * 128 + nt * 8 + t2 + (j & 1);
                    int row = rbase + g + 8 * (j >> 1);
                    if (col > row) t = -1e30f;
                }
                s[nt][j] = t;
            }

        // ---- online softmax ----
        float rmax[2] = {-1e30f, -1e30f};
#pragma unroll
        for (int nt = 0; nt < 16; nt++) {
            rmax[0] = fmaxf(rmax[0], fmaxf(s[nt][0], s[nt][1]));
            rmax[1] = fmaxf(rmax[1], fmaxf(s[nt][2], s[nt][3]));
        }
#pragma unroll
        for (int off = 1; off <= 2; off <<= 1) {
            rmax[0] = fmaxf(rmax[0], __shfl_xor_sync(0xffffffffu, rmax[0], off));
            rmax[1] = fmaxf(rmax[1], __shfl_xor_sync(0xffffffffu, rmax[1], off));
        }
        float alpha[2], rsum[2];
#pragma unroll
        for (int r = 0; r < 2; r++) {
            float mnew = fmaxf(m2[r], rmax[r]);
            alpha[r] = ex2(m2[r] - mnew);
            m2[r] = mnew;
            rsum[r] = 0.f;
        }
#pragma unroll
        for (int nt = 0; nt < 16; nt++) {
            s[nt][0] = ex2(s[nt][0] - m2[0]);
            s[nt][1] = ex2(s[nt][1] - m2[0]);
            s[nt][2] = ex2(s[nt][2] - m2[1]);
            s[nt][3] = ex2(s[nt][3] - m2[1]);
            rsum[0] += s[nt][0] + s[nt][1];
            rsum[1] += s[nt][2] + s[nt][3];
        }
#pragma unroll
        for (int off = 1; off <= 2; off <<= 1) {
            rsum[0] += __shfl_xor_sync(0xffffffffu, rsum[0], off);
            rsum[1] += __shfl_xor_sync(0xffffffffu, rsum[1], off);
        }
#pragma unroll
        for (int r = 0; r < 2; r++) l[r] = l[r] * alpha[r] + rsum[r];
#pragma unroll
        for (int dt = 0; dt < 8; dt++) {
            o[dt][0] *= alpha[0];
            o[dt][1] *= alpha[0];
            o[dt][2] *= alpha[1];
            o[dt][3] *= alpha[1];
        }

        // ---- pack P (single fp16): 8 k-groups of 16 cols ----
        uint32_t ph[8][4];
#pragma unroll
        for (int ks = 0; ks < 8; ks++) {
#pragma unroll
            for (int half = 0; half < 2; half++) {
                int nt = 2 * ks + half;
                ph[ks][2 * half]     = pack_f16(s[nt][0], s[nt][1]);
                ph[ks][2 * half + 1] = pack_f16(s[nt][2], s[nt][3]);
            }
        }

        // ---- O += P V : k-dim 128 (8 steps) ----
#pragma unroll
        for (int ks = 0; ks < 8; ks++) {
            uint32_t vf[4][4];
#pragma unroll
            for (int np = 0; np < 4; np++)
                ldsm_x4_t(VB + voff + (uint32_t)(ks * 16 * AT_STRIDE + np * 16) * 2, vf[np]);
#pragma unroll
            for (int np = 0; np < 4; np++) {
                mma16816(o[2 * np],     ph[ks], vf[np][0], vf[np][1]);
                mma16816(o[2 * np + 1], ph[ks], vf[np][2], vf[np][3]);
            }
        }
        __syncthreads();
    }

    // ---- epilogue: O/l -> att (fp16) ----
    float inv0 = 1.0f / l[0], inv1 = 1.0f / l[1];
#pragma unroll
    for (int dt = 0; dt < 8; dt++) {
        int col = hc + dt * 8 + t2;
        size_t i0 = (rowbase + rbase + g) * EMB + col;
        size_t i1 = (rowbase + rbase + g + 8) * EMB + col;
        *(uint32_t*)(att_hi + i0) = pack_f16(o[dt][0] * inv0, o[dt][1] * inv0);
        *(uint32_t*)(att_hi + i1) = pack_f16(o[dt][2] * inv1, o[dt][3] * inv1);
    }
}

// ---------------------------------------------------------------------------
// Launch
// ---------------------------------------------------------------------------
extern "C" void kernel_launch(void* const* d_in, const int* in_sizes, int n_in,
                              void* d_out, int out_size) {
    const float* x      = (const float*)d_in[0];
    const float* w_qkv  = (const float*)d_in[1];
    const float* w_out  = (const float*)d_in[2];
    const float* b_out  = (const float*)d_in[3];
    float* out = (float*)d_out;

    __half *x_hi, *wq_hi, *wo_hi, *qkv_hi, *a_hi;
    cudaGetSymbolAddress((void**)&x_hi,   g_x_hi);
    cudaGetSymbolAddress((void**)&wq_hi,  g_wqkv_hi);
    cudaGetSymbolAddress((void**)&wo_hi,  g_wout_hi);
    cudaGetSymbolAddress((void**)&qkv_hi, g_qkv_hi);
    cudaGetSymbolAddress((void**)&a_hi,   g_att_hi);

    cudaFuncSetAttribute(attn_mma,
                         cudaFuncAttributeMaxDynamicSharedMemorySize, ATTN_SMEM);
    cudaFuncSetAttribute((const void*)gemm_mma<false, true>,
                         cudaFuncAttributeMaxDynamicSharedMemorySize, GEMM_SMEM);
    cudaFuncSetAttribute((const void*)gemm_mma<true, false>,
                         cudaFuncAttributeMaxDynamicSharedMemorySize, GEMM_SMEM);

    // 0) fp16 rounds: x; w_qkv (permuted [Q|K|V]); w_out
    {
        int n4 = ROWS * EMB / 4;
        round_f16<<<(n4 + 255) / 256, 256>>>((const float4*)x, (__half2*)x_hi, n4);
        int nperm = F3 * (EMB / 4);
        round_f16_perm<<<(nperm + 255) / 256, 256>>>((const float4*)w_qkv,
            (__half2*)wq_hi);
        n4 = EMB * EMB / 4;
        round_f16<<<(n4 + 255) / 256, 256>>>((const float4*)w_out, (__half2*)wo_hi, n4);
    }

    // 1) QKV projection (single pass, BK=128) -> permuted qkv fp16
    gemm_mma<false, true><<<dim3(F3 / 128, ROWS / 256), 256, GEMM_SMEM>>>(
        x_hi, wq_hi, nullptr, nullptr, qkv_hi, F3, EMB);

    // 2) Tensor-core causal flash attention (BN=128) -> att fp16
    attn_mma<<<dim3(SEQ / 128, NH, BS), 256, ATTN_SMEM>>>(qkv_hi, a_hi);

    // 3) Output projection + bias (single pass, BK=128) -> fp32 out
    gemm_mma<true, false><<<dim3(EMB / 128, ROWS / 256), 256, GEMM_SMEM>>>(
        a_hi, wo_hi, b_out, out, nullptr, EMB, EMB);
}

// round 14
// speedup vs baseline: 2.7095x; 1.0286x over previous
#include <cuda_runtime.h>
#include <cuda_fp16.h>
#include <cstdint>
#include <math.h>

// Problem constants (fixed shapes)
#define BS   2
#define SEQ  2048
#define EMB  1024
#define NH   16
#define HD   64
#define F3   3072   // 3*EMB
#define ROWS (BS * SEQ)   // 4096

// ---------------------------------------------------------------------------
// Scratch (device globals: allocation-free rule)
// qkv layout PERMUTED: cols [0,1024) = Q (h*64+d), [1024,2048) = K, [2048,3072) = V.
// ---------------------------------------------------------------------------
__device__ __half g_x_hi[ROWS * EMB];
__device__ __half g_wqkv_hi[F3 * EMB];      // permuted rows: [Q|K|V]
__device__ __half g_wout_hi[EMB * EMB];
__device__ __half g_qkv_hi[ROWS * F3];      // [Q|K|V] per row
__device__ __half g_att_hi[ROWS * EMB];

// ---------------------------------------------------------------------------
// helpers
// ---------------------------------------------------------------------------
__device__ __forceinline__ uint32_t smem_u32(const void* p) {
    uint32_t a;
    asm("{ .reg .u64 t; cvta.to.shared.u64 t, %1; cvt.u32.u64 %0, t; }" : "=r"(a) : "l"(p));
    return a;
}
__device__ __forceinline__ void ldsm_x4(uint32_t addr, uint32_t r[4]) {
    asm volatile("ldmatrix.sync.aligned.m8n8.x4.shared.b16 {%0,%1,%2,%3}, [%4];"
                 : "=r"(r[0]), "=r"(r[1]), "=r"(r[2]), "=r"(r[3]) : "r"(addr));
}
__device__ __forceinline__ void ldsm_x4_t(uint32_t addr, uint32_t r[4]) {
    asm volatile("ldmatrix.sync.aligned.m8n8.x4.trans.shared.b16 {%0,%1,%2,%3}, [%4];"
                 : "=r"(r[0]), "=r"(r[1]), "=r"(r[2]), "=r"(r[3]) : "r"(addr));
}
__device__ __forceinline__ void mma16816(float c[4], const uint32_t a[4],
                                         const uint32_t b0, const uint32_t b1) {
    asm volatile(
        "mma.sync.aligned.m16n8k16.row.col.f32.f16.f16.f32 "
        "{%0,%1,%2,%3}, {%4,%5,%6,%7}, {%8,%9}, {%0,%1,%2,%3};"
        : "+f"(c[0]), "+f"(c[1]), "+f"(c[2]), "+f"(c[3])
        : "r"(a[0]), "r"(a[1]), "r"(a[2]), "r"(a[3]), "r"(b0), "r"(b1));
}
__device__ __forceinline__ uint32_t pack_f16(float lo, float hi) {
    __half2 h = __floats2half2_rn(lo, hi);
    return *(uint32_t*)&h;
}
__device__ __forceinline__ float ex2(float x) {
    float r;
    asm("ex2.approx.ftz.f32 %0, %1;" : "=f"(r) : "f"(x));
    return r;
}
__device__ __forceinline__ void cp_async16(uint32_t dst, const void* src) {
    asm volatile("cp.async.cg.shared.global [%0], [%1], 16;" :: "r"(dst), "l"(src));
}
#define CP_COMMIT() asm volatile("cp.async.commit_group;" ::: "memory")
#define CP_WAIT0()  asm volatile("cp.async.wait_group 0;" ::: "memory")

// ---------------------------------------------------------------------------
// Merged fp16 round: x (identity), w_qkv (permuted [Q|K|V]), w_out (identity)
// ---------------------------------------------------------------------------
#define N4_X   (ROWS * EMB / 4)      // 1048576
#define N4_WQ  (F3 * EMB / 4)        // 786432
#define N4_WO  (EMB * EMB / 4)       // 262144

__global__ void round_all(const float4* __restrict__ x,
                          const float4* __restrict__ wqkv,
                          const float4* __restrict__ wout,
                          __half2* __restrict__ x_hi,
                          __half2* __restrict__ wq_hi,
                          __half2* __restrict__ wo_hi) {
    int i = blockIdx.x * blockDim.x + threadIdx.x;
    float4 v;
    __half2* dst;
    if (i < N4_X) {
        v = x[i];
        dst = x_hi + 2 * i;
    } else if (i < N4_X + N4_WQ) {
        int idx = i - N4_X;
        int r = idx >> 8;            // EMB/4 = 256 float4 per row
        int q = idx & 255;
        int m = r >> 10;
        int within = r & 1023;
        int hsrc = (within >> 6) * 192 + m * 64 + (within & 63);
        v = wqkv[(size_t)hsrc * 256 + q];
        dst = wq_hi + 2 * idx;
    } else if (i < N4_X + N4_WQ + N4_WO) {
        int idx = i - N4_X - N4_WQ;
        v = wout[idx];
        dst = wo_hi + 2 * idx;
    } else {
        return;
    }
    dst[0] = __half2(__float2half_rn(v.x), __float2half_rn(v.y));
    dst[1] = __half2(__float2half_rn(v.z), __float2half_rn(v.w));
}

// ---------------------------------------------------------------------------
// mma.sync fp16 GEMM (single pass), cp.async double-buffered, BK=128.
// CTA tile 256x128, 8 warps, warp tile 64x64. ONE sync per chunk.
// ---------------------------------------------------------------------------
#define SA_STRIDE 136
#define ATILE_B (256 * SA_STRIDE * 2)           // 69632
#define BTILE_B (128 * SA_STRIDE * 2)           // 34816
#define STAGE_B (ATILE_B + BTILE_B)             // 104448
#define GEMM_SMEM (2 * STAGE_B)                 // 208896

template <bool HAS_BIAS, bool OUT_F16>
__global__ __launch_bounds__(256, 1)
void gemm_mma(const __half* __restrict__ A, const __half* __restrict__ B,
              const float* __restrict__ bias, float* __restrict__ C,
              __half* __restrict__ Ch, int N, int K) {
    extern __shared__ char smem[];
    const uint32_t sb = smem_u32(smem);

    const int tid  = threadIdx.x;
    const int wid  = tid >> 5;
    const int lane = tid & 31;
    const int n0 = blockIdx.x * 128;
    const int m0 = blockIdx.y * 256;
    const int wm = (wid & 3) * 64;
    const int wn = (wid >> 2) * 64;

    const int trow  = lane & 7;
    const int tquad = lane >> 3;
    const int a_row_off = (tquad & 1) * 8 + trow;
    const int a_col_off = (tquad >> 1) * 8;
    const int b_row_off = (tquad >> 1) * 8 + trow;
    const int b_col_off = (tquad & 1) * 8;

    float acc[4][8][4];
#pragma unroll
    for (int mt = 0; mt < 4; mt++)
#pragma unroll
        for (int nt = 0; nt < 8; nt++)
#pragma unroll
            for (int j = 0; j < 4; j++) acc[mt][nt][j] = 0.0f;

    // stage loader: A 256x128 (16 x16B per thread), B 128x128 (8 x16B per thread)
    auto load_stage = [&](int stage, int k0) {
        uint32_t s0 = sb + stage * STAGE_B;
#pragma unroll
        for (int i = 0; i < 16; i++) {
            int idx = tid + 256 * i;          // 0..4095
            int row = idx >> 4, q = idx & 15;
            uint32_t soff = (uint32_t)(row * SA_STRIDE + q * 8) * 2;
            cp_async16(s0 + soff, A + (size_t)(m0 + row) * K + k0 + q * 8);
        }
#pragma unroll
        for (int i = 0; i < 8; i++) {
            int idx = tid + 256 * i;          // 0..2047
            int row = idx >> 4, q = idx & 15;
            uint32_t soff = (uint32_t)(row * SA_STRIDE + q * 8) * 2;
            cp_async16(s0 + ATILE_B + soff, B + (size_t)(n0 + row) * K + k0 + q * 8);
        }
        CP_COMMIT();
    };

    const int NC = K >> 7;   // chunks of 128
    load_stage(0, 0);

    for (int c = 0; c < NC; c++) {
        CP_WAIT0();          // stage c landed (was issued one iter earlier)
        __syncthreads();     // releases stage c AND guards overwrite of stage c-1
        if (c + 1 < NC) load_stage((c + 1) & 1, (c + 1) * 128);

        const uint32_t AT = sb + (c & 1) * STAGE_B;
        const uint32_t BT = AT + ATILE_B;

#pragma unroll
        for (int ks = 0; ks < 8; ks++) {
            const int kk = ks * 16;
            uint32_t af[4][4], bf[4][4];
#pragma unroll
            for (int mt = 0; mt < 4; mt++)
                ldsm_x4(AT + (uint32_t)((wm + mt * 16 + a_row_off) * SA_STRIDE +
                                        kk + a_col_off) * 2, af[mt]);
#pragma unroll
            for (int np = 0; np < 4; np++)
                ldsm_x4(BT + (uint32_t)((wn + np * 16 + b_row_off) * SA_STRIDE +
                                        kk + b_col_off) * 2, bf[np]);
#pragma unroll
            for (int mt = 0; mt < 4; mt++)
#pragma unroll
                for (int np = 0; np < 4; np++) {
                    mma16816(acc[mt][2 * np],     af[mt], bf[np][0], bf[np][1]);
                    mma16816(acc[mt][2 * np + 1], af[mt], bf[np][2], bf[np][3]);
                }
        }
    }

    const int g  = lane >> 2;
    const int t2 = (lane & 3) * 2;
#pragma unroll
    for (int mt = 0; mt < 4; mt++) {
        int mrow0 = m0 + wm + mt * 16 + g;
#pragma unroll
        for (int nt = 0; nt < 8; nt++) {
            int n = n0 + wn + nt * 8 + t2;
            float b0 = 0.f, b1 = 0.f;
            if (HAS_BIAS) { b0 = bias[n]; b1 = bias[n + 1]; }
            float v00 = acc[mt][nt][0] + b0, v01 = acc[mt][nt][1] + b1;
            float v10 = acc[mt][nt][2] + b0, v11 = acc[mt][nt][3] + b1;
            if (OUT_F16) {
                *(uint32_t*)(Ch + (size_t)mrow0 * N + n)       = pack_f16(v00, v01);
                *(uint32_t*)(Ch + (size_t)(mrow0 + 8) * N + n) = pack_f16(v10, v11);
            } else {
                *(float2*)(C + (size_t)mrow0 * N + n)       = make_float2(v00, v01);
                *(float2*)(C + (size_t)(mrow0 + 8) * N + n) = make_float2(v10, v11);
            }
        }
    }
}

// ---------------------------------------------------------------------------
// Tensor-core causal flash attention, full fp16 operands, fp32 accum.
// BM=128, BN=128, HD=64, 8 warps, cp.async double-buffered, ONE sync per iter.
// qkv layout: [row][ Q | K | V ], col h*64+d within each block.
// ---------------------------------------------------------------------------
#define AT_STRIDE 72
#define AT_TILE (128 * AT_STRIDE * 2)      // 18432 bytes (128 rows x 64 cols)
#define AT_STAGE (2 * AT_TILE)             // 36864: K, V
#define ATTN_SMEM (2 * AT_STAGE)           // 73728

#define SCALE2 0.1803368801111244f         // 0.125 * log2(e)

__global__ __launch_bounds__(256)
void attn_mma(const __half* __restrict__ qkv_hi,
              __half* __restrict__ att_hi) {
    extern __shared__ char smem[];
    const uint32_t sb = smem_u32(smem);

    const int tid  = threadIdx.x;
    const int wid  = tid >> 5;
    const int lane = tid & 31;
    const int it = gridDim.x - 1 - blockIdx.x;   // big tiles first
    const int h  = blockIdx.y;
    const int b  = blockIdx.z;
    const int hc = h * 64;
    const size_t rowbase = (size_t)b * SEQ;

    // ---- Stage Q (128x64 fp16) into stage-0 K-tile ----
#pragma unroll
    for (int i = 0; i < 4; i++) {
        int idx = tid + 256 * i;      // 0..1023
        int row = idx >> 3, q = idx & 7;
        uint32_t soff = (uint32_t)(row * AT_STRIDE + q * 8) * 2;
        size_t grow = rowbase + it * 128 + row;
        *(uint4*)(smem + soff) = *(const uint4*)(qkv_hi + grow * F3 + hc + q * 8);
    }
    __syncthreads();

    // Q fragments: warp w owns rows 16*(w&3) + 64*(w>>2)
    uint32_t qh[4][4];
    {
        uint32_t qoff = (uint32_t)((16 * (wid & 3) + 64 * (wid >> 2) + (lane & 15)) * AT_STRIDE +
                                   (lane >> 4) * 8) * 2;
#pragma unroll
        for (int ks = 0; ks < 4; ks++)
            ldsm_x4(sb + qoff + ks * 32, qh[ks]);
    }
    __syncthreads();   // everyone done reading Q before load_kv(0) overwrites

    // load K,V tiles of 128 rows (jt counts 128-row tiles)
    auto load_kv = [&](int stage, int jt) {
        uint32_t sbase = sb + stage * AT_STAGE;
#pragma unroll
        for (int i = 0; i < 4; i++) {
            int idx = tid + 256 * i;      // 0..1023
            int row = idx >> 3, q = idx & 7;
            uint32_t soff = (uint32_t)(row * AT_STRIDE + q * 8) * 2;
            size_t grow = rowbase + jt * 128 + row;
            cp_async16(sbase + soff,           qkv_hi + grow * F3 + EMB + hc + q * 8);     // K
            cp_async16(sbase + AT_TILE + soff, qkv_hi + grow * F3 + 2 * EMB + hc + q * 8); // V
        }
        CP_COMMIT();
    };

    float m2[2] = {-1e30f, -1e30f}, l[2] = {0.f, 0.f};
    float o[8][4];
#pragma unroll
    for (int dt = 0; dt < 8; dt++)
#pragma unroll
        for (int j = 0; j < 4; j++) o[dt][j] = 0.0f;

    const int rbase = 128 * it + 16 * (wid & 3) + 64 * (wid >> 2);
    const int g  = lane >> 2;
    const int t2 = (lane & 3) * 2;
    const uint32_t koff = (uint32_t)(((lane >> 4) * 8 + (lane & 7)) * AT_STRIDE +
                                     ((lane >> 3) & 1) * 8) * 2;
    const uint32_t voff = (uint32_t)((lane & 15) * AT_STRIDE + (lane >> 4) * 8) * 2;

    const int jt_max = it + 1;
    load_kv(0, 0);

    for (int jt = 0; jt < jt_max; jt++) {
        CP_WAIT0();          // stage jt landed
        __syncthreads();     // releases stage jt AND guards overwrite of stage jt-1
        if (jt + 1 < jt_max) load_kv((jt + 1) & 1, jt + 1);

        const uint32_t KB = sb + (jt & 1) * AT_STAGE;
        const uint32_t VB = KB + AT_TILE;

        // ---- S = Q K^T (16x128 per warp) ----
        float s[16][4];
#pragma unroll
        for (int nt = 0; nt < 16; nt++)
#pragma unroll
            for (int j = 0; j < 4; j++) s[nt][j] = 0.0f;

#pragma unroll
        for (int ks = 0; ks < 4; ks++) {
            uint32_t kf[8][4];
#pragma unroll
            for (int np = 0; np < 8; np++)
                ldsm_x4(KB + koff + (uint32_t)(np * 16 * AT_STRIDE + ks * 16) * 2, kf[np]);
#pragma unroll
            for (int np = 0; np < 8; np++) {
                mma16816(s[2 * np],     qh[ks], kf[np][0], kf[np][1]);
                mma16816(s[2 * np + 1], qh[ks], kf[np][2], kf[np][3]);
            }
        }

        // ---- scale (+ causal mask on diagonal tile) ----
        const bool diag = (jt == it);
#pragma unroll
        for (int nt = 0; nt < 16; nt++)
#pragma unroll
            for (int j = 0; j < 4; j++) {
                float t = s[nt][j] * SCALE2;
                if (diag) {
                    int col = jt * 128 + nt * 8 + t2 + (j & 1);
                    int row = rbase + g + 8 * (j >> 1);
                    if (col > row) t = -1e30f;
                }
                s[nt][j] = t;
            }

        // ---- online softmax ----
        float rmax[2] = {-1e30f, -1e30f};
#pragma unroll
        for (int nt = 0; nt < 16; nt++) {
            rmax[0] = fmaxf(rmax[0], fmaxf(s[nt][0], s[nt][1]));
            rmax[1] = fmaxf(rmax[1], fmaxf(s[nt][2], s[nt][3]));
        }
#pragma unroll
        for (int off = 1; off <= 2; off <<= 1) {
            rmax[0] = fmaxf(rmax[0], __shfl_xor_sync(0xffffffffu, rmax[0], off));
            rmax[1] = fmaxf(rmax[1], __shfl_xor_sync(0xffffffffu, rmax[1], off));
        }
        float alpha[2], rsum[2];
#pragma unroll
        for (int r = 0; r < 2; r++) {
            float mnew = fmaxf(m2[r], rmax[r]);
            alpha[r] = ex2(m2[r] - mnew);
            m2[r] = mnew;
            rsum[r] = 0.f;
        }
#pragma unroll
        for (int nt = 0; nt < 16; nt++) {
            s[nt][0] = ex2(s[nt][0] - m2[0]);
            s[nt][1] = ex2(s[nt][1] - m2[0]);
            s[nt][2] = ex2(s[nt][2] - m2[1]);
            s[nt][3] = ex2(s[nt][3] - m2[1]);
            rsum[0] += s[nt][0] + s[nt][1];
            rsum[1] += s[nt][2] + s[nt][3];
        }
#pragma unroll
        for (int off = 1; off <= 2; off <<= 1) {
            rsum[0] += __shfl_xor_sync(0xffffffffu, rsum[0], off);
            rsum[1] += __shfl_xor_sync(0xffffffffu, rsum[1], off);
        }
#pragma unroll
        for (int r = 0; r < 2; r++) l[r] = l[r] * alpha[r] + rsum[r];
#pragma unroll
        for (int dt = 0; dt < 8; dt++) {
            o[dt][0] *= alpha[0];
            o[dt][1] *= alpha[0];
            o[dt][2] *= alpha[1];
            o[dt][3] *= alpha[1];
        }

        // ---- pack P (single fp16): 8 k-groups of 16 cols ----
        uint32_t ph[8][4];
#pragma unroll
        for (int ks = 0; ks < 8; ks++) {
#pragma unroll
            for (int half = 0; half < 2; half++) {
                int nt = 2 * ks + half;
                ph[ks][2 * half]     = pack_f16(s[nt][0], s[nt][1]);
                ph[ks][2 * half + 1] = pack_f16(s[nt][2], s[nt][3]);
            }
        }

        // ---- O += P V : k-dim 128 (8 steps) ----
#pragma unroll
        for (int ks = 0; ks < 8; ks++) {
            uint32_t vf[4][4];
#pragma unroll
            for (int np = 0; np < 4; np++)
                ldsm_x4_t(VB + voff + (uint32_t)(ks * 16 * AT_STRIDE + np * 16) * 2, vf[np]);
#pragma unroll
            for (int np = 0; np < 4; np++) {
                mma16816(o[2 * np],     ph[ks], vf[np][0], vf[np][1]);
                mma16816(o[2 * np + 1], ph[ks], vf[np][2], vf[np][3]);
            }
        }
    }

    // ---- epilogue: O/l -> att (fp16) ----
    float inv0 = 1.0f / l[0], inv1 = 1.0f / l[1];
#pragma unroll
    for (int dt = 0; dt < 8; dt++) {
        int col = hc + dt * 8 + t2;
        size_t i0 = (rowbase + rbase + g) * EMB + col;
        size_t i1 = (rowbase + rbase + g + 8) * EMB + col;
        *(uint32_t*)(att_hi + i0) = pack_f16(o[dt][0] * inv0, o[dt][1] * inv0);
        *(uint32_t*)(att_hi + i1) = pack_f16(o[dt][2] * inv1, o[dt][3] * inv1);
    }
}

// ---------------------------------------------------------------------------
// Launch
// ---------------------------------------------------------------------------
extern "C" void kernel_launch(void* const* d_in, const int* in_sizes, int n_in,
                              void* d_out, int out_size) {
    const float* x      = (const float*)d_in[0];
    const float* w_qkv  = (const float*)d_in[1];
    const float* w_out  = (const float*)d_in[2];
    const float* b_out  = (const float*)d_in[3];
    float* out = (float*)d_out;

    __half *x_hi, *wq_hi, *wo_hi, *qkv_hi, *a_hi;
    cudaGetSymbolAddress((void**)&x_hi,   g_x_hi);
    cudaGetSymbolAddress((void**)&wq_hi,  g_wqkv_hi);
    cudaGetSymbolAddress((void**)&wo_hi,  g_wout_hi);
    cudaGetSymbolAddress((void**)&qkv_hi, g_qkv_hi);
    cudaGetSymbolAddress((void**)&a_hi,   g_att_hi);

    cudaFuncSetAttribute(attn_mma,
                         cudaFuncAttributeMaxDynamicSharedMemorySize, ATTN_SMEM);
    cudaFuncSetAttribute((const void*)gemm_mma<false, true>,
                         cudaFuncAttributeMaxDynamicSharedMemorySize, GEMM_SMEM);
    cudaFuncSetAttribute((const void*)gemm_mma<true, false>,
                         cudaFuncAttributeMaxDynamicSharedMemorySize, GEMM_SMEM);

    // 0) merged fp16 rounds: x; w_qkv (permuted [Q|K|V]); w_out — ONE launch
    {
        int total = N4_X + N4_WQ + N4_WO;
        round_all<<<(total + 255) / 256, 256>>>(
            (const float4*)x, (const float4*)w_qkv, (const float4*)w_out,
            (__half2*)x_hi, (__half2*)wq_hi, (__half2*)wo_hi);
    }

    // 1) QKV projection (single pass, BK=128) -> permuted qkv fp16
    gemm_mma<false, true><<<dim3(F3 / 128, ROWS / 256), 256, GEMM_SMEM>>>(
        x_hi, wq_hi, nullptr, nullptr, qkv_hi, F3, EMB);

    // 2) Tensor-core causal flash attention (BN=128) -> att fp16
    attn_mma<<<dim3(SEQ / 128, NH, BS), 256, ATTN_SMEM>>>(qkv_hi, a_hi);

    // 3) Output projection + bias (single pass, BK=128) -> fp32 out
    gemm_mma<true, false><<<dim3(EMB / 128, ROWS / 256), 256, GEMM_SMEM>>>(
        a_hi, wo_hi, b_out, out, nullptr, EMB, EMB);
}

// round 15
// speedup vs baseline: 2.8257x; 1.0429x over previous
#include <cuda_runtime.h>
#include <cuda_fp16.h>
#include <cstdint>
#include <math.h>

// Problem constants (fixed shapes)
#define BS   2
#define SEQ  2048
#define EMB  1024
#define NH   16
#define HD   64
#define F3   3072   // 3*EMB
#define ROWS (BS * SEQ)   // 4096

// ---------------------------------------------------------------------------
// Scratch (device globals: allocation-free rule)
// qkv layout PERMUTED: cols [0,1024) = Q (h*64+d), [1024,2048) = K, [2048,3072) = V.
// ---------------------------------------------------------------------------
__device__ __half g_x_hi[ROWS * EMB];
__device__ __half g_wqkv_hi[F3 * EMB];      // permuted rows: [Q|K|V]
__device__ __half g_wout_hi[EMB * EMB];
__device__ __half g_qkv_hi[ROWS * F3];      // [Q|K|V] per row
__device__ __half g_att_hi[ROWS * EMB];

// ---------------------------------------------------------------------------
// helpers
// ---------------------------------------------------------------------------
__device__ __forceinline__ uint32_t smem_u32(const void* p) {
    uint32_t a;
    asm("{ .reg .u64 t; cvta.to.shared.u64 t, %1; cvt.u32.u64 %0, t; }" : "=r"(a) : "l"(p));
    return a;
}
__device__ __forceinline__ void ldsm_x4(uint32_t addr, uint32_t r[4]) {
    asm volatile("ldmatrix.sync.aligned.m8n8.x4.shared.b16 {%0,%1,%2,%3}, [%4];"
                 : "=r"(r[0]), "=r"(r[1]), "=r"(r[2]), "=r"(r[3]) : "r"(addr));
}
__device__ __forceinline__ void ldsm_x4_t(uint32_t addr, uint32_t r[4]) {
    asm volatile("ldmatrix.sync.aligned.m8n8.x4.trans.shared.b16 {%0,%1,%2,%3}, [%4];"
                 : "=r"(r[0]), "=r"(r[1]), "=r"(r[2]), "=r"(r[3]) : "r"(addr));
}
__device__ __forceinline__ void mma16816(float c[4], const uint32_t a[4],
                                         const uint32_t b0, const uint32_t b1) {
    asm volatile(
        "mma.sync.aligned.m16n8k16.row.col.f32.f16.f16.f32 "
        "{%0,%1,%2,%3}, {%4,%5,%6,%7}, {%8,%9}, {%0,%1,%2,%3};"
        : "+f"(c[0]), "+f"(c[1]), "+f"(c[2]), "+f"(c[3])
        : "r"(a[0]), "r"(a[1]), "r"(a[2]), "r"(a[3]), "r"(b0), "r"(b1));
}
__device__ __forceinline__ uint32_t pack_f16(float lo, float hi) {
    __half2 h = __floats2half2_rn(lo, hi);
    return *(uint32_t*)&h;
}
__device__ __forceinline__ float ex2(float x) {
    float r;
    asm("ex2.approx.ftz.f32 %0, %1;" : "=f"(r) : "f"(x));
    return r;
}
__device__ __forceinline__ void cp_async16(uint32_t dst, const void* src) {
    asm volatile("cp.async.cg.shared.global [%0], [%1], 16;" :: "r"(dst), "l"(src));
}
#define CP_COMMIT() asm volatile("cp.async.commit_group;" ::: "memory")
#define CP_WAIT0()  asm volatile("cp.async.wait_group 0;" ::: "memory")

// ---------------------------------------------------------------------------
// Merged fp16 round: x (identity), w_qkv (permuted [Q|K|V]), w_out (identity)
// ---------------------------------------------------------------------------
#define N4_X   (ROWS * EMB / 4)      // 1048576
#define N4_WQ  (F3 * EMB / 4)        // 786432
#define N4_WO  (EMB * EMB / 4)       // 262144

__global__ void round_all(const float4* __restrict__ x,
                          const float4* __restrict__ wqkv,
                          const float4* __restrict__ wout,
                          __half2* __restrict__ x_hi,
                          __half2* __restrict__ wq_hi,
                          __half2* __restrict__ wo_hi) {
    int i = blockIdx.x * blockDim.x + threadIdx.x;
    float4 v;
    __half2* dst;
    if (i < N4_X) {
        v = x[i];
        dst = x_hi + 2 * i;
    } else if (i < N4_X + N4_WQ) {
        int idx = i - N4_X;
        int r = idx >> 8;            // EMB/4 = 256 float4 per row
        int q = idx & 255;
        int m = r >> 10;
        int within = r & 1023;
        int hsrc = (within >> 6) * 192 + m * 64 + (within & 63);
        v = wqkv[(size_t)hsrc * 256 + q];
        dst = wq_hi + 2 * idx;
    } else if (i < N4_X + N4_WQ + N4_WO) {
        int idx = i - N4_X - N4_WQ;
        v = wout[idx];
        dst = wo_hi + 2 * idx;
    } else {
        return;
    }
    dst[0] = __half2(__float2half_rn(v.x), __float2half_rn(v.y));
    dst[1] = __half2(__float2half_rn(v.z), __float2half_rn(v.w));
}

// ---------------------------------------------------------------------------
// GEMM1: CTA 256x128, 8 warps, BK=128, 1 CTA/SM. (At HMMA ceiling; unchanged.)
// ---------------------------------------------------------------------------
#define SA_STRIDE 136
#define ATILE_B (256 * SA_STRIDE * 2)           // 69632
#define BTILE_B (128 * SA_STRIDE * 2)           // 34816
#define STAGE_B (ATILE_B + BTILE_B)             // 104448
#define GEMM_SMEM (2 * STAGE_B)                 // 208896

__global__ __launch_bounds__(256, 1)
void gemm_mma1(const __half* __restrict__ A, const __half* __restrict__ B,
               __half* __restrict__ Ch, int N, int K) {
    extern __shared__ char smem[];
    const uint32_t sb = smem_u32(smem);

    const int tid  = threadIdx.x;
    const int wid  = tid >> 5;
    const int lane = tid & 31;
    const int n0 = blockIdx.x * 128;
    const int m0 = blockIdx.y * 256;
    const int wm = (wid & 3) * 64;
    const int wn = (wid >> 2) * 64;

    const int trow  = lane & 7;
    const int tquad = lane >> 3;
    const int a_row_off = (tquad & 1) * 8 + trow;
    const int a_col_off = (tquad >> 1) * 8;
    const int b_row_off = (tquad >> 1) * 8 + trow;
    const int b_col_off = (tquad & 1) * 8;

    float acc[4][8][4];
#pragma unroll
    for (int mt = 0; mt < 4; mt++)
#pragma unroll
        for (int nt = 0; nt < 8; nt++)
#pragma unroll
            for (int j = 0; j < 4; j++) acc[mt][nt][j] = 0.0f;

    auto load_stage = [&](int stage, int k0) {
        uint32_t s0 = sb + stage * STAGE_B;
#pragma unroll
        for (int i = 0; i < 16; i++) {
            int idx = tid + 256 * i;
            int row = idx >> 4, q = idx & 15;
            uint32_t soff = (uint32_t)(row * SA_STRIDE + q * 8) * 2;
            cp_async16(s0 + soff, A + (size_t)(m0 + row) * K + k0 + q * 8);
        }
#pragma unroll
        for (int i = 0; i < 8; i++) {
            int idx = tid + 256 * i;
            int row = idx >> 4, q = idx & 15;
            uint32_t soff = (uint32_t)(row * SA_STRIDE + q * 8) * 2;
            cp_async16(s0 + ATILE_B + soff, B + (size_t)(n0 + row) * K + k0 + q * 8);
        }
        CP_COMMIT();
    };

    const int NC = K >> 7;
    load_stage(0, 0);

    for (int c = 0; c < NC; c++) {
        CP_WAIT0();
        __syncthreads();
        if (c + 1 < NC) load_stage((c + 1) & 1, (c + 1) * 128);

        const uint32_t AT = sb + (c & 1) * STAGE_B;
        const uint32_t BT = AT + ATILE_B;

#pragma unroll
        for (int ks = 0; ks < 8; ks++) {
            const int kk = ks * 16;
            uint32_t af[4][4], bf[4][4];
#pragma unroll
            for (int mt = 0; mt < 4; mt++)
                ldsm_x4(AT + (uint32_t)((wm + mt * 16 + a_row_off) * SA_STRIDE +
                                        kk + a_col_off) * 2, af[mt]);
#pragma unroll
            for (int np = 0; np < 4; np++)
                ldsm_x4(BT + (uint32_t)((wn + np * 16 + b_row_off) * SA_STRIDE +
                                        kk + b_col_off) * 2, bf[np]);
#pragma unroll
            for (int mt = 0; mt < 4; mt++)
#pragma unroll
                for (int np = 0; np < 4; np++) {
                    mma16816(acc[mt][2 * np],     af[mt], bf[np][0], bf[np][1]);
                    mma16816(acc[mt][2 * np + 1], af[mt], bf[np][2], bf[np][3]);
                }
        }
    }

    const int g  = lane >> 2;
    const int t2 = (lane & 3) * 2;
#pragma unroll
    for (int mt = 0; mt < 4; mt++) {
        int mrow0 = m0 + wm + mt * 16 + g;
#pragma unroll
        for (int nt = 0; nt < 8; nt++) {
            int n = n0 + wn + nt * 8 + t2;
            *(uint32_t*)(Ch + (size_t)mrow0 * N + n)       = pack_f16(acc[mt][nt][0], acc[mt][nt][1]);
            *(uint32_t*)(Ch + (size_t)(mrow0 + 8) * N + n) = pack_f16(acc[mt][nt][2], acc[mt][nt][3]);
        }
    }
}

// ---------------------------------------------------------------------------
// GEMM2: CTA 128x128, 4 warps (warp tile 64x64), BK=64, 2 CTAs/SM. fp32 out + bias.
// ---------------------------------------------------------------------------
#define S2_STRIDE 72
#define TILE2_B (128 * S2_STRIDE * 2)           // 18432
#define STAGE2_B (2 * TILE2_B)                  // 36864
#define GEMM2_SMEM (2 * STAGE2_B)               // 73728

__global__ __launch_bounds__(128, 2)
void gemm_mma2(const __half* __restrict__ A, const __half* __restrict__ B,
               const float* __restrict__ bias, float* __restrict__ C,
               int N, int K) {
    extern __shared__ char smem[];
    const uint32_t sb = smem_u32(smem);

    const int tid  = threadIdx.x;
    const int wid  = tid >> 5;      // 0..3
    const int lane = tid & 31;
    const int n0 = blockIdx.x * 128;
    const int m0 = blockIdx.y * 128;
    const int wm = (wid & 1) * 64;
    const int wn = (wid >> 1) * 64;

    const int trow  = lane & 7;
    const int tquad = lane >> 3;
    const int a_row_off = (tquad & 1) * 8 + trow;
    const int a_col_off = (tquad >> 1) * 8;
    const int b_row_off = (tquad >> 1) * 8 + trow;
    const int b_col_off = (tquad & 1) * 8;

    float acc[4][8][4];
#pragma unroll
    for (int mt = 0; mt < 4; mt++)
#pragma unroll
        for (int nt = 0; nt < 8; nt++)
#pragma unroll
            for (int j = 0; j < 4; j++) acc[mt][nt][j] = 0.0f;

    // stage: A 128x64 + B 128x64, each 1024 x16B chunks / 128 threads = 8 each
    auto load_stage = [&](int stage, int k0) {
        uint32_t s0 = sb + stage * STAGE2_B;
#pragma unroll
        for (int i = 0; i < 8; i++) {
            int idx = tid + 128 * i;          // 0..1023
            int row = idx >> 3, q = idx & 7;
            uint32_t soff = (uint32_t)(row * S2_STRIDE + q * 8) * 2;
            cp_async16(s0 + soff,           A + (size_t)(m0 + row) * K + k0 + q * 8);
            cp_async16(s0 + TILE2_B + soff, B + (size_t)(n0 + row) * K + k0 + q * 8);
        }
        CP_COMMIT();
    };

    const int NC = K >> 6;
    load_stage(0, 0);

    for (int c = 0; c < NC; c++) {
        CP_WAIT0();
        __syncthreads();
        if (c + 1 < NC) load_stage((c + 1) & 1, (c + 1) * 64);

        const uint32_t AT = sb + (c & 1) * STAGE2_B;
        const uint32_t BT = AT + TILE2_B;

#pragma unroll
        for (int ks = 0; ks < 4; ks++) {
            const int kk = ks * 16;
            uint32_t af[4][4], bf[4][4];
#pragma unroll
            for (int mt = 0; mt < 4; mt++)
                ldsm_x4(AT + (uint32_t)((wm + mt * 16 + a_row_off) * S2_STRIDE +
                                        kk + a_col_off) * 2, af[mt]);
#pragma unroll
            for (int np = 0; np < 4; np++)
                ldsm_x4(BT + (uint32_t)((wn + np * 16 + b_row_off) * S2_STRIDE +
                                        kk + b_col_off) * 2, bf[np]);
#pragma unroll
            for (int mt = 0; mt < 4; mt++)
#pragma unroll
                for (int np = 0; np < 4; np++) {
                    mma16816(acc[mt][2 * np],     af[mt], bf[np][0], bf[np][1]);
                    mma16816(acc[mt][2 * np + 1], af[mt], bf[np][2], bf[np][3]);
                }
        }
    }

    const int g  = lane >> 2;
    const int t2 = (lane & 3) * 2;
#pragma unroll
    for (int mt = 0; mt < 4; mt++) {
        int mrow0 = m0 + wm + mt * 16 + g;
#pragma unroll
        for (int nt = 0; nt < 8; nt++) {
            int n = n0 + wn + nt * 8 + t2;
            float b0 = bias[n], b1 = bias[n + 1];
            *(float2*)(C + (size_t)mrow0 * N + n) =
                make_float2(acc[mt][nt][0] + b0, acc[mt][nt][1] + b1);
            *(float2*)(C + (size_t)(mrow0 + 8) * N + n) =
                make_float2(acc[mt][nt][2] + b0, acc[mt][nt][3] + b1);
        }
    }
}

// ---------------------------------------------------------------------------
// Tensor-core causal flash attention, fp16 operands, fp32 accum.
// BM=128, BN=128, HD=64, 8 warps. TILE-PAIRED: CTA p handles query tiles
// (15-p) then (p) -> constant 17 iterations per CTA (perfect balance).
// ---------------------------------------------------------------------------
#define AT_STRIDE 72
#define AT_TILE (128 * AT_STRIDE * 2)      // 18432 bytes (128 rows x 64 cols)
#define AT_STAGE (2 * AT_TILE)             // 36864: K, V
#define ATTN_SMEM (2 * AT_STAGE)           // 73728

#define SCALE2 0.1803368801111244f         // 0.125 * log2(e)

__global__ __launch_bounds__(256)
void attn_mma(const __half* __restrict__ qkv_hi,
              __half* __restrict__ att_hi) {
    extern __shared__ char smem[];
    const uint32_t sb = smem_u32(smem);

    const int tid  = threadIdx.x;
    const int wid  = tid >> 5;
    const int lane = tid & 31;
    const int p  = blockIdx.x;      // pair index 0..7
    const int h  = blockIdx.y;
    const int b  = blockIdx.z;
    const int hc = h * 64;
    const size_t rowbase = (size_t)b * SEQ;

    const int g  = lane >> 2;
    const int t2 = (lane & 3) * 2;
    const uint32_t koff = (uint32_t)(((lane >> 4) * 8 + (lane & 7)) * AT_STRIDE +
                                     ((lane >> 3) & 1) * 8) * 2;
    const uint32_t voff = (uint32_t)((lane & 15) * AT_STRIDE + (lane >> 4) * 8) * 2;
    const uint32_t qoff = (uint32_t)((16 * (wid & 3) + 64 * (wid >> 2) + (lane & 15)) * AT_STRIDE +
                                     (lane >> 4) * 8) * 2;

    auto load_kv = [&](int stage, int jt) {
        uint32_t sbase = sb + stage * AT_STAGE;
#pragma unroll
        for (int i = 0; i < 4; i++) {
            int idx = tid + 256 * i;
            int row = idx >> 3, q = idx & 7;
            uint32_t soff = (uint32_t)(row * AT_STRIDE + q * 8) * 2;
            size_t grow = rowbase + jt * 128 + row;
            cp_async16(sbase + soff,           qkv_hi + grow * F3 + EMB + hc + q * 8);     // K
            cp_async16(sbase + AT_TILE + soff, qkv_hi + grow * F3 + 2 * EMB + hc + q * 8); // V
        }
        CP_COMMIT();
    };

#pragma unroll 1
    for (int rep = 0; rep < 2; rep++) {
        const int it = rep == 0 ? (15 - p) : p;

        __syncthreads();   // prior tile's smem reads done before Q-stage overwrite

        // ---- Stage Q (128x64 fp16) into stage-0 K-tile ----
#pragma unroll
        for (int i = 0; i < 4; i++) {
            int idx = tid + 256 * i;
            int row = idx >> 3, q = idx & 7;
            uint32_t soff = (uint32_t)(row * AT_STRIDE + q * 8) * 2;
            size_t grow = rowbase + it * 128 + row;
            *(uint4*)(smem + soff) = *(const uint4*)(qkv_hi + grow * F3 + hc + q * 8);
        }
        __syncthreads();

        uint32_t qh[4][4];
#pragma unroll
        for (int ks = 0; ks < 4; ks++)
            ldsm_x4(sb + qoff + ks * 32, qh[ks]);
        __syncthreads();   // Q reads done before load_kv(0) overwrites

        float m2[2] = {-1e30f, -1e30f}, l[2] = {0.f, 0.f};
        float o[8][4];
#pragma unroll
        for (int dt = 0; dt < 8; dt++)
#pragma unroll
            for (int j = 0; j < 4; j++) o[dt][j] = 0.0f;

        const int rbase = 128 * it + 16 * (wid & 3) + 64 * (wid >> 2);
        const int jt_max = it + 1;
        load_kv(0, 0);

        for (int jt = 0; jt < jt_max; jt++) {
            CP_WAIT0();
            __syncthreads();
            if (jt + 1 < jt_max) load_kv((jt + 1) & 1, jt + 1);

            const uint32_t KB = sb + (jt & 1) * AT_STAGE;
            const uint32_t VB = KB + AT_TILE;

            // ---- S = Q K^T (16x128 per warp) ----
            float s[16][4];
#pragma unroll
            for (int nt = 0; nt < 16; nt++)
#pragma unroll
                for (int j = 0; j < 4; j++) s[nt][j] = 0.0f;

#pragma unroll
            for (int ks = 0; ks < 4; ks++) {
                uint32_t kf[8][4];
#pragma unroll
                for (int np = 0; np < 8; np++)
                    ldsm_x4(KB + koff + (uint32_t)(np * 16 * AT_STRIDE + ks * 16) * 2, kf[np]);
#pragma unroll
                for (int np = 0; np < 8; np++) {
                    mma16816(s[2 * np],     qh[ks], kf[np][0], kf[np][1]);
                    mma16816(s[2 * np + 1], qh[ks], kf[np][2], kf[np][3]);
                }
            }

            // ---- scale (+ causal mask on diagonal tile) ----
            const bool diag = (jt == it);
#pragma unroll
            for (int nt = 0; nt < 16; nt++)
#pragma unroll
                for (int j = 0; j < 4; j++) {
                    float t = s[nt][j] * SCALE2;
                    if (diag) {
                        int col = jt * 128 + nt * 8 + t2 + (j & 1);
                        int row = rbase + g + 8 * (j >> 1);
                        if (col > row) t = -1e30f;
                    }
                    s[nt][j] = t;
                }

            // ---- online softmax ----
            float rmax[2] = {-1e30f, -1e30f};
#pragma unroll
            for (int nt = 0; nt < 16; nt++) {
                rmax[0] = fmaxf(rmax[0], fmaxf(s[nt][0], s[nt][1]));
                rmax[1] = fmaxf(rmax[1], fmaxf(s[nt][2], s[nt][3]));
            }
#pragma unroll
            for (int off = 1; off <= 2; off <<= 1) {
                rmax[0] = fmaxf(rmax[0], __shfl_xor_sync(0xffffffffu, rmax[0], off));
                rmax[1] = fmaxf(rmax[1], __shfl_xor_sync(0xffffffffu, rmax[1], off));
            }
            float alpha[2], rsum[2];
#pragma unroll
            for (int r = 0; r < 2; r++) {
                float mnew = fmaxf(m2[r], rmax[r]);
                alpha[r] = ex2(m2[r] - mnew);
                m2[r] = mnew;
                rsum[r] = 0.f;
            }
#pragma unroll
            for (int nt = 0; nt < 16; nt++) {
                s[nt][0] = ex2(s[nt][0] - m2[0]);
                s[nt][1] = ex2(s[nt][1] - m2[0]);
                s[nt][2] = ex2(s[nt][2] - m2[1]);
                s[nt][3] = ex2(s[nt][3] - m2[1]);
                rsum[0] += s[nt][0] + s[nt][1];
                rsum[1] += s[nt][2] + s[nt][3];
            }
#pragma unroll
            for (int off = 1; off <= 2; off <<= 1) {
                rsum[0] += __shfl_xor_sync(0xffffffffu, rsum[0], off);
                rsum[1] += __shfl_xor_sync(0xffffffffu, rsum[1], off);
            }
#pragma unroll
            for (int r = 0; r < 2; r++) l[r] = l[r] * alpha[r] + rsum[r];
#pragma unroll
            for (int dt = 0; dt < 8; dt++) {
                o[dt][0] *= alpha[0];
                o[dt][1] *= alpha[0];
                o[dt][2] *= alpha[1];
                o[dt][3] *= alpha[1];
            }

            // ---- pack P (single fp16): 8 k-groups of 16 cols ----
            uint32_t ph[8][4];
#pragma unroll
            for (int ks = 0; ks < 8; ks++) {
#pragma unroll
                for (int half = 0; half < 2; half++) {
                    int nt = 2 * ks + half;
                    ph[ks][2 * half]     = pack_f16(s[nt][0], s[nt][1]);
                    ph[ks][2 * half + 1] = pack_f16(s[nt][2], s[nt][3]);
                }
            }

            // ---- O += P V : k-dim 128 (8 steps) ----
#pragma unroll
            for (int ks = 0; ks < 8; ks++) {
                uint32_t vf[4][4];
#pragma unroll
                for (int np = 0; np < 4; np++)
                    ldsm_x4_t(VB + voff + (uint32_t)(ks * 16 * AT_STRIDE + np * 16) * 2, vf[np]);
#pragma unroll
                for (int np = 0; np < 4; np++) {
                    mma16816(o[2 * np],     ph[ks], vf[np][0], vf[np][1]);
                    mma16816(o[2 * np + 1], ph[ks], vf[np][2], vf[np][3]);
                }
            }
        }

        // ---- epilogue: O/l -> att (fp16) ----
        float inv0 = 1.0f / l[0], inv1 = 1.0f / l[1];
#pragma unroll
        for (int dt = 0; dt < 8; dt++) {
            int col = hc + dt * 8 + t2;
            size_t i0 = (rowbase + rbase + g) * EMB + col;
            size_t i1 = (rowbase + rbase + g + 8) * EMB + col;
            *(uint32_t*)(att_hi + i0) = pack_f16(o[dt][0] * inv0, o[dt][1] * inv0);
            *(uint32_t*)(att_hi + i1) = pack_f16(o[dt][2] * inv1, o[dt][3] * inv1);
        }
    }
}

// ---------------------------------------------------------------------------
// Launch
// ---------------------------------------------------------------------------
extern "C" void kernel_launch(void* const* d_in, const int* in_sizes, int n_in,
                              void* d_out, int out_size) {
    const float* x      = (const float*)d_in[0];
    const float* w_qkv  = (const float*)d_in[1];
    const float* w_out  = (const float*)d_in[2];
    const float* b_out  = (const float*)d_in[3];
    float* out = (float*)d_out;

    __half *x_hi, *wq_hi, *wo_hi, *qkv_hi, *a_hi;
    cudaGetSymbolAddress((void**)&x_hi,   g_x_hi);
    cudaGetSymbolAddress((void**)&wq_hi,  g_wqkv_hi);
    cudaGetSymbolAddress((void**)&wo_hi,  g_wout_hi);
    cudaGetSymbolAddress((void**)&qkv_hi, g_qkv_hi);
    cudaGetSymbolAddress((void**)&a_hi,   g_att_hi);

    cudaFuncSetAttribute(attn_mma,
                         cudaFuncAttributeMaxDynamicSharedMemorySize, ATTN_SMEM);
    cudaFuncSetAttribute(gemm_mma1,
                         cudaFuncAttributeMaxDynamicSharedMemorySize, GEMM_SMEM);
    cudaFuncSetAttribute(gemm_mma2,
                         cudaFuncAttributeMaxDynamicSharedMemorySize, GEMM2_SMEM);

    // 0) merged fp16 rounds — ONE launch
    {
        int total = N4_X + N4_WQ + N4_WO;
        round_all<<<(total + 255) / 256, 256>>>(
            (const float4*)x, (const float4*)w_qkv, (const float4*)w_out,
            (__half2*)x_hi, (__half2*)wq_hi, (__half2*)wo_hi);
    }

    // 1) QKV projection (BK=128) -> permuted qkv fp16
    gemm_mma1<<<dim3(F3 / 128, ROWS / 256), 256, GEMM_SMEM>>>(
        x_hi, wq_hi, qkv_hi, F3, EMB);

    // 2) Tensor-core causal flash attention (tile-paired, BN=128) -> att fp16
    attn_mma<<<dim3(SEQ / 256, NH, BS), 256, ATTN_SMEM>>>(qkv_hi, a_hi);

    // 3) Output projection + bias (128x128 tiles, 2 CTAs/SM) -> fp32 out
    gemm_mma2<<<dim3(EMB / 128, ROWS / 128), 128, GEMM2_SMEM>>>(
        a_hi, wo_hi, b_out, out, EMB, EMB);
}

// round 16
// speedup vs baseline: 2.8415x; 1.0056x over previous
#include <cuda_runtime.h>
#include <cuda_fp16.h>
#include <cstdint>
#include <math.h>

// Problem constants (fixed shapes)
#define BS   2
#define SEQ  2048
#define EMB  1024
#define NH   16
#define HD   64
#define F3   3072   // 3*EMB
#define ROWS (BS * SEQ)   // 4096

// ---------------------------------------------------------------------------
// Scratch (device globals: allocation-free rule)
// qkv layout PERMUTED: cols [0,1024) = Q (h*64+d), [1024,2048) = K, [2048,3072) = V.
// ---------------------------------------------------------------------------
__device__ __half g_x_hi[ROWS * EMB];
__device__ __half g_wqkv_hi[F3 * EMB];      // permuted rows: [Q|K|V]
__device__ __half g_wout_hi[EMB * EMB];
__device__ __half g_qkv_hi[ROWS * F3];      // [Q|K|V] per row
__device__ __half g_att_hi[ROWS * EMB];

// ---------------------------------------------------------------------------
// helpers
// ---------------------------------------------------------------------------
__device__ __forceinline__ uint32_t smem_u32(const void* p) {
    uint32_t a;
    asm("{ .reg .u64 t; cvta.to.shared.u64 t, %1; cvt.u32.u64 %0, t; }" : "=r"(a) : "l"(p));
    return a;
}
__device__ __forceinline__ void ldsm_x4(uint32_t addr, uint32_t r[4]) {
    asm volatile("ldmatrix.sync.aligned.m8n8.x4.shared.b16 {%0,%1,%2,%3}, [%4];"
                 : "=r"(r[0]), "=r"(r[1]), "=r"(r[2]), "=r"(r[3]) : "r"(addr));
}
__device__ __forceinline__ void ldsm_x4_t(uint32_t addr, uint32_t r[4]) {
    asm volatile("ldmatrix.sync.aligned.m8n8.x4.trans.shared.b16 {%0,%1,%2,%3}, [%4];"
                 : "=r"(r[0]), "=r"(r[1]), "=r"(r[2]), "=r"(r[3]) : "r"(addr));
}
__device__ __forceinline__ void mma16816(float c[4], const uint32_t a[4],
                                         const uint32_t b0, const uint32_t b1) {
    asm volatile(
        "mma.sync.aligned.m16n8k16.row.col.f32.f16.f16.f32 "
        "{%0,%1,%2,%3}, {%4,%5,%6,%7}, {%8,%9}, {%0,%1,%2,%3};"
        : "+f"(c[0]), "+f"(c[1]), "+f"(c[2]), "+f"(c[3])
        : "r"(a[0]), "r"(a[1]), "r"(a[2]), "r"(a[3]), "r"(b0), "r"(b1));
}
__device__ __forceinline__ uint32_t pack_f16(float lo, float hi) {
    __half2 h = __floats2half2_rn(lo, hi);
    return *(uint32_t*)&h;
}
__device__ __forceinline__ float ex2(float x) {
    float r;
    asm("ex2.approx.ftz.f32 %0, %1;" : "=f"(r) : "f"(x));
    return r;
}
__device__ __forceinline__ void cp_async16(uint32_t dst, const void* src) {
    asm volatile("cp.async.cg.shared.global [%0], [%1], 16;" :: "r"(dst), "l"(src));
}
#define CP_COMMIT() asm volatile("cp.async.commit_group;" ::: "memory")
#define CP_WAIT1()  asm volatile("cp.async.wait_group 1;" ::: "memory")
#define CP_WAIT0()  asm volatile("cp.async.wait_group 0;" ::: "memory")

// ---------------------------------------------------------------------------
// Merged fp16 round: x (identity), w_qkv (permuted [Q|K|V]), w_out (identity)
// ---------------------------------------------------------------------------
#define N4_X   (ROWS * EMB / 4)      // 1048576
#define N4_WQ  (F3 * EMB / 4)        // 786432
#define N4_WO  (EMB * EMB / 4)       // 262144

__global__ void round_all(const float4* __restrict__ x,
                          const float4* __restrict__ wqkv,
                          const float4* __restrict__ wout,
                          __half2* __restrict__ x_hi,
                          __half2* __restrict__ wq_hi,
                          __half2* __restrict__ wo_hi) {
    int i = blockIdx.x * blockDim.x + threadIdx.x;
    float4 v;
    __half2* dst;
    if (i < N4_X) {
        v = x[i];
        dst = x_hi + 2 * i;
    } else if (i < N4_X + N4_WQ) {
        int idx = i - N4_X;
        int r = idx >> 8;            // EMB/4 = 256 float4 per row
        int q = idx & 255;
        int m = r >> 10;
        int within = r & 1023;
        int hsrc = (within >> 6) * 192 + m * 64 + (within & 63);
        v = wqkv[(size_t)hsrc * 256 + q];
        dst = wq_hi + 2 * idx;
    } else if (i < N4_X + N4_WQ + N4_WO) {
        int idx = i - N4_X - N4_WQ;
        v = wout[idx];
        dst = wo_hi + 2 * idx;
    } else {
        return;
    }
    dst[0] = __half2(__float2half_rn(v.x), __float2half_rn(v.y));
    dst[1] = __half2(__float2half_rn(v.z), __float2half_rn(v.w));
}

// ---------------------------------------------------------------------------
// GEMM: CTA 256x128, 8 warps, BK=128, 1 CTA/SM (HMMA-ceiling config).
// OUT_F16: fp16 output (no bias). Else fp32 + bias.
// ---------------------------------------------------------------------------
#define SA_STRIDE 136
#define ATILE_B (256 * SA_STRIDE * 2)           // 69632
#define BTILE_B (128 * SA_STRIDE * 2)           // 34816
#define STAGE_B (ATILE_B + BTILE_B)             // 104448
#define GEMM_SMEM (2 * STAGE_B)                 // 208896

template <bool HAS_BIAS, bool OUT_F16>
__global__ __launch_bounds__(256, 1)
void gemm_mma(const __half* __restrict__ A, const __half* __restrict__ B,
              const float* __restrict__ bias, float* __restrict__ C,
              __half* __restrict__ Ch, int N, int K) {
    extern __shared__ char smem[];
    const uint32_t sb = smem_u32(smem);

    const int tid  = threadIdx.x;
    const int wid  = tid >> 5;
    const int lane = tid & 31;
    const int n0 = blockIdx.x * 128;
    const int m0 = blockIdx.y * 256;
    const int wm = (wid & 3) * 64;
    const int wn = (wid >> 2) * 64;

    const int trow  = lane & 7;
    const int tquad = lane >> 3;
    const int a_row_off = (tquad & 1) * 8 + trow;
    const int a_col_off = (tquad >> 1) * 8;
    const int b_row_off = (tquad >> 1) * 8 + trow;
    const int b_col_off = (tquad & 1) * 8;

    float acc[4][8][4];
#pragma unroll
    for (int mt = 0; mt < 4; mt++)
#pragma unroll
        for (int nt = 0; nt < 8; nt++)
#pragma unroll
            for (int j = 0; j < 4; j++) acc[mt][nt][j] = 0.0f;

    auto load_stage = [&](int stage, int k0) {
        uint32_t s0 = sb + stage * STAGE_B;
#pragma unroll
        for (int i = 0; i < 16; i++) {
            int idx = tid + 256 * i;
            int row = idx >> 4, q = idx & 15;
            uint32_t soff = (uint32_t)(row * SA_STRIDE + q * 8) * 2;
            cp_async16(s0 + soff, A + (size_t)(m0 + row) * K + k0 + q * 8);
        }
#pragma unroll
        for (int i = 0; i < 8; i++) {
            int idx = tid + 256 * i;
            int row = idx >> 4, q = idx & 15;
            uint32_t soff = (uint32_t)(row * SA_STRIDE + q * 8) * 2;
            cp_async16(s0 + ATILE_B + soff, B + (size_t)(n0 + row) * K + k0 + q * 8);
        }
        CP_COMMIT();
    };

    const int NC = K >> 7;
    load_stage(0, 0);

    for (int c = 0; c < NC; c++) {
        CP_WAIT0();
        __syncthreads();
        if (c + 1 < NC) load_stage((c + 1) & 1, (c + 1) * 128);

        const uint32_t AT = sb + (c & 1) * STAGE_B;
        const uint32_t BT = AT + ATILE_B;

#pragma unroll
        for (int ks = 0; ks < 8; ks++) {
            const int kk = ks * 16;
            uint32_t af[4][4], bf[4][4];
#pragma unroll
            for (int mt = 0; mt < 4; mt++)
                ldsm_x4(AT + (uint32_t)((wm + mt * 16 + a_row_off) * SA_STRIDE +
                                        kk + a_col_off) * 2, af[mt]);
#pragma unroll
            for (int np = 0; np < 4; np++)
                ldsm_x4(BT + (uint32_t)((wn + np * 16 + b_row_off) * SA_STRIDE +
                                        kk + b_col_off) * 2, bf[np]);
#pragma unroll
            for (int mt = 0; mt < 4; mt++)
#pragma unroll
                for (int np = 0; np < 4; np++) {
                    mma16816(acc[mt][2 * np],     af[mt], bf[np][0], bf[np][1]);
                    mma16816(acc[mt][2 * np + 1], af[mt], bf[np][2], bf[np][3]);
                }
        }
    }

    const int g  = lane >> 2;
    const int t2 = (lane & 3) * 2;
#pragma unroll
    for (int mt = 0; mt < 4; mt++) {
        int mrow0 = m0 + wm + mt * 16 + g;
#pragma unroll
        for (int nt = 0; nt < 8; nt++) {
            int n = n0 + wn + nt * 8 + t2;
            float b0 = 0.f, b1 = 0.f;
            if (HAS_BIAS) { b0 = bias[n]; b1 = bias[n + 1]; }
            float v00 = acc[mt][nt][0] + b0, v01 = acc[mt][nt][1] + b1;
            float v10 = acc[mt][nt][2] + b0, v11 = acc[mt][nt][3] + b1;
            if (OUT_F16) {
                *(uint32_t*)(Ch + (size_t)mrow0 * N + n)       = pack_f16(v00, v01);
                *(uint32_t*)(Ch + (size_t)(mrow0 + 8) * N + n) = pack_f16(v10, v11);
            } else {
                *(float2*)(C + (size_t)mrow0 * N + n)       = make_float2(v00, v01);
                *(float2*)(C + (size_t)(mrow0 + 8) * N + n) = make_float2(v10, v11);
            }
        }
    }
}

// ---------------------------------------------------------------------------
// Tensor-core causal flash attention, fp16 operands, fp32 accum.
// BM=128, BN=128, HD=64, 8 warps. TILE-PAIRED (CTA p: tiles 15-p then p).
// 3-stage cp.async ring, prefetch distance 2.
// ---------------------------------------------------------------------------
#define AT_STRIDE 72
#define AT_TILE (128 * AT_STRIDE * 2)      // 18432 bytes (128 rows x 64 cols)
#define AT_STAGE (2 * AT_TILE)             // 36864: K, V
#define ATTN_SMEM (3 * AT_STAGE)           // 110592

#define SCALE2 0.1803368801111244f         // 0.125 * log2(e)

__global__ __launch_bounds__(256)
void attn_mma(const __half* __restrict__ qkv_hi,
              __half* __restrict__ att_hi) {
    extern __shared__ char smem[];
    const uint32_t sb = smem_u32(smem);

    const int tid  = threadIdx.x;
    const int wid  = tid >> 5;
    const int lane = tid & 31;
    const int p  = blockIdx.x;      // pair index 0..7
    const int h  = blockIdx.y;
    const int b  = blockIdx.z;
    const int hc = h * 64;
    const size_t rowbase = (size_t)b * SEQ;

    const int g  = lane >> 2;
    const int t2 = (lane & 3) * 2;
    const uint32_t koff = (uint32_t)(((lane >> 4) * 8 + (lane & 7)) * AT_STRIDE +
                                     ((lane >> 3) & 1) * 8) * 2;
    const uint32_t voff = (uint32_t)((lane & 15) * AT_STRIDE + (lane >> 4) * 8) * 2;
    const uint32_t qoff = (uint32_t)((16 * (wid & 3) + 64 * (wid >> 2) + (lane & 15)) * AT_STRIDE +
                                     (lane >> 4) * 8) * 2;

    auto load_kv = [&](int jt) {
        uint32_t sbase = sb + (jt % 3) * AT_STAGE;
#pragma unroll
        for (int i = 0; i < 4; i++) {
            int idx = tid + 256 * i;
            int row = idx >> 3, q = idx & 7;
            uint32_t soff = (uint32_t)(row * AT_STRIDE + q * 8) * 2;
            size_t grow = rowbase + jt * 128 + row;
            cp_async16(sbase + soff,           qkv_hi + grow * F3 + EMB + hc + q * 8);     // K
            cp_async16(sbase + AT_TILE + soff, qkv_hi + grow * F3 + 2 * EMB + hc + q * 8); // V
        }
        CP_COMMIT();
    };

#pragma unroll 1
    for (int rep = 0; rep < 2; rep++) {
        const int it = rep == 0 ? (15 - p) : p;

        __syncthreads();   // prior tile's smem reads done before Q-stage overwrite

        // ---- Stage Q (128x64 fp16) into stage-0 K-tile ----
#pragma unroll
        for (int i = 0; i < 4; i++) {
            int idx = tid + 256 * i;
            int row = idx >> 3, q = idx & 7;
            uint32_t soff = (uint32_t)(row * AT_STRIDE + q * 8) * 2;
            size_t grow = rowbase + it * 128 + row;
            *(uint4*)(smem + soff) = *(const uint4*)(qkv_hi + grow * F3 + hc + q * 8);
        }
        __syncthreads();

        uint32_t qh[4][4];
#pragma unroll
        for (int ks = 0; ks < 4; ks++)
            ldsm_x4(sb + qoff + ks * 32, qh[ks]);
        __syncthreads();   // Q reads done before load_kv(0) overwrites stage 0

        float m2[2] = {-1e30f, -1e30f}, l[2] = {0.f, 0.f};
        float o[8][4];
#pragma unroll
        for (int dt = 0; dt < 8; dt++)
#pragma unroll
            for (int j = 0; j < 4; j++) o[dt][j] = 0.0f;

        const int rbase = 128 * it + 16 * (wid & 3) + 64 * (wid >> 2);
        const int jt_max = it + 1;
        load_kv(0);
        if (jt_max > 1) load_kv(1);

        for (int jt = 0; jt < jt_max; jt++) {
            if (jt + 1 < jt_max) CP_WAIT1(); else CP_WAIT0();  // stage jt landed
            __syncthreads();
            if (jt + 2 < jt_max) load_kv(jt + 2);   // overwrites stage (jt-1)%3, read last iter

            const uint32_t KB = sb + (jt % 3) * AT_STAGE;
            const uint32_t VB = KB + AT_TILE;

            // ---- S = Q K^T (16x128 per warp) ----
            float s[16][4];
#pragma unroll
            for (int nt = 0; nt < 16; nt++)
#pragma unroll
                for (int j = 0; j < 4; j++) s[nt][j] = 0.0f;

#pragma unroll
            for (int ks = 0; ks < 4; ks++) {
                uint32_t kf[8][4];
#pragma unroll
                for (int np = 0; np < 8; np++)
                    ldsm_x4(KB + koff + (uint32_t)(np * 16 * AT_STRIDE + ks * 16) * 2, kf[np]);
#pragma unroll
                for (int np = 0; np < 8; np++) {
                    mma16816(s[2 * np],     qh[ks], kf[np][0], kf[np][1]);
                    mma16816(s[2 * np + 1], qh[ks], kf[np][2], kf[np][3]);
                }
            }

            // ---- scale (+ causal mask on diagonal tile) ----
            const bool diag = (jt == it);
#pragma unroll
            for (int nt = 0; nt < 16; nt++)
#pragma unroll
                for (int j = 0; j < 4; j++) {
                    float t = s[nt][j] * SCALE2;
                    if (diag) {
                        int col = jt * 128 + nt * 8 + t2 + (j & 1);
                        int row = rbase + g + 8 * (j >> 1);
                        if (col > row) t = -1e30f;
                    }
                    s[nt][j] = t;
                }

            // ---- online softmax ----
            float rmax[2] = {-1e30f, -1e30f};
#pragma unroll
            for (int nt = 0; nt < 16; nt++) {
                rmax[0] = fmaxf(rmax[0], fmaxf(s[nt][0], s[nt][1]));
                rmax[1] = fmaxf(rmax[1], fmaxf(s[nt][2], s[nt][3]));
            }
#pragma unroll
            for (int off = 1; off <= 2; off <<= 1) {
                rmax[0] = fmaxf(rmax[0], __shfl_xor_sync(0xffffffffu, rmax[0], off));
                rmax[1] = fmaxf(rmax[1], __shfl_xor_sync(0xffffffffu, rmax[1], off));
            }
            float alpha[2], rsum[2];
#pragma unroll
            for (int r = 0; r < 2; r++) {
                float mnew = fmaxf(m2[r], rmax[r]);
                alpha[r] = ex2(m2[r] - mnew);
                m2[r] = mnew;
                rsum[r] = 0.f;
            }
#pragma unroll
            for (int nt = 0; nt < 16; nt++) {
                s[nt][0] = ex2(s[nt][0] - m2[0]);
                s[nt][1] = ex2(s[nt][1] - m2[0]);
                s[nt][2] = ex2(s[nt][2] - m2[1]);
                s[nt][3] = ex2(s[nt][3] - m2[1]);
                rsum[0] += s[nt][0] + s[nt][1];
                rsum[1] += s[nt][2] + s[nt][3];
            }
#pragma unroll
            for (int off = 1; off <= 2; off <<= 1) {
                rsum[0] += __shfl_xor_sync(0xffffffffu, rsum[0], off);
                rsum[1] += __shfl_xor_sync(0xffffffffu, rsum[1], off);
            }
#pragma unroll
            for (int r = 0; r < 2; r++) l[r] = l[r] * alpha[r] + rsum[r];
#pragma unroll
            for (int dt = 0; dt < 8; dt++) {
                o[dt][0] *= alpha[0];
                o[dt][1] *= alpha[0];
                o[dt][2] *= alpha[1];
                o[dt][3] *= alpha[1];
            }

            // ---- pack P (single fp16): 8 k-groups of 16 cols ----
            uint32_t ph[8][4];
#pragma unroll
            for (int ks = 0; ks < 8; ks++) {
#pragma unroll
                for (int half = 0; half < 2; half++) {
                    int nt = 2 * ks + half;
                    ph[ks][2 * half]     = pack_f16(s[nt][0], s[nt][1]);
                    ph[ks][2 * half + 1] = pack_f16(s[nt][2], s[nt][3]);
                }
            }

            // ---- O += P V : k-dim 128 (8 steps) ----
#pragma unroll
            for (int ks = 0; ks < 8; ks++) {
                uint32_t vf[4][4];
#pragma unroll
                for (int np = 0; np < 4; np++)
                    ldsm_x4_t(VB + voff + (uint32_t)(ks * 16 * AT_STRIDE + np * 16) * 2, vf[np]);
#pragma unroll
                for (int np = 0; np < 4; np++) {
                    mma16816(o[2 * np],     ph[ks], vf[np][0], vf[np][1]);
                    mma16816(o[2 * np + 1], ph[ks], vf[np][2], vf[np][3]);
                }
            }
        }

        // ---- epilogue: O/l -> att (fp16) ----
        float inv0 = 1.0f / l[0], inv1 = 1.0f / l[1];
#pragma unroll
        for (int dt = 0; dt < 8; dt++) {
            int col = hc + dt * 8 + t2;
            size_t i0 = (rowbase + rbase + g) * EMB + col;
            size_t i1 = (rowbase + rbase + g + 8) * EMB + col;
            *(uint32_t*)(att_hi + i0) = pack_f16(o[dt][0] * inv0, o[dt][1] * inv0);
            *(uint32_t*)(att_hi + i1) = pack_f16(o[dt][2] * inv1, o[dt][3] * inv1);
        }
    }
}

// ---------------------------------------------------------------------------
// Launch
// ---------------------------------------------------------------------------
extern "C" void kernel_launch(void* const* d_in, const int* in_sizes, int n_in,
                              void* d_out, int out_size) {
    const float* x      = (const float*)d_in[0];
    const float* w_qkv  = (const float*)d_in[1];
    const float* w_out  = (const float*)d_in[2];
    const float* b_out  = (const float*)d_in[3];
    float* out = (float*)d_out;

    __half *x_hi, *wq_hi, *wo_hi, *qkv_hi, *a_hi;
    cudaGetSymbolAddress((void**)&x_hi,   g_x_hi);
    cudaGetSymbolAddress((void**)&wq_hi,  g_wqkv_hi);
    cudaGetSymbolAddress((void**)&wo_hi,  g_wout_hi);
    cudaGetSymbolAddress((void**)&qkv_hi, g_qkv_hi);
    cudaGetSymbolAddress((void**)&a_hi,   g_att_hi);

    cudaFuncSetAttribute(attn_mma,
                         cudaFuncAttributeMaxDynamicSharedMemorySize, ATTN_SMEM);
    cudaFuncSetAttribute((const void*)gemm_mma<false, true>,
                         cudaFuncAttributeMaxDynamicSharedMemorySize, GEMM_SMEM);
    cudaFuncSetAttribute((const void*)gemm_mma<true, false>,
                         cudaFuncAttributeMaxDynamicSharedMemorySize, GEMM_SMEM);

    // 0) merged fp16 rounds — ONE launch
    {
        int total = N4_X + N4_WQ + N4_WO;
        round_all<<<(total + 255) / 256, 256>>>(
            (const float4*)x, (const float4*)w_qkv, (const float4*)w_out,
            (__half2*)x_hi, (__half2*)wq_hi, (__half2*)wo_hi);
    }

    // 1) QKV projection (BK=128) -> permuted qkv fp16
    gemm_mma<false, true><<<dim3(F3 / 128, ROWS / 256), 256, GEMM_SMEM>>>(
        x_hi, wq_hi, nullptr, nullptr, qkv_hi, F3, EMB);

    // 2) Tensor-core causal flash attention (tile-paired, 3-stage ring) -> att fp16
    attn_mma<<<dim3(SEQ / 256, NH, BS), 256, ATTN_SMEM>>>(qkv_hi, a_hi);

    // 3) Output projection + bias (256x128 CTA, 8 warps, BK=128) -> fp32 out
    gemm_mma<true, false><<<dim3(EMB / 128, ROWS / 256), 256, GEMM_SMEM>>>(
        a_hi, wo_hi, b_out, out, nullptr, EMB, EMB);
}

// round 17
// speedup vs baseline: 2.9330x; 1.0322x over previous
#include <cuda_runtime.h>
#include <cuda_fp16.h>
#include <cstdint>
#include <math.h>

// Problem constants (fixed shapes)
#define BS   2
#define SEQ  2048
#define EMB  1024
#define NH   16
#define HD   64
#define F3   3072   // 3*EMB
#define ROWS (BS * SEQ)   // 4096

// ---------------------------------------------------------------------------
// Scratch (device globals: allocation-free rule)
// qkv layout PERMUTED: cols [0,1024) = Q (h*64+d), [1024,2048) = K, [2048,3072) = V.
// ---------------------------------------------------------------------------
__device__ __half g_x_hi[ROWS * EMB];
__device__ __half g_wqkv_hi[F3 * EMB];      // permuted rows: [Q|K|V]
__device__ __half g_wout_hi[EMB * EMB];
__device__ __half g_qkv_hi[ROWS * F3];      // [Q|K|V] per row
__device__ __half g_att_hi[ROWS * EMB];

// ---------------------------------------------------------------------------
// helpers
// ---------------------------------------------------------------------------
__device__ __forceinline__ uint32_t smem_u32(const void* p) {
    uint32_t a;
    asm("{ .reg .u64 t; cvta.to.shared.u64 t, %1; cvt.u32.u64 %0, t; }" : "=r"(a) : "l"(p));
    return a;
}
__device__ __forceinline__ void ldsm_x4(uint32_t addr, uint32_t r[4]) {
    asm volatile("ldmatrix.sync.aligned.m8n8.x4.shared.b16 {%0,%1,%2,%3}, [%4];"
                 : "=r"(r[0]), "=r"(r[1]), "=r"(r[2]), "=r"(r[3]) : "r"(addr));
}
__device__ __forceinline__ void ldsm_x4_t(uint32_t addr, uint32_t r[4]) {
    asm volatile("ldmatrix.sync.aligned.m8n8.x4.trans.shared.b16 {%0,%1,%2,%3}, [%4];"
                 : "=r"(r[0]), "=r"(r[1]), "=r"(r[2]), "=r"(r[3]) : "r"(addr));
}
__device__ __forceinline__ void mma16816(float c[4], const uint32_t a[4],
                                         const uint32_t b0, const uint32_t b1) {
    asm volatile(
        "mma.sync.aligned.m16n8k16.row.col.f32.f16.f16.f32 "
        "{%0,%1,%2,%3}, {%4,%5,%6,%7}, {%8,%9}, {%0,%1,%2,%3};"
        : "+f"(c[0]), "+f"(c[1]), "+f"(c[2]), "+f"(c[3])
        : "r"(a[0]), "r"(a[1]), "r"(a[2]), "r"(a[3]), "r"(b0), "r"(b1));
}
__device__ __forceinline__ uint32_t pack_f16(float lo, float hi) {
    __half2 h = __floats2half2_rn(lo, hi);
    return *(uint32_t*)&h;
}
__device__ __forceinline__ float ex2(float x) {
    float r;
    asm("ex2.approx.ftz.f32 %0, %1;" : "=f"(r) : "f"(x));
    return r;
}
__device__ __forceinline__ void cp_async16(uint32_t dst, const void* src) {
    asm volatile("cp.async.cg.shared.global [%0], [%1], 16;" :: "r"(dst), "l"(src));
}
#define CP_COMMIT() asm volatile("cp.async.commit_group;" ::: "memory")
#define CP_WAIT1()  asm volatile("cp.async.wait_group 1;" ::: "memory")
#define CP_WAIT0()  asm volatile("cp.async.wait_group 0;" ::: "memory")

// ---------------------------------------------------------------------------
// Merged fp16 round: x (identity), w_qkv (permuted [Q|K|V]), w_out (identity)
// ---------------------------------------------------------------------------
#define N4_X   (ROWS * EMB / 4)      // 1048576
#define N4_WQ  (F3 * EMB / 4)        // 786432
#define N4_WO  (EMB * EMB / 4)       // 262144

__global__ void round_all(const float4* __restrict__ x,
                          const float4* __restrict__ wqkv,
                          const float4* __restrict__ wout,
                          __half2* __restrict__ x_hi,
                          __half2* __restrict__ wq_hi,
                          __half2* __restrict__ wo_hi) {
    int i = blockIdx.x * blockDim.x + threadIdx.x;
    float4 v;
    __half2* dst;
    if (i < N4_X) {
        v = x[i];
        dst = x_hi + 2 * i;
    } else if (i < N4_X + N4_WQ) {
        int idx = i - N4_X;
        int r = idx >> 8;            // EMB/4 = 256 float4 per row
        int q = idx & 255;
        int m = r >> 10;
        int within = r & 1023;
        int hsrc = (within >> 6) * 192 + m * 64 + (within & 63);
        v = wqkv[(size_t)hsrc * 256 + q];
        dst = wq_hi + 2 * idx;
    } else if (i < N4_X + N4_WQ + N4_WO) {
        int idx = i - N4_X - N4_WQ;
        v = wout[idx];
        dst = wo_hi + 2 * idx;
    } else {
        return;
    }
    dst[0] = __half2(__float2half_rn(v.x), __float2half_rn(v.y));
    dst[1] = __half2(__float2half_rn(v.z), __float2half_rn(v.w));
}

// ---------------------------------------------------------------------------
// GEMM: CTA 256x128, 8 warps, BK=128, 1 CTA/SM (HMMA-ceiling config).
// OUT_F16: fp16 output (no bias). Else fp32 + bias.
// ---------------------------------------------------------------------------
#define SA_STRIDE 136
#define ATILE_B (256 * SA_STRIDE * 2)           // 69632
#define BTILE_B (128 * SA_STRIDE * 2)           // 34816
#define STAGE_B (ATILE_B + BTILE_B)             // 104448
#define GEMM_SMEM (2 * STAGE_B)                 // 208896

template <bool HAS_BIAS, bool OUT_F16>
__global__ __launch_bounds__(256, 1)
void gemm_mma(const __half* __restrict__ A, const __half* __restrict__ B,
              const float* __restrict__ bias, float* __restrict__ C,
              __half* __restrict__ Ch, int N, int K) {
    extern __shared__ char smem[];
    const uint32_t sb = smem_u32(smem);

    const int tid  = threadIdx.x;
    const int wid  = tid >> 5;
    const int lane = tid & 31;
    const int n0 = blockIdx.x * 128;
    const int m0 = blockIdx.y * 256;
    const int wm = (wid & 3) * 64;
    const int wn = (wid >> 2) * 64;

    const int trow  = lane & 7;
    const int tquad = lane >> 3;
    const int a_row_off = (tquad & 1) * 8 + trow;
    const int a_col_off = (tquad >> 1) * 8;
    const int b_row_off = (tquad >> 1) * 8 + trow;
    const int b_col_off = (tquad & 1) * 8;

    float acc[4][8][4];
#pragma unroll
    for (int mt = 0; mt < 4; mt++)
#pragma unroll
        for (int nt = 0; nt < 8; nt++)
#pragma unroll
            for (int j = 0; j < 4; j++) acc[mt][nt][j] = 0.0f;

    auto load_stage = [&](int stage, int k0) {
        uint32_t s0 = sb + stage * STAGE_B;
#pragma unroll
        for (int i = 0; i < 16; i++) {
            int idx = tid + 256 * i;
            int row = idx >> 4, q = idx & 15;
            uint32_t soff = (uint32_t)(row * SA_STRIDE + q * 8) * 2;
            cp_async16(s0 + soff, A + (size_t)(m0 + row) * K + k0 + q * 8);
        }
#pragma unroll
        for (int i = 0; i < 8; i++) {
            int idx = tid + 256 * i;
            int row = idx >> 4, q = idx & 15;
            uint32_t soff = (uint32_t)(row * SA_STRIDE + q * 8) * 2;
            cp_async16(s0 + ATILE_B + soff, B + (size_t)(n0 + row) * K + k0 + q * 8);
        }
        CP_COMMIT();
    };

    const int NC = K >> 7;
    load_stage(0, 0);

    for (int c = 0; c < NC; c++) {
        CP_WAIT0();
        __syncthreads();
        if (c + 1 < NC) load_stage((c + 1) & 1, (c + 1) * 128);

        const uint32_t AT = sb + (c & 1) * STAGE_B;
        const uint32_t BT = AT + ATILE_B;

#pragma unroll
        for (int ks = 0; ks < 8; ks++) {
            const int kk = ks * 16;
            uint32_t af[4][4], bf[4][4];
#pragma unroll
            for (int mt = 0; mt < 4; mt++)
                ldsm_x4(AT + (uint32_t)((wm + mt * 16 + a_row_off) * SA_STRIDE +
                                        kk + a_col_off) * 2, af[mt]);
#pragma unroll
            for (int np = 0; np < 4; np++)
                ldsm_x4(BT + (uint32_t)((wn + np * 16 + b_row_off) * SA_STRIDE +
                                        kk + b_col_off) * 2, bf[np]);
#pragma unroll
            for (int mt = 0; mt < 4; mt++)
#pragma unroll
                for (int np = 0; np < 4; np++) {
                    mma16816(acc[mt][2 * np],     af[mt], bf[np][0], bf[np][1]);
                    mma16816(acc[mt][2 * np + 1], af[mt], bf[np][2], bf[np][3]);
                }
        }
    }

    const int g  = lane >> 2;
    const int t2 = (lane & 3) * 2;
#pragma unroll
    for (int mt = 0; mt < 4; mt++) {
        int mrow0 = m0 + wm + mt * 16 + g;
#pragma unroll
        for (int nt = 0; nt < 8; nt++) {
            int n = n0 + wn + nt * 8 + t2;
            float b0 = 0.f, b1 = 0.f;
            if (HAS_BIAS) { b0 = bias[n]; b1 = bias[n + 1]; }
            float v00 = acc[mt][nt][0] + b0, v01 = acc[mt][nt][1] + b1;
            float v10 = acc[mt][nt][2] + b0, v11 = acc[mt][nt][3] + b1;
            if (OUT_F16) {
                *(uint32_t*)(Ch + (size_t)mrow0 * N + n)       = pack_f16(v00, v01);
                *(uint32_t*)(Ch + (size_t)(mrow0 + 8) * N + n) = pack_f16(v10, v11);
            } else {
                *(float2*)(C + (size_t)mrow0 * N + n)       = make_float2(v00, v01);
                *(float2*)(C + (size_t)(mrow0 + 8) * N + n) = make_float2(v10, v11);
            }
        }
    }
}

// ---------------------------------------------------------------------------
// Tensor-core causal flash attention, fp16 operands, fp32 accum.
// BM=128, BN=128, HD=64, 8 warps. SINGLE-WAVE SNAKE SCHEDULE:
// 512 items (b,h,it) in descending-it order; CTA c (of 148) takes items
// row*148 + (row even ? c : 147-c), row=0..3. Max bin ~35 units (vs 38).
// 3-stage cp.async ring, prefetch distance 2.
// ---------------------------------------------------------------------------
#define AT_STRIDE 72
#define AT_TILE (128 * AT_STRIDE * 2)      // 18432 bytes (128 rows x 64 cols)
#define AT_STAGE (2 * AT_TILE)             // 36864: K, V
#define ATTN_SMEM (3 * AT_STAGE)           // 110592

#define SCALE2 0.1803368801111244f         // 0.125 * log2(e)
#define N_ITEMS 512                        // 16 q-tiles * NH * BS
#define N_CTAS  148

__global__ __launch_bounds__(256)
void attn_mma(const __half* __restrict__ qkv_hi,
              __half* __restrict__ att_hi) {
    extern __shared__ char smem[];
    const uint32_t sb = smem_u32(smem);

    const int tid  = threadIdx.x;
    const int wid  = tid >> 5;
    const int lane = tid & 31;
    const int cta  = blockIdx.x;

    const int g  = lane >> 2;
    const int t2 = (lane & 3) * 2;
    const uint32_t koff = (uint32_t)(((lane >> 4) * 8 + (lane & 7)) * AT_STRIDE +
                                     ((lane >> 3) & 1) * 8) * 2;
    const uint32_t voff = (uint32_t)((lane & 15) * AT_STRIDE + (lane >> 4) * 8) * 2;
    const uint32_t qoff = (uint32_t)((16 * (wid & 3) + 64 * (wid >> 2) + (lane & 15)) * AT_STRIDE +
                                     (lane >> 4) * 8) * 2;

#pragma unroll 1
    for (int row = 0; row < 4; row++) {
        int jj = row * N_CTAS + ((row & 1) ? (N_CTAS - 1 - cta) : cta);
        if (jj >= N_ITEMS) continue;     // uniform across CTA
        const int it = 15 - (jj >> 5);   // descending-weight order
        const int bh = jj & 31;
        const int b  = bh >> 4;
        const int h  = bh & 15;
        const int hc = h * 64;
        const size_t rowbase = (size_t)b * SEQ;

        auto load_kv = [&](int jt) {
            uint32_t sbase = sb + (jt % 3) * AT_STAGE;
#pragma unroll
            for (int i = 0; i < 4; i++) {
                int idx = tid + 256 * i;
                int r = idx >> 3, q = idx & 7;
                uint32_t soff = (uint32_t)(r * AT_STRIDE + q * 8) * 2;
                size_t grow = rowbase + jt * 128 + r;
                cp_async16(sbase + soff,           qkv_hi + grow * F3 + EMB + hc + q * 8);     // K
                cp_async16(sbase + AT_TILE + soff, qkv_hi + grow * F3 + 2 * EMB + hc + q * 8); // V
            }
            CP_COMMIT();
        };

        __syncthreads();   // prior item's smem reads done before Q-stage overwrite

        // ---- Stage Q (128x64 fp16) into stage-0 K-tile ----
#pragma unroll
        for (int i = 0; i < 4; i++) {
            int idx = tid + 256 * i;
            int r = idx >> 3, q = idx & 7;
            uint32_t soff = (uint32_t)(r * AT_STRIDE + q * 8) * 2;
            size_t grow = rowbase + it * 128 + r;
            *(uint4*)(smem + soff) = *(const uint4*)(qkv_hi + grow * F3 + hc + q * 8);
        }
        __syncthreads();

        uint32_t qh[4][4];
#pragma unroll
        for (int ks = 0; ks < 4; ks++)
            ldsm_x4(sb + qoff + ks * 32, qh[ks]);
        __syncthreads();   // Q reads done before load_kv(0) overwrites stage 0

        float m2[2] = {-1e30f, -1e30f}, l[2] = {0.f, 0.f};
        float o[8][4];
#pragma unroll
        for (int dt = 0; dt < 8; dt++)
#pragma unroll
            for (int j = 0; j < 4; j++) o[dt][j] = 0.0f;

        const int rbase = 128 * it + 16 * (wid & 3) + 64 * (wid >> 2);
        const int jt_max = it + 1;
        load_kv(0);
        if (jt_max > 1) load_kv(1);

        for (int jt = 0; jt < jt_max; jt++) {
            if (jt + 1 < jt_max) CP_WAIT1(); else CP_WAIT0();
            __syncthreads();
            if (jt + 2 < jt_max) load_kv(jt + 2);

            const uint32_t KB = sb + (jt % 3) * AT_STAGE;
            const uint32_t VB = KB + AT_TILE;

            // ---- S = Q K^T (16x128 per warp) ----
            float s[16][4];
#pragma unroll
            for (int nt = 0; nt < 16; nt++)
#pragma unroll
                for (int j = 0; j < 4; j++) s[nt][j] = 0.0f;

#pragma unroll
            for (int ks = 0; ks < 4; ks++) {
                uint32_t kf[8][4];
#pragma unroll
                for (int np = 0; np < 8; np++)
                    ldsm_x4(KB + koff + (uint32_t)(np * 16 * AT_STRIDE + ks * 16) * 2, kf[np]);
#pragma unroll
                for (int np = 0; np < 8; np++) {
                    mma16816(s[2 * np],     qh[ks], kf[np][0], kf[np][1]);
                    mma16816(s[2 * np + 1], qh[ks], kf[np][2], kf[np][3]);
                }
            }

            // ---- scale (+ causal mask on diagonal tile) ----
            const bool diag = (jt == it);
#pragma unroll
            for (int nt = 0; nt < 16; nt++)
#pragma unroll
                for (int j = 0; j < 4; j++) {
                    float t = s[nt][j] * SCALE2;
                    if (diag) {
                        int col = jt * 128 + nt * 8 + t2 + (j & 1);
                        int r = rbase + g + 8 * (j >> 1);
                        if (col > r) t = -1e30f;
                    }
                    s[nt][j] = t;
                }

            // ---- online softmax ----
            float rmax[2] = {-1e30f, -1e30f};
#pragma unroll
            for (int nt = 0; nt < 16; nt++) {
                rmax[0] = fmaxf(rmax[0], fmaxf(s[nt][0], s[nt][1]));
                rmax[1] = fmaxf(rmax[1], fmaxf(s[nt][2], s[nt][3]));
            }
#pragma unroll
            for (int off = 1; off <= 2; off <<= 1) {
                rmax[0] = fmaxf(rmax[0], __shfl_xor_sync(0xffffffffu, rmax[0], off));
                rmax[1] = fmaxf(rmax[1], __shfl_xor_sync(0xffffffffu, rmax[1], off));
            }
            float alpha[2], rsum[2];
#pragma unroll
            for (int r = 0; r < 2; r++) {
                float mnew = fmaxf(m2[r], rmax[r]);
                alpha[r] = ex2(m2[r] - mnew);
                m2[r] = mnew;
                rsum[r] = 0.f;
            }
#pragma unroll
            for (int nt = 0; nt < 16; nt++) {
                s[nt][0] = ex2(s[nt][0] - m2[0]);
                s[nt][1] = ex2(s[nt][1] - m2[0]);
                s[nt][2] = ex2(s[nt][2] - m2[1]);
                s[nt][3] = ex2(s[nt][3] - m2[1]);
                rsum[0] += s[nt][0] + s[nt][1];
                rsum[1] += s[nt][2] + s[nt][3];
            }
#pragma unroll
            for (int off = 1; off <= 2; off <<= 1) {
                rsum[0] += __shfl_xor_sync(0xffffffffu, rsum[0], off);
                rsum[1] += __shfl_xor_sync(0xffffffffu, rsum[1], off);
            }
#pragma unroll
            for (int r = 0; r < 2; r++) l[r] = l[r] * alpha[r] + rsum[r];
#pragma unroll
            for (int dt = 0; dt < 8; dt++) {
                o[dt][0] *= alpha[0];
                o[dt][1] *= alpha[0];
                o[dt][2] *= alpha[1];
                o[dt][3] *= alpha[1];
            }

            // ---- pack P (single fp16): 8 k-groups of 16 cols ----
            uint32_t ph[8][4];
#pragma unroll
            for (int ks = 0; ks < 8; ks++) {
#pragma unroll
                for (int half = 0; half < 2; half++) {
                    int nt = 2 * ks + half;
                    ph[ks][2 * half]     = pack_f16(s[nt][0], s[nt][1]);
                    ph[ks][2 * half + 1] = pack_f16(s[nt][2], s[nt][3]);
                }
            }

            // ---- O += P V : k-dim 128 (8 steps) ----
#pragma unroll
            for (int ks = 0; ks < 8; ks++) {
                uint32_t vf[4][4];
#pragma unroll
                for (int np = 0; np < 4; np++)
                    ldsm_x4_t(VB + voff + (uint32_t)(ks * 16 * AT_STRIDE + np * 16) * 2, vf[np]);
#pragma unroll
                for (int np = 0; np < 4; np++) {
                    mma16816(o[2 * np],     ph[ks], vf[np][0], vf[np][1]);
                    mma16816(o[2 * np + 1], ph[ks], vf[np][2], vf[np][3]);
                }
            }
        }

        // ---- epilogue: O/l -> att (fp16) ----
        float inv0 = 1.0f / l[0], inv1 = 1.0f / l[1];
#pragma unroll
        for (int dt = 0; dt < 8; dt++) {
            int col = hc + dt * 8 + t2;
            size_t i0 = (rowbase + rbase + g) * EMB + col;
            size_t i1 = (rowbase + rbase + g + 8) * EMB + col;
            *(uint32_t*)(att_hi + i0) = pack_f16(o[dt][0] * inv0, o[dt][1] * inv0);
            *(uint32_t*)(att_hi + i1) = pack_f16(o[dt][2] * inv1, o[dt][3] * inv1);
        }
    }
}

// ---------------------------------------------------------------------------
// Launch
// ---------------------------------------------------------------------------
extern "C" void kernel_launch(void* const* d_in, const int* in_sizes, int n_in,
                              void* d_out, int out_size) {
    const float* x      = (const float*)d_in[0];
    const float* w_qkv  = (const float*)d_in[1];
    const float* w_out  = (const float*)d_in[2];
    const float* b_out  = (const float*)d_in[3];
    float* out = (float*)d_out;

    __half *x_hi, *wq_hi, *wo_hi, *qkv_hi, *a_hi;
    cudaGetSymbolAddress((void**)&x_hi,   g_x_hi);
    cudaGetSymbolAddress((void**)&wq_hi,  g_wqkv_hi);
    cudaGetSymbolAddress((void**)&wo_hi,  g_wout_hi);
    cudaGetSymbolAddress((void**)&qkv_hi, g_qkv_hi);
    cudaGetSymbolAddress((void**)&a_hi,   g_att_hi);

    cudaFuncSetAttribute(attn_mma,
                         cudaFuncAttributeMaxDynamicSharedMemorySize, ATTN_SMEM);
    cudaFuncSetAttribute((const void*)gemm_mma<false, true>,
                         cudaFuncAttributeMaxDynamicSharedMemorySize, GEMM_SMEM);
    cudaFuncSetAttribute((const void*)gemm_mma<true, false>,
                         cudaFuncAttributeMaxDynamicSharedMemorySize, GEMM_SMEM);

    // 0) merged fp16 rounds — ONE launch
    {
        int total = N4_X + N4_WQ + N4_WO;
        round_all<<<(total + 255) / 256, 256>>>(
            (const float4*)x, (const float4*)w_qkv, (const float4*)w_out,
            (__half2*)x_hi, (__half2*)wq_hi, (__half2*)wo_hi);
    }

    // 1) QKV projection (BK=128) -> permuted qkv fp16
    gemm_mma<false, true><<<dim3(F3 / 128, ROWS / 256), 256, GEMM_SMEM>>>(
        x_hi, wq_hi, nullptr, nullptr, qkv_hi, F3, EMB);

    // 2) Causal flash attention, single-wave snake schedule -> att fp16
    attn_mma<<<N_CTAS, 256, ATTN_SMEM>>>(qkv_hi, a_hi);

    // 3) Output projection + bias (256x128 CTA, 8 warps, BK=128) -> fp32 out
    gemm_mma<true, false><<<dim3(EMB / 128, ROWS / 256), 256, GEMM_SMEM>>>(
        a_hi, wo_hi, b_out, out, nullptr, EMB, EMB);
}